// round 2
// baseline (speedup 1.0000x reference)
#include <cuda_runtime.h>
#include <math.h>

#define BB 2
#define CC 256
#define NNT 13824          // tokens
#define NHH 4
#define DHH 64
#define PPP 64
#define GGG 8
#define MTOT (BB*NNT)      // 27648

// ---------------- scratch (device globals; no allocation) ----------------
__device__ float  g_h1 [BB*CC*NNT];                 // conv1 out -> later x_SA scrambled
__device__ float  g_xc [BB*CC*NNT];                 // conv2 out -> xc
__device__ float  g_xt [BB*NNT*CC];                 // xt -> x_n (in place)
__device__ float  g_xct[BB*NNT*CC];                 // xct -> xc_n (in place)
__device__ float  g_qkv[(size_t)BB*NNT*3*CC];       // [B,N,768]
__device__ float  g_att[BB*NNT*CC];                 // concat(SA_out, CA_out)
__device__ float2 g_st1[BB*CC];
__device__ float2 g_st2[BB*CC];
// pooled[512] | qss[512] | kproj[32768] | vproj[32768]
#define ZOFF_POOL 0
#define ZOFF_QSS  512
#define ZOFF_KP   1024
#define ZOFF_VP   33792
#define ZTOT      66560
__device__ float  g_zero[ZTOT];
__device__ float  g_qrn [BB*CC];
__device__ float  g_gate[BB*CC];

// ---------------- kernels ----------------
__global__ void k_zero() {
    int i = blockIdx.x*256 + threadIdx.x;
    if (i < ZTOT) g_zero[i] = 0.f;
}

// grouped 1x1x1 conv (+ optional fused instance-norm + lrelu on the input)
__global__ void k_conv(const float* __restrict__ src, const float* __restrict__ w,
                       const float* __restrict__ bias, float* __restrict__ dst,
                       const float2* __restrict__ instat)
{
    int bg = blockIdx.y; int b = bg >> 3; int g = bg & 7;
    int n  = blockIdx.x*256 + threadIdx.x;
    __shared__ float ws[1024];
    __shared__ float ins[32][256];
    for (int idx = threadIdx.x; idx < 1024; idx += 256) ws[idx] = w[g*1024 + idx];
    int cbase = b*CC + g*32;
    for (int i = 0; i < 32; ++i) {
        float v = src[(size_t)(cbase+i)*NNT + n];
        if (instat) {
            float2 st = instat[cbase+i];
            v = (v - st.x) * st.y;
            v = v >= 0.f ? v : 0.01f*v;
        }
        ins[i][threadIdx.x] = v;
    }
    __syncthreads();
    float acc[32];
    #pragma unroll
    for (int o = 0; o < 32; ++o) acc[o] = bias[g*32+o];
    for (int i = 0; i < 32; ++i) {
        float v = ins[i][threadIdx.x];
        #pragma unroll
        for (int o = 0; o < 32; ++o) acc[o] += v * ws[i*32+o];
    }
    #pragma unroll 4
    for (int o = 0; o < 32; ++o)
        dst[(size_t)(cbase+o)*NNT + n] = acc[o];
}

// instance-norm stats per (b,c) row over N
__global__ void k_stats(const float* __restrict__ src, float2* __restrict__ st)
{
    int row = blockIdx.x;
    const float* p = src + (size_t)row*NNT;
    float s = 0.f, q = 0.f;
    for (int n = threadIdx.x; n < NNT; n += 256) { float v = p[n]; s += v; q += v*v; }
    #pragma unroll
    for (int o = 16; o; o >>= 1) {
        s += __shfl_down_sync(0xffffffffu, s, o);
        q += __shfl_down_sync(0xffffffffu, q, o);
    }
    __shared__ float sh[16];
    int w = threadIdx.x >> 5, l = threadIdx.x & 31;
    if (l == 0) { sh[w] = s; sh[w+8] = q; }
    __syncthreads();
    if (threadIdx.x == 0) {
        float S = 0.f, Q = 0.f;
        for (int i = 0; i < 8; ++i) { S += sh[i]; Q += sh[i+8]; }
        float m = S / NNT;
        float var = Q / NNT - m*m;
        st[row] = make_float2(m, rsqrtf(var + 1e-5f));
    }
}

// xc = lrelu(inorm(h2) + x)
__global__ void k_xc(const float* __restrict__ x)
{
    int row = blockIdx.y;
    int n   = blockIdx.x*256 + threadIdx.x;
    size_t i = (size_t)row*NNT + n;
    float2 st = g_st2[row];
    float v = (g_xc[i] - st.x)*st.y + x[i];
    g_xc[i] = v >= 0.f ? v : 0.01f*v;
}

// build xt = x^T + pos, xct = xc^T + pos   (tiled transpose)
__global__ void k_trans(const float* __restrict__ x, const float* __restrict__ pos)
{
    __shared__ float t1[32][33], t2[32][33];
    int n0 = blockIdx.x*32, c0 = blockIdx.y*32, b = blockIdx.z;
    int tx = threadIdx.x, ty = threadIdx.y;
    for (int yy = ty; yy < 32; yy += 8) {
        size_t s = (size_t)(b*CC + c0 + yy)*NNT + n0 + tx;
        t1[yy][tx] = x[s];
        t2[yy][tx] = g_xc[s];
    }
    __syncthreads();
    for (int yy = ty; yy < 32; yy += 8) {
        float p = pos[(size_t)(n0+yy)*CC + c0 + tx];
        size_t d = ((size_t)b*NNT + n0 + yy)*CC + c0 + tx;
        g_xt [d] = t1[tx][yy] + p;
        g_xct[d] = t2[tx][yy] + p;
    }
}

// in-place LayerNorm of xt and xct rows (C=256)
__global__ void k_ln(const float* __restrict__ lg, const float* __restrict__ lb)
{
    size_t row = blockIdx.x;
    int t = threadIdx.x;
    size_t i = row*CC + t;
    float v1 = g_xt[i], v2 = g_xct[i];
    float s1 = v1, q1 = v1*v1, s2 = v2, q2 = v2*v2;
    #pragma unroll
    for (int o = 16; o; o >>= 1) {
        s1 += __shfl_down_sync(0xffffffffu, s1, o);
        q1 += __shfl_down_sync(0xffffffffu, q1, o);
        s2 += __shfl_down_sync(0xffffffffu, s2, o);
        q2 += __shfl_down_sync(0xffffffffu, q2, o);
    }
    __shared__ float sh[4][8];
    __shared__ float fin[4];
    int w = t >> 5, l = t & 31;
    if (l == 0) { sh[0][w]=s1; sh[1][w]=q1; sh[2][w]=s2; sh[3][w]=q2; }
    __syncthreads();
    if (t < 4) { float a = 0.f; for (int j = 0; j < 8; ++j) a += sh[t][j]; fin[t] = a; }
    __syncthreads();
    float m1 = fin[0]/CC, r1 = rsqrtf(fin[1]/CC - m1*m1 + 1e-5f);
    float m2 = fin[2]/CC, r2 = rsqrtf(fin[3]/CC - m2*m2 + 1e-5f);
    g_xt [i] = (v1 - m1)*r1*lg[t] + lb[t];
    g_xct[i] = (v2 - m2)*r2*lg[t] + lb[t];
}

// pooled[b,c] = sum_n xc_n[b,n,c]*w_pool[n]
__global__ void k_pool(const float* __restrict__ wp)
{
    int b = blockIdx.x, ch = blockIdx.y;
    int c = threadIdx.x;
    int n0 = ch*432;
    const float* base = g_xct + ((size_t)b*NNT + n0)*CC + c;
    float acc = 0.f;
    for (int n = 0; n < 432; ++n) acc += base[(size_t)n*CC] * wp[n0+n];
    atomicAdd(&g_zero[ZOFF_POOL + b*CC + c], acc);
}

// gate = sigmoid(relu((pooled+b_pool) @ w_fc1) @ w_fc2)
__global__ void k_gate(const float* __restrict__ bp, const float* __restrict__ w1,
                       const float* __restrict__ w2)
{
    __shared__ float ps[256], hs[64];
    int b = blockIdx.x, t = threadIdx.x;
    ps[t] = g_zero[ZOFF_POOL + b*CC + t] + bp[0];
    __syncthreads();
    if (t < 64) {
        float a = 0.f;
        for (int c = 0; c < 256; ++c) a += ps[c]*w1[c*64 + t];
        hs[t] = fmaxf(a, 0.f);
    }
    __syncthreads();
    float a = 0.f;
    for (int j = 0; j < 64; ++j) a += hs[j]*w2[j*256 + t];
    g_gate[b*CC + t] = 1.f/(1.f + expf(-a));
}

// 128x128x8 fp32 SGEMM, 8x8 thread tiles. Optional bias (len Nw) and per-(b,k) gate on A.
__global__ __launch_bounds__(256) void k_gemm(
    const float* __restrict__ A, const float* __restrict__ Bw,
    const float* __restrict__ bias, const float* __restrict__ gate,
    float* __restrict__ Cm, int Nw, int K, int ldc, int coff)
{
    __shared__ float As[8][128];
    __shared__ float Bs[8][128];
    int bx = blockIdx.x, by = blockIdx.y;
    int tid = threadIdx.x;
    int tx = tid & 15, ty = tid >> 4;
    float acc[8][8] = {};
    int arow = tid >> 1, acol = (tid & 1)*4;
    int brow = tid >> 5, bcol = (tid & 31)*4;
    const float* Ap = A + (size_t)(by*128 + arow)*K + acol;
    const float* Bp = Bw + (size_t)brow*Nw + bx*128 + bcol;
    const float* grow = gate ? (gate + ((by*128)/NNT)*CC) : (const float*)0;
    for (int k0 = 0; k0 < K; k0 += 8) {
        float4 av = *(const float4*)(Ap + k0);
        if (grow) {
            av.x *= grow[k0+acol+0]; av.y *= grow[k0+acol+1];
            av.z *= grow[k0+acol+2]; av.w *= grow[k0+acol+3];
        }
        As[acol+0][arow] = av.x; As[acol+1][arow] = av.y;
        As[acol+2][arow] = av.z; As[acol+3][arow] = av.w;
        float4 bv = *(const float4*)(Bp + (size_t)k0*Nw);
        *(float4*)&Bs[brow][bcol] = bv;
        __syncthreads();
        #pragma unroll
        for (int kk = 0; kk < 8; ++kk) {
            float ar[8], br[8];
            #pragma unroll
            for (int i = 0; i < 8; ++i) ar[i] = As[kk][ty*8 + i];
            #pragma unroll
            for (int j = 0; j < 8; ++j) br[j] = Bs[kk][tx*8 + j];
            #pragma unroll
            for (int i = 0; i < 8; ++i)
                #pragma unroll
                for (int j = 0; j < 8; ++j) acc[i][j] += ar[i]*br[j];
        }
        __syncthreads();
    }
    #pragma unroll
    for (int i = 0; i < 8; ++i) {
        int r = by*128 + ty*8 + i;
        float* crow = Cm + (size_t)r*ldc + coff + bx*128 + tx*8;
        #pragma unroll
        for (int j = 0; j < 8; ++j) {
            float v = acc[i][j];
            if (bias) v += bias[bx*128 + tx*8 + j];
            crow[j] = v;
        }
    }
}

// sum of squares of q over tokens per (b, h*64+d)
__global__ void k_qss()
{
    int b = blockIdx.x, ch = blockIdx.y;
    int t = threadIdx.x;
    const float* base = g_qkv + ((size_t)b*NNT + ch*432)*768 + t;
    float acc = 0.f;
    for (int n = 0; n < 432; ++n) { float v = base[(size_t)n*768]; acc += v*v; }
    atomicAdd(&g_zero[ZOFF_QSS + b*256 + t], acc);
}

__global__ void k_qrn()
{
    int i = blockIdx.x*256 + threadIdx.x;
    float ss = g_zero[ZOFF_QSS + i];
    g_qrn[i] = 1.f / fmaxf(sqrtf(ss), 1e-12f);
}

// k_proj / v_proj: [d,p] = sum_n kv[n,d]*w_e[n,p]  (split-K over grid.z, atomic combine)
__global__ void k_kvproj(const float* __restrict__ we)
{
    int bh = blockIdx.x;          // B*NH
    int which = blockIdx.y;       // 0 = k, 1 = v
    int n0 = blockIdx.z * 512;
    int b = bh >> 2, h = bh & 3;
    const float* src = g_qkv + (size_t)b*NNT*768 + (which+1)*256 + h*64;
    __shared__ float ks[64][65], es[64][65];
    int tid = threadIdx.x;
    int tx = tid & 15, ty = tid >> 4;
    float acc[4][4] = {};
    for (int c = 0; c < 8; ++c) {
        int nb = n0 + c*64;
        #pragma unroll
        for (int l = 0; l < 16; ++l) {
            int idx = l*256 + tid;
            int nn = idx >> 6, d = idx & 63;
            ks[nn][d] = src[(size_t)(nb+nn)*768 + d];
            es[nn][d] = we[(size_t)(nb+nn)*64 + d];
        }
        __syncthreads();
        for (int nn = 0; nn < 64; ++nn) {
            float a[4], e[4];
            #pragma unroll
            for (int i = 0; i < 4; ++i) a[i] = ks[nn][ty*4 + i];
            #pragma unroll
            for (int j = 0; j < 4; ++j) e[j] = es[nn][tx*4 + j];
            #pragma unroll
            for (int i = 0; i < 4; ++i)
                #pragma unroll
                for (int j = 0; j < 4; ++j) acc[i][j] += a[i]*e[j];
        }
        __syncthreads();
    }
    float* out = &g_zero[ZOFF_KP + which*32768 + bh*4096];
    #pragma unroll
    for (int i = 0; i < 4; ++i)
        #pragma unroll
        for (int j = 0; j < 4; ++j)
            atomicAdd(&out[(ty*4+i)*64 + tx*4 + j], acc[i][j]);
}

// fused: q-normalize, attn = qn @ kproj * temp, softmax, x_SA = attn @ vproj^T,
// scrambled store sa[b][(d*4+h)*N + n]
__global__ void k_attn(const float* __restrict__ be, const float* __restrict__ temp)
{
    int bh = blockIdx.y; int b = bh >> 2, h = bh & 3;
    int n0 = blockIdx.x*64;
    __shared__ float s1[64][65];   // qn -> attn -> out-stage
    __shared__ float s2[64][65];   // kproj -> vproj
    int tid = threadIdx.x;
    const float* kbase = &g_zero[ZOFF_KP + bh*4096];
    const float* vbase = &g_zero[ZOFF_VP + bh*4096];
    #pragma unroll
    for (int l = 0; l < 16; ++l) {
        int idx = l*256 + tid;
        int r = idx >> 6, cidx = idx & 63;
        s2[r][cidx] = kbase[idx] + be[cidx];                     // kp[d][p] + b_e
        s1[r][cidx] = g_qkv[((size_t)(b*NNT + n0 + r))*768 + h*64 + cidx]
                      * g_qrn[b*256 + h*64 + cidx];              // qn[nn][d]
    }
    __syncthreads();
    int tx = tid & 15, ty = tid >> 4;
    float acc[4][4] = {};
    for (int d = 0; d < 64; ++d) {
        float a[4], kv[4];
        #pragma unroll
        for (int i = 0; i < 4; ++i) a[i] = s1[ty*4+i][d];
        #pragma unroll
        for (int j = 0; j < 4; ++j) kv[j] = s2[d][tx*4+j];
        #pragma unroll
        for (int i = 0; i < 4; ++i)
            #pragma unroll
            for (int j = 0; j < 4; ++j) acc[i][j] += a[i]*kv[j];
    }
    float ts = temp[h];
    __syncthreads();
    // attn -> s1; vproj -> s2
    #pragma unroll
    for (int i = 0; i < 4; ++i)
        #pragma unroll
        for (int j = 0; j < 4; ++j) s1[ty*4+i][tx*4+j] = acc[i][j]*ts;
    #pragma unroll
    for (int l = 0; l < 16; ++l) {
        int idx = l*256 + tid;
        int d = idx >> 6, p = idx & 63;
        s2[d][p] = vbase[idx] + be[p];
    }
    __syncthreads();
    if (tid < 64) {
        float mx = -1e30f;
        for (int p = 0; p < 64; ++p) mx = fmaxf(mx, s1[tid][p]);
        float s = 0.f;
        for (int p = 0; p < 64; ++p) { float e = expf(s1[tid][p]-mx); s1[tid][p] = e; s += e; }
        float inv = 1.f/s;
        for (int p = 0; p < 64; ++p) s1[tid][p] *= inv;
    }
    __syncthreads();
    float acc2[4][4] = {};
    for (int p = 0; p < 64; ++p) {
        float a[4], v[4];
        #pragma unroll
        for (int i = 0; i < 4; ++i) a[i] = s1[ty*4+i][p];
        #pragma unroll
        for (int j = 0; j < 4; ++j) v[j] = s2[tx*4+j][p];
        #pragma unroll
        for (int i = 0; i < 4; ++i)
            #pragma unroll
            for (int j = 0; j < 4; ++j) acc2[i][j] += a[i]*v[j];
    }
    __syncthreads();
    #pragma unroll
    for (int i = 0; i < 4; ++i)
        #pragma unroll
        for (int j = 0; j < 4; ++j) s1[tx*4+j][ty*4+i] = acc2[i][j];  // s1[d][nn]
    __syncthreads();
    #pragma unroll
    for (int l = 0; l < 16; ++l) {
        int idx = l*256 + tid;
        int d = idx >> 6, nn = idx & 63;
        g_h1[(size_t)b*NNT*CC + (size_t)(d*4 + h)*NNT + n0 + nn] = s1[d][nn];
    }
}

// out[b,c,n] = x_n[b,n,c] + gamma[c]*x_att[b,n,c]   (tiled transpose)
__global__ void k_final(const float* __restrict__ gamma, float* __restrict__ out)
{
    __shared__ float t1[32][33];
    int n0 = blockIdx.x*32, c0 = blockIdx.y*32, b = blockIdx.z;
    int tx = threadIdx.x, ty = threadIdx.y;
    for (int yy = ty; yy < 32; yy += 8) {
        size_t s = ((size_t)b*NNT + n0 + yy)*CC + c0 + tx;
        t1[yy][tx] = g_xt[s] + gamma[c0+tx]*g_att[s];
    }
    __syncthreads();
    for (int yy = ty; yy < 32; yy += 8)
        out[(size_t)(b*CC + c0 + yy)*NNT + n0 + tx] = t1[tx][yy];
}

// ---------------- launch ----------------
extern "C" void kernel_launch(void* const* d_in, const int* in_sizes, int n_in,
                              void* d_out, int out_size)
{
    const float* x      = (const float*)d_in[0];
    const float* pos    = (const float*)d_in[1];
    const float* ln_g   = (const float*)d_in[2];
    const float* ln_b   = (const float*)d_in[3];
    const float* gamma  = (const float*)d_in[4];
    const float* temp2  = (const float*)d_in[5];
    const float* w_qkv  = (const float*)d_in[6];
    const float* w_e    = (const float*)d_in[7];
    const float* b_e    = (const float*)d_in[8];
    const float* w_pool = (const float*)d_in[9];
    const float* b_pool = (const float*)d_in[10];
    const float* w_fc1  = (const float*)d_in[11];
    const float* w_fc2  = (const float*)d_in[12];
    const float* w_out1 = (const float*)d_in[13];
    const float* b_out1 = (const float*)d_in[14];
    const float* w_out2 = (const float*)d_in[15];
    const float* b_out2 = (const float*)d_in[16];
    const float* w_c1   = (const float*)d_in[17];
    const float* b_c1   = (const float*)d_in[18];
    const float* w_c2   = (const float*)d_in[19];
    const float* b_c2   = (const float*)d_in[20];

    float  *p_h1, *p_xc, *p_xt, *p_xct, *p_qkv, *p_att, *p_gate;
    float2 *p_st1, *p_st2;
    cudaGetSymbolAddress((void**)&p_h1,  g_h1);
    cudaGetSymbolAddress((void**)&p_xc,  g_xc);
    cudaGetSymbolAddress((void**)&p_xt,  g_xt);
    cudaGetSymbolAddress((void**)&p_xct, g_xct);
    cudaGetSymbolAddress((void**)&p_qkv, g_qkv);
    cudaGetSymbolAddress((void**)&p_att, g_att);
    cudaGetSymbolAddress((void**)&p_gate,g_gate);
    cudaGetSymbolAddress((void**)&p_st1, g_st1);
    cudaGetSymbolAddress((void**)&p_st2, g_st2);

    k_zero <<<(ZTOT+255)/256, 256>>>();
    // MHCResBlock
    k_conv <<<dim3(54,16), 256>>>(x,    w_c1, b_c1, p_h1, (const float2*)0);
    k_stats<<<512, 256>>>(p_h1, p_st1);
    k_conv <<<dim3(54,16), 256>>>(p_h1, w_c2, b_c2, p_xc, p_st1);
    k_stats<<<512, 256>>>(p_xc, p_st2);
    k_xc   <<<dim3(54,512), 256>>>(x);
    // tokens + LN
    k_trans<<<dim3(432,8,BB), dim3(32,8)>>>(x, pos);
    k_ln   <<<MTOT, 256>>>(ln_g, ln_b);
    // channel attention gate
    k_pool <<<dim3(BB,32), 256>>>(w_pool);
    k_gate <<<BB, 256>>>(b_pool, w_fc1, w_fc2);
    // qkv
    k_gemm <<<dim3(6,216), 256>>>(p_xt, w_qkv, (const float*)0, (const float*)0,
                                   p_qkv, 768, 256, 768, 0);
    // q token-norms
    k_qss  <<<dim3(BB,32), 256>>>();
    k_qrn  <<<2, 256>>>();
    // low-rank K/V projection
    k_kvproj<<<dim3(BB*NHH, 2, 27), 256>>>(w_e);
    // spatial attention (+ scramble)
    k_attn <<<dim3(216, BB*NHH), 256>>>(b_e, temp2);
    // output projections into concat buffer
    k_gemm <<<dim3(1,216), 256>>>(p_h1,  w_out1, b_out1, (const float*)0,
                                   p_att, 128, 256, 256, 0);
    k_gemm <<<dim3(1,216), 256>>>(p_xct, w_out2, b_out2, p_gate,
                                   p_att, 128, 256, 256, 128);
    // residual + gamma, transpose to [B,C,N]
    k_final<<<dim3(432,8,BB), dim3(32,8)>>>(gamma, (float*)d_out);
}

// round 4
// speedup vs baseline: 1.6786x; 1.6786x over previous
#include <cuda_runtime.h>
#include <cuda_bf16.h>
#include <cstdint>
#include <math.h>

#define BB 2
#define CC 256
#define NNT 13824
#define NHH 4
#define MTOT (BB*NNT)

// ---------------- scratch ----------------
__device__ __nv_bfloat16 g_h1b[BB*CC*NNT];           // conv1 out
__device__ __nv_bfloat16 g_c2b[BB*CC*NNT];           // conv2 raw out
__device__ float         g_xt [BB*NNT*CC];           // xt_pre -> x_n (fp32, residual)
__device__ float         g_att[BB*NNT*CC];           // xct_pre -> concat(SA,CA) out
__device__ __nv_bfloat16 g_xt_bf [BB*NNT*CC];        // x_n bf16 (qkv A)
__device__ __nv_bfloat16 g_xct_bf[BB*NNT*CC];        // xc_n bf16
__device__ __nv_bfloat16 g_qkv_bf[(size_t)BB*NNT*768];
__device__ __nv_bfloat16 g_sa_bf [BB*NNT*CC];        // scrambled x_SA
__device__ __nv_bfloat16 g_wqkv_bf[256*768];
__device__ __nv_bfloat16 g_wo1_bf [256*128];
__device__ __nv_bfloat16 g_wo2_bf [256*128];
__device__ float2 g_st1[BB*CC];
__device__ float2 g_st2[BB*CC];
#define ZOFF_POOL 0
#define ZOFF_QSS  512
#define ZOFF_KP   1024
#define ZOFF_VP   33792
#define ZTOT      66560
__device__ float g_zero[ZTOT];
__device__ float g_qrn [BB*CC];
__device__ float g_gate[BB*CC];

// ---------------- mma helpers ----------------
__device__ __forceinline__ void ldm_x4(unsigned int (&r)[4], const void* p) {
    unsigned int a = (unsigned int)__cvta_generic_to_shared(p);
    asm volatile("ldmatrix.sync.aligned.m8n8.x4.shared.b16 {%0,%1,%2,%3}, [%4];"
        : "=r"(r[0]),"=r"(r[1]),"=r"(r[2]),"=r"(r[3]) : "r"(a));
}
__device__ __forceinline__ void ldm_x4_t(unsigned int (&r)[4], const void* p) {
    unsigned int a = (unsigned int)__cvta_generic_to_shared(p);
    asm volatile("ldmatrix.sync.aligned.m8n8.x4.trans.shared.b16 {%0,%1,%2,%3}, [%4];"
        : "=r"(r[0]),"=r"(r[1]),"=r"(r[2]),"=r"(r[3]) : "r"(a));
}
__device__ __forceinline__ void mma16816(float (&d)[4], const unsigned int (&a)[4],
                                         unsigned int b0, unsigned int b1) {
    asm volatile("mma.sync.aligned.m16n8k16.row.col.f32.bf16.bf16.f32 "
        "{%0,%1,%2,%3},{%4,%5,%6,%7},{%8,%9},{%0,%1,%2,%3};"
        : "+f"(d[0]),"+f"(d[1]),"+f"(d[2]),"+f"(d[3])
        : "r"(a[0]),"r"(a[1]),"r"(a[2]),"r"(a[3]),"r"(b0),"r"(b1));
}

// ---------------- kernels ----------------
__global__ void k_zero() {
    int i = blockIdx.x*256 + threadIdx.x;
    if (i < ZTOT) g_zero[i] = 0.f;
}

__global__ void k_wcvt(const float* __restrict__ wq, const float* __restrict__ w1,
                       const float* __restrict__ w2)
{
    int i = blockIdx.x*256 + threadIdx.x;
    if (i < 196608) g_wqkv_bf[i] = __float2bfloat16(wq[i]);
    if (i < 32768)  { g_wo1_bf[i] = __float2bfloat16(w1[i]);
                      g_wo2_bf[i] = __float2bfloat16(w2[i]); }
}

// grouped 1x1x1 conv; conv2 fuses instance-norm + lrelu of its input
__global__ __launch_bounds__(256) void k_conv(
    const float* __restrict__ srcf, const __nv_bfloat16* __restrict__ srcb,
    const float* __restrict__ w, const float* __restrict__ bias,
    __nv_bfloat16* __restrict__ dst, const float2* __restrict__ instat)
{
    int bg = blockIdx.y; int b = bg >> 3; int g = bg & 7;
    int n  = blockIdx.x*256 + threadIdx.x;
    __shared__ float ws[1024];
    for (int i = threadIdx.x; i < 1024; i += 256) ws[i] = w[g*1024 + i];
    __syncthreads();
    int cbase = b*CC + g*32;
    float acc[32];
    #pragma unroll
    for (int o = 0; o < 32; ++o) acc[o] = bias[g*32+o];
    bool useb = (srcb != nullptr);
    #pragma unroll 4
    for (int i = 0; i < 32; ++i) {
        float v;
        if (useb) {
            v = __bfloat162float(srcb[(size_t)(cbase+i)*NNT + n]);
            float2 st = instat[cbase+i];
            v = (v - st.x)*st.y;
            v = v >= 0.f ? v : 0.01f*v;
        } else {
            v = srcf[(size_t)(cbase+i)*NNT + n];
        }
        #pragma unroll
        for (int o = 0; o < 32; ++o) acc[o] += v*ws[i*32+o];
    }
    #pragma unroll 4
    for (int o = 0; o < 32; ++o)
        dst[(size_t)(cbase+o)*NNT + n] = __float2bfloat16(acc[o]);
}

__global__ void k_stats(const __nv_bfloat16* __restrict__ src, float2* __restrict__ st)
{
    int row = blockIdx.x;
    const __nv_bfloat16* p = src + (size_t)row*NNT;
    float s = 0.f, q = 0.f;
    for (int n = threadIdx.x; n < NNT; n += 256) {
        float v = __bfloat162float(p[n]); s += v; q += v*v;
    }
    #pragma unroll
    for (int o = 16; o; o >>= 1) {
        s += __shfl_down_sync(0xffffffffu, s, o);
        q += __shfl_down_sync(0xffffffffu, q, o);
    }
    __shared__ float sh[16];
    int w = threadIdx.x >> 5, l = threadIdx.x & 31;
    if (l == 0) { sh[w] = s; sh[w+8] = q; }
    __syncthreads();
    if (threadIdx.x == 0) {
        float S = 0.f, Q = 0.f;
        for (int i = 0; i < 8; ++i) { S += sh[i]; Q += sh[i+8]; }
        float m = S / NNT;
        st[row] = make_float2(m, rsqrtf(Q/NNT - m*m + 1e-5f));
    }
}

// fused: xc = lrelu(inorm(conv2)+x); write xt_pre = x^T+pos (g_xt), xct_pre (g_att)
__global__ void k_trans(const float* __restrict__ x, const float* __restrict__ pos)
{
    __shared__ float t1[32][33], t2[32][33];
    int n0 = blockIdx.x*32, c0 = blockIdx.y*32, b = blockIdx.z;
    int tx = threadIdx.x, ty = threadIdx.y;
    for (int yy = ty; yy < 32; yy += 8) {
        size_t s = (size_t)(b*CC + c0 + yy)*NNT + n0 + tx;
        float xv = x[s];
        float2 st = g_st2[b*CC + c0 + yy];
        float hv = (__bfloat162float(g_c2b[s]) - st.x)*st.y + xv;
        t1[yy][tx] = xv;
        t2[yy][tx] = hv >= 0.f ? hv : 0.01f*hv;
    }
    __syncthreads();
    for (int yy = ty; yy < 32; yy += 8) {
        float p = pos[(size_t)(n0+yy)*CC + c0 + tx];
        size_t d = ((size_t)b*NNT + n0 + yy)*CC + c0 + tx;
        g_xt [d] = t1[tx][yy] + p;
        g_att[d] = t2[tx][yy] + p;
    }
}

// LayerNorm rows: g_xt(pre)->x_n fp32+bf16 ; g_att(pre)->xc_n bf16
__global__ void k_ln(const float* __restrict__ lg, const float* __restrict__ lb)
{
    size_t row = blockIdx.x;
    int t = threadIdx.x;
    size_t i = row*CC + t;
    float v1 = g_xt[i], v2 = g_att[i];
    float s1 = v1, q1 = v1*v1, s2 = v2, q2 = v2*v2;
    #pragma unroll
    for (int o = 16; o; o >>= 1) {
        s1 += __shfl_down_sync(0xffffffffu, s1, o);
        q1 += __shfl_down_sync(0xffffffffu, q1, o);
        s2 += __shfl_down_sync(0xffffffffu, s2, o);
        q2 += __shfl_down_sync(0xffffffffu, q2, o);
    }
    __shared__ float sh[4][8];
    __shared__ float fin[4];
    int w = t >> 5, l = t & 31;
    if (l == 0) { sh[0][w]=s1; sh[1][w]=q1; sh[2][w]=s2; sh[3][w]=q2; }
    __syncthreads();
    if (t < 4) { float a = 0.f; for (int j = 0; j < 8; ++j) a += sh[t][j]; fin[t] = a; }
    __syncthreads();
    float m1 = fin[0]/CC, r1 = rsqrtf(fin[1]/CC - m1*m1 + 1e-5f);
    float m2 = fin[2]/CC, r2 = rsqrtf(fin[3]/CC - m2*m2 + 1e-5f);
    float o1 = (v1 - m1)*r1*lg[t] + lb[t];
    float o2 = (v2 - m2)*r2*lg[t] + lb[t];
    g_xt[i]     = o1;
    g_xt_bf[i]  = __float2bfloat16(o1);
    g_xct_bf[i] = __float2bfloat16(o2);
}

__global__ void k_pool(const float* __restrict__ wp)
{
    int b = blockIdx.x, ch = blockIdx.y;
    int c = threadIdx.x;
    int n0 = ch*432;
    const __nv_bfloat16* base = g_xct_bf + ((size_t)b*NNT + n0)*CC + c;
    float acc = 0.f;
    for (int n = 0; n < 432; ++n)
        acc += __bfloat162float(base[(size_t)n*CC]) * wp[n0+n];
    atomicAdd(&g_zero[ZOFF_POOL + b*CC + c], acc);
}

__global__ void k_gate(const float* __restrict__ bp, const float* __restrict__ w1,
                       const float* __restrict__ w2)
{
    __shared__ float ps[256], hs[64];
    int b = blockIdx.x, t = threadIdx.x;
    ps[t] = g_zero[ZOFF_POOL + b*CC + t] + bp[0];
    __syncthreads();
    if (t < 64) {
        float a = 0.f;
        for (int c = 0; c < 256; ++c) a += ps[c]*w1[c*64 + t];
        hs[t] = fmaxf(a, 0.f);
    }
    __syncthreads();
    float a = 0.f;
    for (int j = 0; j < 64; ++j) a += hs[j]*w2[j*256 + t];
    g_gate[b*CC + t] = 1.f/(1.f + expf(-a));
}

// bf16 tensor-core GEMM: C[M,Nld] = A[M,256] @ B[256,Nld] (+bias, optional gate on A cols)
__global__ __launch_bounds__(256) void k_mma(
    const __nv_bfloat16* __restrict__ A, const __nv_bfloat16* __restrict__ Bw,
    const float* __restrict__ bias, const float* __restrict__ gate,
    float* __restrict__ Cf, __nv_bfloat16* __restrict__ Cb,
    int Nld, int ldc, int coff)
{
    __shared__ __align__(16) __nv_bfloat16 As[128][40];
    __shared__ __align__(16) __nv_bfloat16 Bs[32][136];
    int tid = threadIdx.x;
    int wid = tid >> 5, lane = tid & 31;
    int wm = wid >> 2;   // 0-1, 64 rows
    int wn = wid & 3;    // 0-3, 32 cols
    int m0 = blockIdx.y * 128;
    int n0 = blockIdx.x * 128;

    float acc[4][4][4] = {};
    const float* grow = gate ? (gate + (m0 / NNT)*CC) : (const float*)0;

    for (int k0 = 0; k0 < 256; k0 += 32) {
        #pragma unroll
        for (int p = 0; p < 2; ++p) {
            int idx = tid + p*256;
            int r = idx >> 2, seg = idx & 3;
            uint4 v = *(const uint4*)(A + (size_t)(m0 + r)*256 + k0 + seg*8);
            if (grow) {
                __nv_bfloat16 tmp[8];
                *(uint4*)tmp = v;
                #pragma unroll
                for (int j = 0; j < 8; ++j)
                    tmp[j] = __float2bfloat16(__bfloat162float(tmp[j]) * grow[k0+seg*8+j]);
                v = *(uint4*)tmp;
            }
            *(uint4*)&As[r][seg*8] = v;
        }
        #pragma unroll
        for (int p = 0; p < 2; ++p) {
            int idx = tid + p*256;
            int r = idx >> 4, seg = idx & 15;
            *(uint4*)&Bs[r][seg*8] = *(const uint4*)(Bw + (size_t)(k0 + r)*Nld + n0 + seg*8);
        }
        __syncthreads();
        #pragma unroll
        for (int kk = 0; kk < 2; ++kk) {
            unsigned int af[4][4];
            #pragma unroll
            for (int mt = 0; mt < 4; ++mt)
                ldm_x4(af[mt], &As[wm*64 + mt*16 + (lane & 15)][kk*16 + (lane >> 4)*8]);
            unsigned int bfr[2][4];
            #pragma unroll
            for (int g2 = 0; g2 < 2; ++g2)
                ldm_x4_t(bfr[g2], &Bs[kk*16 + (lane & 15)][wn*32 + g2*16 + (lane >> 4)*8]);
            #pragma unroll
            for (int mt = 0; mt < 4; ++mt)
                #pragma unroll
                for (int nt = 0; nt < 4; ++nt)
                    mma16816(acc[mt][nt], af[mt],
                             bfr[nt>>1][(nt&1)*2], bfr[nt>>1][(nt&1)*2+1]);
        }
        __syncthreads();
    }
    #pragma unroll
    for (int mt = 0; mt < 4; ++mt) {
        int row0 = m0 + wm*64 + mt*16 + (lane >> 2);
        #pragma unroll
        for (int nt = 0; nt < 4; ++nt) {
            int col = wn*32 + nt*8 + (lane & 3)*2;
            #pragma unroll
            for (int h = 0; h < 2; ++h) {
                int r = row0 + h*8;
                float v0 = acc[mt][nt][h*2+0];
                float v1 = acc[mt][nt][h*2+1];
                if (bias) { v0 += bias[n0+col]; v1 += bias[n0+col+1]; }
                if (Cf) {
                    float* p = Cf + (size_t)r*ldc + coff + n0 + col;
                    p[0] = v0; p[1] = v1;
                } else {
                    __nv_bfloat16* p = Cb + (size_t)r*ldc + coff + n0 + col;
                    p[0] = __float2bfloat16(v0); p[1] = __float2bfloat16(v1);
                }
            }
        }
    }
}

__global__ void k_qss()
{
    int b = blockIdx.x, ch = blockIdx.y;
    int t = threadIdx.x;
    const __nv_bfloat16* base = g_qkv_bf + ((size_t)b*NNT + ch*432)*768 + t;
    float acc = 0.f;
    for (int n = 0; n < 432; ++n) {
        float v = __bfloat162float(base[(size_t)n*768]); acc += v*v;
    }
    atomicAdd(&g_zero[ZOFF_QSS + b*256 + t], acc);
}

__global__ void k_qrn()
{
    int i = blockIdx.x*256 + threadIdx.x;
    g_qrn[i] = 1.f / fmaxf(sqrtf(g_zero[ZOFF_QSS + i]), 1e-12f);
}

__global__ __launch_bounds__(256) void k_kvproj(const float* __restrict__ we)
{
    int bh = blockIdx.x;
    int which = blockIdx.y;
    int n0 = blockIdx.z * 512;
    int b = bh >> 2, h = bh & 3;
    const __nv_bfloat16* src = g_qkv_bf + (size_t)b*NNT*768 + (which+1)*256 + h*64;
    __shared__ float ks[64][65], es[64][65];
    int tid = threadIdx.x;
    int tx = tid & 15, ty = tid >> 4;
    float acc[4][4] = {};
    for (int c = 0; c < 8; ++c) {
        int nb = n0 + c*64;
        #pragma unroll
        for (int l = 0; l < 16; ++l) {
            int idx = l*256 + tid;
            int nn = idx >> 6, d = idx & 63;
            ks[nn][d] = __bfloat162float(src[(size_t)(nb+nn)*768 + d]);
            es[nn][d] = we[(size_t)(nb+nn)*64 + d];
        }
        __syncthreads();
        for (int nn = 0; nn < 64; ++nn) {
            float a[4], e[4];
            #pragma unroll
            for (int i = 0; i < 4; ++i) a[i] = ks[nn][ty*4 + i];
            #pragma unroll
            for (int j = 0; j < 4; ++j) e[j] = es[nn][tx*4 + j];
            #pragma unroll
            for (int i = 0; i < 4; ++i)
                #pragma unroll
                for (int j = 0; j < 4; ++j) acc[i][j] += a[i]*e[j];
        }
        __syncthreads();
    }
    float* out = &g_zero[ZOFF_KP + which*32768 + bh*4096];
    #pragma unroll
    for (int i = 0; i < 4; ++i)
        #pragma unroll
        for (int j = 0; j < 4; ++j)
            atomicAdd(&out[(ty*4+i)*64 + tx*4 + j], acc[i][j]);
}

__global__ __launch_bounds__(256) void k_attn(const float* __restrict__ be,
                                              const float* __restrict__ temp)
{
    int bh = blockIdx.y; int b = bh >> 2, h = bh & 3;
    int n0 = blockIdx.x*64;
    __shared__ float s1[64][65];
    __shared__ float s2[64][65];
    int tid = threadIdx.x;
    const float* kbase = &g_zero[ZOFF_KP + bh*4096];
    const float* vbase = &g_zero[ZOFF_VP + bh*4096];
    #pragma unroll
    for (int l = 0; l < 16; ++l) {
        int idx = l*256 + tid;
        int r = idx >> 6, cidx = idx & 63;
        s2[r][cidx] = kbase[idx] + be[cidx];
        s1[r][cidx] = __bfloat162float(
            g_qkv_bf[((size_t)(b*NNT + n0 + r))*768 + h*64 + cidx])
            * g_qrn[b*256 + h*64 + cidx];
    }
    __syncthreads();
    int tx = tid & 15, ty = tid >> 4;
    float acc[4][4] = {};
    for (int d = 0; d < 64; ++d) {
        float a[4], kv[4];
        #pragma unroll
        for (int i = 0; i < 4; ++i) a[i] = s1[ty*4+i][d];
        #pragma unroll
        for (int j = 0; j < 4; ++j) kv[j] = s2[d][tx*4+j];
        #pragma unroll
        for (int i = 0; i < 4; ++i)
            #pragma unroll
            for (int j = 0; j < 4; ++j) acc[i][j] += a[i]*kv[j];
    }
    float ts = temp[h];
    __syncthreads();
    #pragma unroll
    for (int i = 0; i < 4; ++i)
        #pragma unroll
        for (int j = 0; j < 4; ++j) s1[ty*4+i][tx*4+j] = acc[i][j]*ts;
    #pragma unroll
    for (int l = 0; l < 16; ++l) {
        int idx = l*256 + tid;
        int d = idx >> 6, p = idx & 63;
        s2[d][p] = vbase[idx] + be[p];
    }
    __syncthreads();
    if (tid < 64) {
        float mx = -1e30f;
        for (int p = 0; p < 64; ++p) mx = fmaxf(mx, s1[tid][p]);
        float s = 0.f;
        for (int p = 0; p < 64; ++p) { float e = expf(s1[tid][p]-mx); s1[tid][p] = e; s += e; }
        float inv = 1.f/s;
        for (int p = 0; p < 64; ++p) s1[tid][p] *= inv;
    }
    __syncthreads();
    float acc2[4][4] = {};
    for (int p = 0; p < 64; ++p) {
        float a[4], v[4];
        #pragma unroll
        for (int i = 0; i < 4; ++i) a[i] = s1[ty*4+i][p];
        #pragma unroll
        for (int j = 0; j < 4; ++j) v[j] = s2[tx*4+j][p];
        #pragma unroll
        for (int i = 0; i < 4; ++i)
            #pragma unroll
            for (int j = 0; j < 4; ++j) acc2[i][j] += a[i]*v[j];
    }
    __syncthreads();
    #pragma unroll
    for (int i = 0; i < 4; ++i)
        #pragma unroll
        for (int j = 0; j < 4; ++j) s1[tx*4+j][ty*4+i] = acc2[i][j];
    __syncthreads();
    #pragma unroll
    for (int l = 0; l < 16; ++l) {
        int idx = l*256 + tid;
        int d = idx >> 6, nn = idx & 63;
        g_sa_bf[(size_t)b*NNT*CC + (size_t)(d*4 + h)*NNT + n0 + nn]
            = __float2bfloat16(s1[d][nn]);
    }
}

__global__ void k_final(const float* __restrict__ gamma, float* __restrict__ out)
{
    __shared__ float t1[32][33];
    int n0 = blockIdx.x*32, c0 = blockIdx.y*32, b = blockIdx.z;
    int tx = threadIdx.x, ty = threadIdx.y;
    for (int yy = ty; yy < 32; yy += 8) {
        size_t s = ((size_t)b*NNT + n0 + yy)*CC + c0 + tx;
        t1[yy][tx] = g_xt[s] + gamma[c0+tx]*g_att[s];
    }
    __syncthreads();
    for (int yy = ty; yy < 32; yy += 8)
        out[(size_t)(b*CC + c0 + yy)*NNT + n0 + tx] = t1[tx][yy];
}

// ---------------- launch ----------------
extern "C" void kernel_launch(void* const* d_in, const int* in_sizes, int n_in,
                              void* d_out, int out_size)
{
    const float* x      = (const float*)d_in[0];
    const float* pos    = (const float*)d_in[1];
    const float* ln_g   = (const float*)d_in[2];
    const float* ln_b   = (const float*)d_in[3];
    const float* gamma  = (const float*)d_in[4];
    const float* temp2  = (const float*)d_in[5];
    const float* w_qkv  = (const float*)d_in[6];
    const float* w_e    = (const float*)d_in[7];
    const float* b_e    = (const float*)d_in[8];
    const float* w_pool = (const float*)d_in[9];
    const float* b_pool = (const float*)d_in[10];
    const float* w_fc1  = (const float*)d_in[11];
    const float* w_fc2  = (const float*)d_in[12];
    const float* w_out1 = (const float*)d_in[13];
    const float* b_out1 = (const float*)d_in[14];
    const float* w_out2 = (const float*)d_in[15];
    const float* b_out2 = (const float*)d_in[16];
    const float* w_c1   = (const float*)d_in[17];
    const float* b_c1   = (const float*)d_in[18];
    const float* w_c2   = (const float*)d_in[19];
    const float* b_c2   = (const float*)d_in[20];

    __nv_bfloat16 *p_h1b, *p_c2b, *p_xtbf, *p_xctbf, *p_qkvbf, *p_sabf;
    __nv_bfloat16 *p_wq, *p_w1, *p_w2;
    float *p_att, *p_gate;
    float2 *p_st1, *p_st2;
    cudaGetSymbolAddress((void**)&p_h1b,  g_h1b);
    cudaGetSymbolAddress((void**)&p_c2b,  g_c2b);
    cudaGetSymbolAddress((void**)&p_xtbf, g_xt_bf);
    cudaGetSymbolAddress((void**)&p_xctbf,g_xct_bf);
    cudaGetSymbolAddress((void**)&p_qkvbf,g_qkv_bf);
    cudaGetSymbolAddress((void**)&p_sabf, g_sa_bf);
    cudaGetSymbolAddress((void**)&p_wq,   g_wqkv_bf);
    cudaGetSymbolAddress((void**)&p_w1,   g_wo1_bf);
    cudaGetSymbolAddress((void**)&p_w2,   g_wo2_bf);
    cudaGetSymbolAddress((void**)&p_att,  g_att);
    cudaGetSymbolAddress((void**)&p_gate, g_gate);
    cudaGetSymbolAddress((void**)&p_st1,  g_st1);
    cudaGetSymbolAddress((void**)&p_st2,  g_st2);

    k_zero <<<(ZTOT+255)/256, 256>>>();
    k_wcvt <<<768, 256>>>(w_qkv, w_out1, w_out2);
    // MHCResBlock
    k_conv <<<dim3(54,16), 256>>>(x, (const __nv_bfloat16*)0, w_c1, b_c1, p_h1b, (const float2*)0);
    k_stats<<<512, 256>>>(p_h1b, p_st1);
    k_conv <<<dim3(54,16), 256>>>((const float*)0, p_h1b, w_c2, b_c2, p_c2b, p_st1);
    k_stats<<<512, 256>>>(p_c2b, p_st2);
    // tokens + LN (xc fused into trans)
    k_trans<<<dim3(432,8,BB), dim3(32,8)>>>(x, pos);
    k_ln   <<<MTOT, 256>>>(ln_g, ln_b);
    // channel attention gate
    k_pool <<<dim3(BB,32), 256>>>(w_pool);
    k_gate <<<BB, 256>>>(b_pool, w_fc1, w_fc2);
    // qkv (bf16 tensor cores)
    k_mma  <<<dim3(6,216), 256>>>(p_xtbf, p_wq, (const float*)0, (const float*)0,
                                  (float*)0, p_qkvbf, 768, 768, 0);
    // q token-norms
    k_qss  <<<dim3(BB,32), 256>>>();
    k_qrn  <<<2, 256>>>();
    // low-rank K/V projection
    k_kvproj<<<dim3(BB*NHH, 2, 27), 256>>>(w_e);
    // spatial attention (+ scramble, bf16 out)
    k_attn <<<dim3(216, BB*NHH), 256>>>(b_e, temp2);
    // output projections (bf16 tensor cores, fp32 out)
    k_mma  <<<dim3(1,216), 256>>>(p_sabf,  p_w1, b_out1, (const float*)0,
                                  p_att, (__nv_bfloat16*)0, 128, 256, 0);
    k_mma  <<<dim3(1,216), 256>>>(p_xctbf, p_w2, b_out2, p_gate,
                                  p_att, (__nv_bfloat16*)0, 128, 256, 128);
    // residual + gamma, transpose to [B,C,N]
    k_final<<<dim3(432,8,BB), dim3(32,8)>>>(gamma, (float*)d_out);
}

// round 5
// speedup vs baseline: 1.9328x; 1.1514x over previous
#include <cuda_runtime.h>
#include <cuda_bf16.h>
#include <cstdint>
#include <math.h>

#define BB 2
#define CC 256
#define NNT 13824
#define NHH 4
#define MTOT (BB*NNT)

// ---------------- scratch ----------------
__device__ __nv_bfloat16 g_h1b[BB*CC*NNT];            // conv1 out
__device__ __nv_bfloat16 g_c2b[BB*CC*NNT];            // conv2 raw out
__device__ float         g_xt [BB*NNT*CC];            // xt_pre -> x_n (fp32 residual)
__device__ __nv_bfloat16 g_xcpre[BB*NNT*CC];          // xct_pre (bf16) -> REUSED as concat out
__device__ __nv_bfloat16 g_xt_bf [BB*NNT*CC];         // x_n bf16 (qkv A)
__device__ __nv_bfloat16 g_xct_bf[BB*NNT*CC];         // xc_n bf16
__device__ __nv_bfloat16 g_qkv_bf[(size_t)BB*NNT*768];
__device__ __nv_bfloat16 g_sa_bf [BB*NNT*CC];         // scrambled x_SA
__device__ __nv_bfloat16 g_wqkv_bf[256*768];
__device__ __nv_bfloat16 g_wo1_bf [256*128];
__device__ __nv_bfloat16 g_wo2_bf [256*128];
__device__ __nv_bfloat16 g_we_bf  [NNT*64];
__device__ float2 g_st1[BB*CC];
__device__ float2 g_st2[BB*CC];
#define ZOFF_POOL 0
#define ZOFF_QSS  512
#define ZOFF_KP   1024
#define ZOFF_VP   33792
#define ZTOT      66560
__device__ float g_zero[ZTOT];
__device__ float g_qrn [BB*CC];
__device__ float g_gate[BB*CC];

// ---------------- asm helpers ----------------
__device__ __forceinline__ void ldm_x4(unsigned int (&r)[4], const void* p) {
    unsigned int a = (unsigned int)__cvta_generic_to_shared(p);
    asm volatile("ldmatrix.sync.aligned.m8n8.x4.shared.b16 {%0,%1,%2,%3}, [%4];"
        : "=r"(r[0]),"=r"(r[1]),"=r"(r[2]),"=r"(r[3]) : "r"(a));
}
__device__ __forceinline__ void ldm_x4_t(unsigned int (&r)[4], const void* p) {
    unsigned int a = (unsigned int)__cvta_generic_to_shared(p);
    asm volatile("ldmatrix.sync.aligned.m8n8.x4.trans.shared.b16 {%0,%1,%2,%3}, [%4];"
        : "=r"(r[0]),"=r"(r[1]),"=r"(r[2]),"=r"(r[3]) : "r"(a));
}
__device__ __forceinline__ void mma16816(float (&d)[4], const unsigned int (&a)[4],
                                         unsigned int b0, unsigned int b1) {
    asm volatile("mma.sync.aligned.m16n8k16.row.col.f32.bf16.bf16.f32 "
        "{%0,%1,%2,%3},{%4,%5,%6,%7},{%8,%9},{%0,%1,%2,%3};"
        : "+f"(d[0]),"+f"(d[1]),"+f"(d[2]),"+f"(d[3])
        : "r"(a[0]),"r"(a[1]),"r"(a[2]),"r"(a[3]),"r"(b0),"r"(b1));
}
__device__ __forceinline__ void cpa16(void* dst, const void* src) {
    unsigned int d = (unsigned int)__cvta_generic_to_shared(dst);
    asm volatile("cp.async.cg.shared.global [%0], [%1], 16;" :: "r"(d), "l"(src));
}
__device__ __forceinline__ void cp_commit() { asm volatile("cp.async.commit_group;"); }
template<int N> __device__ __forceinline__ void cp_wait() {
    asm volatile("cp.async.wait_group %0;" :: "n"(N));
}

// ---------------- kernels ----------------
__global__ void k_zero() {
    int i = blockIdx.x*256 + threadIdx.x;
    if (i < ZTOT) g_zero[i] = 0.f;
}

__global__ void k_wcvt(const float* __restrict__ wq, const float* __restrict__ w1,
                       const float* __restrict__ w2, const float* __restrict__ we)
{
    int i = blockIdx.x*256 + threadIdx.x;
    if (i < 196608) g_wqkv_bf[i] = __float2bfloat16(wq[i]);
    if (i < 32768)  { g_wo1_bf[i] = __float2bfloat16(w1[i]);
                      g_wo2_bf[i] = __float2bfloat16(w2[i]); }
    if (i < NNT*64) g_we_bf[i] = __float2bfloat16(we[i]);
}

// grouped 1x1x1 conv; conv2 fuses instance-norm + lrelu of its input
__global__ __launch_bounds__(256) void k_conv(
    const float* __restrict__ srcf, const __nv_bfloat16* __restrict__ srcb,
    const float* __restrict__ w, const float* __restrict__ bias,
    __nv_bfloat16* __restrict__ dst, const float2* __restrict__ instat)
{
    int bg = blockIdx.y; int b = bg >> 3; int g = bg & 7;
    int n  = blockIdx.x*256 + threadIdx.x;
    __shared__ float ws[1024];
    for (int i = threadIdx.x; i < 1024; i += 256) ws[i] = w[g*1024 + i];
    __syncthreads();
    int cbase = b*CC + g*32;
    float acc[32];
    #pragma unroll
    for (int o = 0; o < 32; ++o) acc[o] = bias[g*32+o];
    bool useb = (srcb != nullptr);
    #pragma unroll 4
    for (int i = 0; i < 32; ++i) {
        float v;
        if (useb) {
            v = __bfloat162float(srcb[(size_t)(cbase+i)*NNT + n]);
            float2 st = instat[cbase+i];
            v = (v - st.x)*st.y;
            v = v >= 0.f ? v : 0.01f*v;
        } else {
            v = srcf[(size_t)(cbase+i)*NNT + n];
        }
        #pragma unroll
        for (int o = 0; o < 32; ++o) acc[o] += v*ws[i*32+o];
    }
    #pragma unroll 4
    for (int o = 0; o < 32; ++o)
        dst[(size_t)(cbase+o)*NNT + n] = __float2bfloat16(acc[o]);
}

// instance-norm stats per (b,c) row — vectorized uint4 (8 bf16/load)
__global__ void k_stats(const __nv_bfloat16* __restrict__ src, float2* __restrict__ st)
{
    int row = blockIdx.x;
    const uint4* p4 = (const uint4*)(src + (size_t)row*NNT);
    float s = 0.f, q = 0.f;
    for (int i = threadIdx.x; i < NNT/8; i += 256) {
        uint4 v = p4[i];
        const __nv_bfloat162* h = (const __nv_bfloat162*)&v;
        #pragma unroll
        for (int j = 0; j < 4; ++j) {
            float2 f = __bfloat1622float2(h[j]);
            s += f.x + f.y; q += f.x*f.x + f.y*f.y;
        }
    }
    #pragma unroll
    for (int o = 16; o; o >>= 1) {
        s += __shfl_down_sync(0xffffffffu, s, o);
        q += __shfl_down_sync(0xffffffffu, q, o);
    }
    __shared__ float sh[16];
    int w = threadIdx.x >> 5, l = threadIdx.x & 31;
    if (l == 0) { sh[w] = s; sh[w+8] = q; }
    __syncthreads();
    if (threadIdx.x == 0) {
        float S = 0.f, Q = 0.f;
        for (int i = 0; i < 8; ++i) { S += sh[i]; Q += sh[i+8]; }
        float m = S / NNT;
        st[row] = make_float2(m, rsqrtf(Q/NNT - m*m + 1e-5f));
    }
}

// fused: xc = lrelu(inorm(conv2)+x); write xt_pre (fp32) and xct_pre (bf16)
__global__ void k_trans(const float* __restrict__ x, const float* __restrict__ pos)
{
    __shared__ float t1[32][33], t2[32][33];
    int n0 = blockIdx.x*32, c0 = blockIdx.y*32, b = blockIdx.z;
    int tx = threadIdx.x, ty = threadIdx.y;
    for (int yy = ty; yy < 32; yy += 8) {
        size_t s = (size_t)(b*CC + c0 + yy)*NNT + n0 + tx;
        float xv = x[s];
        float2 st = g_st2[b*CC + c0 + yy];
        float hv = (__bfloat162float(g_c2b[s]) - st.x)*st.y + xv;
        t1[yy][tx] = xv;
        t2[yy][tx] = hv >= 0.f ? hv : 0.01f*hv;
    }
    __syncthreads();
    for (int yy = ty; yy < 32; yy += 8) {
        float p = pos[(size_t)(n0+yy)*CC + c0 + tx];
        size_t d = ((size_t)b*NNT + n0 + yy)*CC + c0 + tx;
        g_xt   [d] = t1[tx][yy] + p;
        g_xcpre[d] = __float2bfloat16(t2[tx][yy] + p);
    }
}

// LayerNorm: warp per token, no block barriers
__global__ __launch_bounds__(256) void k_ln(const float* __restrict__ lg,
                                            const float* __restrict__ lb)
{
    int wid = threadIdx.x >> 5, lane = threadIdx.x & 31;
    size_t row = (size_t)blockIdx.x*8 + wid;
    size_t base = row*CC;
    float v1[8], v2[8];
    float s1 = 0.f, q1 = 0.f, s2 = 0.f, q2 = 0.f;
    #pragma unroll
    for (int j = 0; j < 8; ++j) {
        v1[j] = g_xt[base + j*32 + lane];
        v2[j] = __bfloat162float(g_xcpre[base + j*32 + lane]);
        s1 += v1[j]; q1 += v1[j]*v1[j];
        s2 += v2[j]; q2 += v2[j]*v2[j];
    }
    #pragma unroll
    for (int o = 16; o; o >>= 1) {
        s1 += __shfl_xor_sync(0xffffffffu, s1, o);
        q1 += __shfl_xor_sync(0xffffffffu, q1, o);
        s2 += __shfl_xor_sync(0xffffffffu, s2, o);
        q2 += __shfl_xor_sync(0xffffffffu, q2, o);
    }
    float m1 = s1/CC, r1 = rsqrtf(q1/CC - m1*m1 + 1e-5f);
    float m2 = s2/CC, r2 = rsqrtf(q2/CC - m2*m2 + 1e-5f);
    #pragma unroll
    for (int j = 0; j < 8; ++j) {
        int c = j*32 + lane;
        size_t i = base + c;
        float o1 = (v1[j] - m1)*r1*lg[c] + lb[c];
        float o2 = (v2[j] - m2)*r2*lg[c] + lb[c];
        g_xt[i]     = o1;
        g_xt_bf[i]  = __float2bfloat16(o1);
        g_xct_bf[i] = __float2bfloat16(o2);
    }
}

__global__ void k_pool(const float* __restrict__ wp)
{
    int b = blockIdx.x, ch = blockIdx.y;
    int c = threadIdx.x;
    int n0 = ch*432;
    const __nv_bfloat16* base = g_xct_bf + ((size_t)b*NNT + n0)*CC + c;
    float acc = 0.f;
    #pragma unroll 4
    for (int n = 0; n < 432; ++n)
        acc += __bfloat162float(base[(size_t)n*CC]) * wp[n0+n];
    atomicAdd(&g_zero[ZOFF_POOL + b*CC + c], acc);
}

__global__ void k_gate(const float* __restrict__ bp, const float* __restrict__ w1,
                       const float* __restrict__ w2)
{
    __shared__ float ps[256], hs[64];
    int b = blockIdx.x, t = threadIdx.x;
    ps[t] = g_zero[ZOFF_POOL + b*CC + t] + bp[0];
    __syncthreads();
    if (t < 64) {
        float a = 0.f;
        for (int c = 0; c < 256; ++c) a += ps[c]*w1[c*64 + t];
        hs[t] = fmaxf(a, 0.f);
    }
    __syncthreads();
    float a = 0.f;
    for (int j = 0; j < 64; ++j) a += hs[j]*w2[j*256 + t];
    g_gate[b*CC + t] = 1.f/(1.f + expf(-a));
}

// bf16 tensor-core GEMM with cp.async double buffering.
// blockIdx.z==1 selects (A2,Bw2,bias2,coff=128,gated).
__global__ __launch_bounds__(256) void k_mma(
    const __nv_bfloat16* __restrict__ A, const __nv_bfloat16* __restrict__ A2,
    const __nv_bfloat16* __restrict__ Bw, const __nv_bfloat16* __restrict__ Bw2,
    const float* __restrict__ bias, const float* __restrict__ bias2,
    const float* __restrict__ gate,
    __nv_bfloat16* __restrict__ Cb, int Nld, int ldc)
{
    __shared__ __align__(16) __nv_bfloat16 As[2][128][40];
    __shared__ __align__(16) __nv_bfloat16 Bs[2][32][136];
    int tid = threadIdx.x;
    int wid = tid >> 5, lane = tid & 31;
    int wm = wid >> 2;
    int wn = wid & 3;
    int m0 = blockIdx.y * 128;
    int n0 = blockIdx.x * 128;
    int coff = 0;
    const float* grow = nullptr;
    if (blockIdx.z == 1) {
        A = A2; Bw = Bw2; bias = bias2; coff = 128;
        grow = gate + (m0 / NNT)*CC;
    }

    float acc[4][4][4] = {};

    // prologue
    #pragma unroll
    for (int p = 0; p < 2; ++p) {
        int idx = p*256 + tid; int r = idx >> 2, sg = idx & 3;
        cpa16(&As[0][r][sg*8], A + (size_t)(m0 + r)*256 + sg*8);
    }
    #pragma unroll
    for (int p = 0; p < 2; ++p) {
        int idx = p*256 + tid; int r = idx >> 4, sg = idx & 15;
        cpa16(&Bs[0][r][sg*8], Bw + (size_t)r*Nld + n0 + sg*8);
    }
    cp_commit();

    for (int it = 0; it < 8; ++it) {
        int k0 = it*32, st = it & 1;
        if (it < 7) {
            int kn = k0 + 32, sn = st ^ 1;
            #pragma unroll
            for (int p = 0; p < 2; ++p) {
                int idx = p*256 + tid; int r = idx >> 2, sg = idx & 3;
                cpa16(&As[sn][r][sg*8], A + (size_t)(m0 + r)*256 + kn + sg*8);
            }
            #pragma unroll
            for (int p = 0; p < 2; ++p) {
                int idx = p*256 + tid; int r = idx >> 4, sg = idx & 15;
                cpa16(&Bs[sn][r][sg*8], Bw + (size_t)(kn + r)*Nld + n0 + sg*8);
            }
            cp_commit();
            cp_wait<1>();
        } else {
            cp_wait<0>();
        }
        __syncthreads();
        if (grow) {
            #pragma unroll
            for (int p = 0; p < 2; ++p) {
                int idx = p*256 + tid; int r = idx >> 2, sg = idx & 3;
                __nv_bfloat16* qp = &As[st][r][sg*8];
                #pragma unroll
                for (int j = 0; j < 8; ++j)
                    qp[j] = __float2bfloat16(__bfloat162float(qp[j])*grow[k0+sg*8+j]);
            }
            __syncthreads();
        }
        #pragma unroll
        for (int kk = 0; kk < 2; ++kk) {
            unsigned int af[4][4];
            #pragma unroll
            for (int mt = 0; mt < 4; ++mt)
                ldm_x4(af[mt], &As[st][wm*64 + mt*16 + (lane & 15)][kk*16 + (lane >> 4)*8]);
            unsigned int bfr[2][4];
            #pragma unroll
            for (int g2 = 0; g2 < 2; ++g2)
                ldm_x4_t(bfr[g2], &Bs[st][kk*16 + (lane & 15)][wn*32 + g2*16 + (lane >> 4)*8]);
            #pragma unroll
            for (int mt = 0; mt < 4; ++mt)
                #pragma unroll
                for (int nt = 0; nt < 4; ++nt)
                    mma16816(acc[mt][nt], af[mt],
                             bfr[nt>>1][(nt&1)*2], bfr[nt>>1][(nt&1)*2+1]);
        }
        __syncthreads();
    }
    #pragma unroll
    for (int mt = 0; mt < 4; ++mt) {
        int row0 = m0 + wm*64 + mt*16 + (lane >> 2);
        #pragma unroll
        for (int nt = 0; nt < 4; ++nt) {
            int col = wn*32 + nt*8 + (lane & 3)*2;
            #pragma unroll
            for (int h = 0; h < 2; ++h) {
                int r = row0 + h*8;
                float v0 = acc[mt][nt][h*2+0];
                float v1 = acc[mt][nt][h*2+1];
                if (bias) { v0 += bias[n0+col]; v1 += bias[n0+col+1]; }
                __nv_bfloat16* p = Cb + (size_t)r*ldc + coff + n0 + col;
                p[0] = __float2bfloat16(v0); p[1] = __float2bfloat16(v1);
            }
        }
    }
}

__global__ void k_qss()
{
    int b = blockIdx.x, ch = blockIdx.y;
    int t = threadIdx.x;
    const __nv_bfloat16* base = g_qkv_bf + ((size_t)b*NNT + ch*432)*768 + t;
    float acc = 0.f;
    #pragma unroll 4
    for (int n = 0; n < 432; ++n) {
        float v = __bfloat162float(base[(size_t)n*768]); acc += v*v;
    }
    atomicAdd(&g_zero[ZOFF_QSS + b*256 + t], acc);
}

__global__ void k_qrn()
{
    int i = blockIdx.x*256 + threadIdx.x;
    g_qrn[i] = 1.f / fmaxf(sqrtf(g_zero[ZOFF_QSS + i]), 1e-12f);
}

// K/V low-rank projection via tensor cores.
// out[m=d(256), p(64)] = sum_n kv[n, m] * we[n, p]; A trans-loaded from [n][d] tiles.
__global__ __launch_bounds__(256) void k_kvmma()
{
    int b = blockIdx.x >> 1, which = blockIdx.x & 1;
    int n0 = blockIdx.y * 512;
    int coff = 256*(which+1);
    __shared__ __align__(16) __nv_bfloat16 Ks[32][264];
    __shared__ __align__(16) __nv_bfloat16 Es[32][72];
    int tid = threadIdx.x, lane = tid & 31, wid = tid >> 5;
    int m0w = wid*32;
    float acc[2][8][4] = {};

    for (int c = 0; c < 16; ++c) {
        int nt0 = n0 + c*32;
        #pragma unroll
        for (int v = 0; v < 4; ++v) {
            int idx = v*256 + tid; int r = idx >> 5, sg = idx & 31;
            *(uint4*)&Ks[r][sg*8] =
                *(const uint4*)(g_qkv_bf + ((size_t)(b*NNT + nt0 + r))*768 + coff + sg*8);
        }
        {
            int r = tid >> 3, sg = tid & 7;
            *(uint4*)&Es[r][sg*8] = *(const uint4*)(g_we_bf + (size_t)(nt0 + r)*64 + sg*8);
        }
        __syncthreads();
        #pragma unroll
        for (int kk = 0; kk < 32; kk += 16) {
            unsigned int af[2][4];
            #pragma unroll
            for (int mt = 0; mt < 2; ++mt)
                ldm_x4_t(af[mt], &Ks[kk + (lane & 7) + ((lane >> 4) << 3)]
                                    [m0w + mt*16 + ((lane >> 3) & 1)*8]);
            unsigned int bfr[4][4];
            #pragma unroll
            for (int ng = 0; ng < 4; ++ng)
                ldm_x4_t(bfr[ng], &Es[kk + (lane & 15)][ng*16 + (lane >> 4)*8]);
            #pragma unroll
            for (int mt = 0; mt < 2; ++mt)
                #pragma unroll
                for (int nt = 0; nt < 8; ++nt)
                    mma16816(acc[mt][nt], af[mt],
                             bfr[nt>>1][(nt&1)*2], bfr[nt>>1][(nt&1)*2+1]);
        }
        __syncthreads();
    }
    float* out = &g_zero[ZOFF_KP + which*32768 + b*16384];
    #pragma unroll
    for (int mt = 0; mt < 2; ++mt) {
        int m = m0w + mt*16 + (lane >> 2);
        #pragma unroll
        for (int nt = 0; nt < 8; ++nt) {
            int p = nt*8 + (lane & 3)*2;
            atomicAdd(&out[m*64 + p],       acc[mt][nt][0]);
            atomicAdd(&out[m*64 + p + 1],   acc[mt][nt][1]);
            atomicAdd(&out[(m+8)*64 + p],   acc[mt][nt][2]);
            atomicAdd(&out[(m+8)*64 + p+1], acc[mt][nt][3]);
        }
    }
}

__global__ __launch_bounds__(256) void k_attn(const float* __restrict__ be,
                                              const float* __restrict__ temp)
{
    int bh = blockIdx.y; int b = bh >> 2, h = bh & 3;
    int n0 = blockIdx.x*64;
    __shared__ float s1[64][65];
    __shared__ float s2[64][65];
    int tid = threadIdx.x;
    const float* kbase = &g_zero[ZOFF_KP + bh*4096];
    const float* vbase = &g_zero[ZOFF_VP + bh*4096];
    // load kproj (+be) and qn tiles, vectorized
    #pragma unroll
    for (int v = 0; v < 4; ++v) {
        int i4 = v*256 + tid; int d = i4 >> 4, pp = (i4 & 15)*4;
        float4 kv = *(const float4*)(kbase + d*64 + pp);
        s2[d][pp]   = kv.x + be[pp];
        s2[d][pp+1] = kv.y + be[pp+1];
        s2[d][pp+2] = kv.z + be[pp+2];
        s2[d][pp+3] = kv.w + be[pp+3];
    }
    #pragma unroll
    for (int l = 0; l < 2; ++l) {
        int i8 = l*256 + tid; int r = i8 >> 3, sg = (i8 & 7)*8;
        uint4 v = *(const uint4*)(g_qkv_bf + ((size_t)(b*NNT + n0 + r))*768 + h*64 + sg);
        const __nv_bfloat162* hh = (const __nv_bfloat162*)&v;
        #pragma unroll
        for (int j = 0; j < 4; ++j) {
            float2 f = __bfloat1622float2(hh[j]);
            s1[r][sg + j*2]   = f.x * g_qrn[b*256 + h*64 + sg + j*2];
            s1[r][sg + j*2+1] = f.y * g_qrn[b*256 + h*64 + sg + j*2+1];
        }
    }
    __syncthreads();
    int tx = tid & 15, ty = tid >> 4;
    float acc[4][4] = {};
    for (int d = 0; d < 64; ++d) {
        float a[4], kv[4];
        #pragma unroll
        for (int i = 0; i < 4; ++i) a[i] = s1[ty*4+i][d];
        #pragma unroll
        for (int j = 0; j < 4; ++j) kv[j] = s2[d][tx*4+j];
        #pragma unroll
        for (int i = 0; i < 4; ++i)
            #pragma unroll
            for (int j = 0; j < 4; ++j) acc[i][j] += a[i]*kv[j];
    }
    float ts = temp[h];
    __syncthreads();
    #pragma unroll
    for (int i = 0; i < 4; ++i)
        #pragma unroll
        for (int j = 0; j < 4; ++j) s1[ty*4+i][tx*4+j] = acc[i][j]*ts;
    #pragma unroll
    for (int v = 0; v < 4; ++v) {
        int i4 = v*256 + tid; int d = i4 >> 4, pp = (i4 & 15)*4;
        float4 vv = *(const float4*)(vbase + d*64 + pp);
        s2[d][pp]   = vv.x + be[pp];
        s2[d][pp+1] = vv.y + be[pp+1];
        s2[d][pp+2] = vv.z + be[pp+2];
        s2[d][pp+3] = vv.w + be[pp+3];
    }
    __syncthreads();
    // softmax: 4 threads per row
    {
        int row = tid >> 2, g4 = (tid & 3)*16;
        float mx = -1e30f;
        #pragma unroll
        for (int p = 0; p < 16; ++p) mx = fmaxf(mx, s1[row][g4+p]);
        mx = fmaxf(mx, __shfl_xor_sync(0xffffffffu, mx, 1));
        mx = fmaxf(mx, __shfl_xor_sync(0xffffffffu, mx, 2));
        float sum = 0.f;
        #pragma unroll
        for (int p = 0; p < 16; ++p) {
            float e = __expf(s1[row][g4+p] - mx);
            s1[row][g4+p] = e; sum += e;
        }
        sum += __shfl_xor_sync(0xffffffffu, sum, 1);
        sum += __shfl_xor_sync(0xffffffffu, sum, 2);
        float inv = 1.f/sum;
        #pragma unroll
        for (int p = 0; p < 16; ++p) s1[row][g4+p] *= inv;
    }
    __syncthreads();
    float acc2[4][4] = {};
    for (int p = 0; p < 64; ++p) {
        float a[4], v[4];
        #pragma unroll
        for (int i = 0; i < 4; ++i) a[i] = s1[ty*4+i][p];
        #pragma unroll
        for (int j = 0; j < 4; ++j) v[j] = s2[tx*4+j][p];
        #pragma unroll
        for (int i = 0; i < 4; ++i)
            #pragma unroll
            for (int j = 0; j < 4; ++j) acc2[i][j] += a[i]*v[j];
    }
    __syncthreads();
    #pragma unroll
    for (int i = 0; i < 4; ++i)
        #pragma unroll
        for (int j = 0; j < 4; ++j) s1[tx*4+j][ty*4+i] = acc2[i][j];   // s1[d][nn]
    __syncthreads();
    #pragma unroll
    for (int l = 0; l < 2; ++l) {
        int i8 = l*256 + tid; int d = i8 >> 3, nn = (i8 & 7)*8;
        __nv_bfloat16 tmp[8];
        #pragma unroll
        for (int j = 0; j < 8; ++j) tmp[j] = __float2bfloat16(s1[d][nn+j]);
        *(uint4*)&g_sa_bf[(size_t)b*NNT*CC + (size_t)(d*4 + h)*NNT + n0 + nn]
            = *(uint4*)tmp;
    }
}

__global__ void k_final(const float* __restrict__ gamma, float* __restrict__ out)
{
    __shared__ float t1[32][33];
    int n0 = blockIdx.x*32, c0 = blockIdx.y*32, b = blockIdx.z;
    int tx = threadIdx.x, ty = threadIdx.y;
    for (int yy = ty; yy < 32; yy += 8) {
        size_t s = ((size_t)b*NNT + n0 + yy)*CC + c0 + tx;
        t1[yy][tx] = g_xt[s] + gamma[c0+tx]*__bfloat162float(g_xcpre[s]);
    }
    __syncthreads();
    for (int yy = ty; yy < 32; yy += 8)
        out[(size_t)(b*CC + c0 + yy)*NNT + n0 + tx] = t1[tx][yy];
}

// ---------------- launch ----------------
extern "C" void kernel_launch(void* const* d_in, const int* in_sizes, int n_in,
                              void* d_out, int out_size)
{
    const float* x      = (const float*)d_in[0];
    const float* pos    = (const float*)d_in[1];
    const float* ln_g   = (const float*)d_in[2];
    const float* ln_b   = (const float*)d_in[3];
    const float* gamma  = (const float*)d_in[4];
    const float* temp2  = (const float*)d_in[5];
    const float* w_qkv  = (const float*)d_in[6];
    const float* w_e    = (const float*)d_in[7];
    const float* b_e    = (const float*)d_in[8];
    const float* w_pool = (const float*)d_in[9];
    const float* b_pool = (const float*)d_in[10];
    const float* w_fc1  = (const float*)d_in[11];
    const float* w_fc2  = (const float*)d_in[12];
    const float* b_out1 = (const float*)d_in[14];
    const float* b_out2 = (const float*)d_in[16];
    const float* w_c1   = (const float*)d_in[17];
    const float* b_c1   = (const float*)d_in[18];
    const float* w_c2   = (const float*)d_in[19];
    const float* b_c2   = (const float*)d_in[20];

    __nv_bfloat16 *p_h1b, *p_c2b, *p_xtbf, *p_xctbf, *p_qkvbf, *p_sabf, *p_xcpre;
    __nv_bfloat16 *p_wq, *p_w1, *p_w2;
    float *p_gate;
    float2 *p_st1, *p_st2;
    cudaGetSymbolAddress((void**)&p_h1b,   g_h1b);
    cudaGetSymbolAddress((void**)&p_c2b,   g_c2b);
    cudaGetSymbolAddress((void**)&p_xtbf,  g_xt_bf);
    cudaGetSymbolAddress((void**)&p_xctbf, g_xct_bf);
    cudaGetSymbolAddress((void**)&p_qkvbf, g_qkv_bf);
    cudaGetSymbolAddress((void**)&p_sabf,  g_sa_bf);
    cudaGetSymbolAddress((void**)&p_xcpre, g_xcpre);
    cudaGetSymbolAddress((void**)&p_wq,    g_wqkv_bf);
    cudaGetSymbolAddress((void**)&p_w1,    g_wo1_bf);
    cudaGetSymbolAddress((void**)&p_w2,    g_wo2_bf);
    cudaGetSymbolAddress((void**)&p_gate,  g_gate);
    cudaGetSymbolAddress((void**)&p_st1,   g_st1);
    cudaGetSymbolAddress((void**)&p_st2,   g_st2);

    k_zero <<<(ZTOT+255)/256, 256>>>();
    k_wcvt <<<(NNT*64+255)/256, 256>>>(w_qkv, (const float*)d_in[13],
                                       (const float*)d_in[15], w_e);
    // MHCResBlock
    k_conv <<<dim3(54,16), 256>>>(x, (const __nv_bfloat16*)0, w_c1, b_c1, p_h1b, (const float2*)0);
    k_stats<<<512, 256>>>(p_h1b, p_st1);
    k_conv <<<dim3(54,16), 256>>>((const float*)0, p_h1b, w_c2, b_c2, p_c2b, p_st1);
    k_stats<<<512, 256>>>(p_c2b, p_st2);
    // tokens + LN
    k_trans<<<dim3(432,8,BB), dim3(32,8)>>>(x, pos);
    k_ln   <<<MTOT/8, 256>>>(ln_g, ln_b);
    // channel attention gate
    k_pool <<<dim3(BB,32), 256>>>(w_pool);
    k_gate <<<BB, 256>>>(b_pool, w_fc1, w_fc2);
    // qkv (pipelined bf16 HMMA)
    k_mma  <<<dim3(6,216,1), 256>>>(p_xtbf, (const __nv_bfloat16*)0, p_wq,
                                    (const __nv_bfloat16*)0, (const float*)0,
                                    (const float*)0, (const float*)0,
                                    p_qkvbf, 768, 768);
    // q token-norms
    k_qss  <<<dim3(BB,32), 256>>>();
    k_qrn  <<<2, 256>>>();
    // low-rank K/V projection (tensor cores, split-N atomics)
    k_kvmma<<<dim3(4,27), 256>>>();
    // spatial attention (+ scramble)
    k_attn <<<dim3(216, BB*NHH), 256>>>(b_e, temp2);
    // both output projections in one launch (z=0: SA, z=1: CA gated), bf16 into g_xcpre
    k_mma  <<<dim3(1,216,2), 256>>>(p_sabf, p_xctbf, p_w1, p_w2,
                                    b_out1, b_out2, p_gate,
                                    p_xcpre, 128, 256);
    // residual + gamma, transpose to [B,C,N]
    k_final<<<dim3(432,8,BB), dim3(32,8)>>>(gamma, (float*)d_out);
}

// round 6
// speedup vs baseline: 2.5650x; 1.3271x over previous
#include <cuda_runtime.h>
#include <cuda_bf16.h>
#include <cstdint>
#include <math.h>

#define BB 2
#define CC 256
#define NNT 13824
#define NHH 4
#define MTOT (BB*NNT)

// ---------------- scratch ----------------
__device__ __nv_bfloat16 g_h1b[BB*CC*NNT];            // conv1 out
__device__ __nv_bfloat16 g_c2b[BB*CC*NNT];            // conv2 raw out
__device__ float         g_xt [BB*NNT*CC];            // xt_pre (fp32, pre-LN residual)
__device__ __nv_bfloat16 g_xcpre[BB*NNT*CC];          // xct_pre (bf16) -> REUSED as concat out
__device__ __nv_bfloat16 g_xt_bf [BB*NNT*CC];         // x_n bf16 (qkv A)
__device__ __nv_bfloat16 g_xct_bf[BB*NNT*CC];         // xc_n bf16
__device__ __nv_bfloat16 g_qkv_bf[(size_t)BB*NNT*768];
__device__ __nv_bfloat16 g_sa_bf [BB*NNT*CC];         // scrambled x_SA
__device__ __nv_bfloat16 g_wqkv_bf[256*768];
__device__ __nv_bfloat16 g_wo1_bf [256*128];
__device__ __nv_bfloat16 g_wo2_bf [256*128];
__device__ __nv_bfloat16 g_we_bf  [NNT*64];
__device__ float2 g_st1[BB*CC];
__device__ float2 g_st2[BB*CC];
__device__ float2 g_lnst[MTOT];                       // per-token (mean, rstd)
#define ZOFF_POOL 0
#define ZOFF_QSS  512
#define ZOFF_KP   1024
#define ZOFF_VP   33792
#define ZTOT      66560
__device__ float g_zero[ZTOT];
__device__ float g_gate[BB*CC];

// ---------------- asm helpers ----------------
__device__ __forceinline__ void ldm_x4(unsigned int (&r)[4], const void* p) {
    unsigned int a = (unsigned int)__cvta_generic_to_shared(p);
    asm volatile("ldmatrix.sync.aligned.m8n8.x4.shared.b16 {%0,%1,%2,%3}, [%4];"
        : "=r"(r[0]),"=r"(r[1]),"=r"(r[2]),"=r"(r[3]) : "r"(a));
}
__device__ __forceinline__ void ldm_x4_t(unsigned int (&r)[4], const void* p) {
    unsigned int a = (unsigned int)__cvta_generic_to_shared(p);
    asm volatile("ldmatrix.sync.aligned.m8n8.x4.trans.shared.b16 {%0,%1,%2,%3}, [%4];"
        : "=r"(r[0]),"=r"(r[1]),"=r"(r[2]),"=r"(r[3]) : "r"(a));
}
__device__ __forceinline__ void mma16816(float (&d)[4], const unsigned int (&a)[4],
                                         unsigned int b0, unsigned int b1) {
    asm volatile("mma.sync.aligned.m16n8k16.row.col.f32.bf16.bf16.f32 "
        "{%0,%1,%2,%3},{%4,%5,%6,%7},{%8,%9},{%0,%1,%2,%3};"
        : "+f"(d[0]),"+f"(d[1]),"+f"(d[2]),"+f"(d[3])
        : "r"(a[0]),"r"(a[1]),"r"(a[2]),"r"(a[3]),"r"(b0),"r"(b1));
}
__device__ __forceinline__ void cpa16(void* dst, const void* src) {
    unsigned int d = (unsigned int)__cvta_generic_to_shared(dst);
    asm volatile("cp.async.cg.shared.global [%0], [%1], 16;" :: "r"(d), "l"(src));
}
__device__ __forceinline__ void cp_commit() { asm volatile("cp.async.commit_group;"); }
template<int N> __device__ __forceinline__ void cp_wait() {
    asm volatile("cp.async.wait_group %0;" :: "n"(N));
}

// ---------------- kernels ----------------
__global__ void k_zero() {
    int i = blockIdx.x*256 + threadIdx.x;
    if (i < ZTOT) g_zero[i] = 0.f;
}

__global__ void k_wcvt(const float* __restrict__ wq, const float* __restrict__ w1,
                       const float* __restrict__ w2, const float* __restrict__ we)
{
    int i = blockIdx.x*256 + threadIdx.x;
    if (i < 196608) g_wqkv_bf[i] = __float2bfloat16(wq[i]);
    if (i < 32768)  { g_wo1_bf[i] = __float2bfloat16(w1[i]);
                      g_wo2_bf[i] = __float2bfloat16(w2[i]); }
    if (i < NNT*64) g_we_bf[i] = __float2bfloat16(we[i]);
}

// grouped 1x1x1 conv; conv2 fuses instance-norm + lrelu of its input
__global__ __launch_bounds__(256) void k_conv(
    const float* __restrict__ srcf, const __nv_bfloat16* __restrict__ srcb,
    const float* __restrict__ w, const float* __restrict__ bias,
    __nv_bfloat16* __restrict__ dst, const float2* __restrict__ instat)
{
    int bg = blockIdx.y; int b = bg >> 3; int g = bg & 7;
    int n  = blockIdx.x*256 + threadIdx.x;
    __shared__ float ws[1024];
    for (int i = threadIdx.x; i < 1024; i += 256) ws[i] = w[g*1024 + i];
    __syncthreads();
    int cbase = b*CC + g*32;
    float acc[32];
    #pragma unroll
    for (int o = 0; o < 32; ++o) acc[o] = bias[g*32+o];
    bool useb = (srcb != nullptr);
    #pragma unroll 8
    for (int i = 0; i < 32; ++i) {
        float v;
        if (useb) {
            v = __bfloat162float(srcb[(size_t)(cbase+i)*NNT + n]);
            float2 st = instat[cbase+i];
            v = (v - st.x)*st.y;
            v = v >= 0.f ? v : 0.01f*v;
        } else {
            v = srcf[(size_t)(cbase+i)*NNT + n];
        }
        #pragma unroll
        for (int o = 0; o < 32; ++o) acc[o] += v*ws[i*32+o];
    }
    #pragma unroll 4
    for (int o = 0; o < 32; ++o)
        dst[(size_t)(cbase+o)*NNT + n] = __float2bfloat16(acc[o]);
}

// instance-norm stats per (b,c) row — vectorized uint4
__global__ void k_stats(const __nv_bfloat16* __restrict__ src, float2* __restrict__ st)
{
    int row = blockIdx.x;
    const uint4* p4 = (const uint4*)(src + (size_t)row*NNT);
    float s = 0.f, q = 0.f;
    for (int i = threadIdx.x; i < NNT/8; i += 256) {
        uint4 v = p4[i];
        const __nv_bfloat162* h = (const __nv_bfloat162*)&v;
        #pragma unroll
        for (int j = 0; j < 4; ++j) {
            float2 f = __bfloat1622float2(h[j]);
            s += f.x + f.y; q += f.x*f.x + f.y*f.y;
        }
    }
    #pragma unroll
    for (int o = 16; o; o >>= 1) {
        s += __shfl_down_sync(0xffffffffu, s, o);
        q += __shfl_down_sync(0xffffffffu, q, o);
    }
    __shared__ float sh[16];
    int w = threadIdx.x >> 5, l = threadIdx.x & 31;
    if (l == 0) { sh[w] = s; sh[w+8] = q; }
    __syncthreads();
    if (threadIdx.x == 0) {
        float S = 0.f, Q = 0.f;
        for (int i = 0; i < 8; ++i) { S += sh[i]; Q += sh[i+8]; }
        float m = S / NNT;
        st[row] = make_float2(m, rsqrtf(Q/NNT - m*m + 1e-5f));
    }
}

// fused: xc = lrelu(inorm(conv2)+x); write xt_pre (fp32) and xct_pre (bf16)
__global__ void k_trans(const float* __restrict__ x, const float* __restrict__ pos)
{
    __shared__ float t1[32][33], t2[32][33];
    int n0 = blockIdx.x*32, c0 = blockIdx.y*32, b = blockIdx.z;
    int tx = threadIdx.x, ty = threadIdx.y;
    for (int yy = ty; yy < 32; yy += 8) {
        size_t s = (size_t)(b*CC + c0 + yy)*NNT + n0 + tx;
        float xv = x[s];
        float2 st = g_st2[b*CC + c0 + yy];
        float hv = (__bfloat162float(g_c2b[s]) - st.x)*st.y + xv;
        t1[yy][tx] = xv;
        t2[yy][tx] = hv >= 0.f ? hv : 0.01f*hv;
    }
    __syncthreads();
    for (int yy = ty; yy < 32; yy += 8) {
        float p = pos[(size_t)(n0+yy)*CC + c0 + tx];
        size_t d = ((size_t)b*NNT + n0 + yy)*CC + c0 + tx;
        g_xt   [d] = t1[tx][yy] + p;
        g_xcpre[d] = __float2bfloat16(t2[tx][yy] + p);
    }
}

// LayerNorm: warp per token; store stats only + bf16 normalized copies
__global__ __launch_bounds__(256) void k_ln(const float* __restrict__ lg,
                                            const float* __restrict__ lb)
{
    int wid = threadIdx.x >> 5, lane = threadIdx.x & 31;
    size_t row = (size_t)blockIdx.x*8 + wid;
    size_t base = row*CC;
    float v1[8], v2[8];
    float s1 = 0.f, q1 = 0.f, s2 = 0.f, q2 = 0.f;
    #pragma unroll
    for (int j = 0; j < 8; ++j) {
        v1[j] = g_xt[base + j*32 + lane];
        v2[j] = __bfloat162float(g_xcpre[base + j*32 + lane]);
        s1 += v1[j]; q1 += v1[j]*v1[j];
        s2 += v2[j]; q2 += v2[j]*v2[j];
    }
    #pragma unroll
    for (int o = 16; o; o >>= 1) {
        s1 += __shfl_xor_sync(0xffffffffu, s1, o);
        q1 += __shfl_xor_sync(0xffffffffu, q1, o);
        s2 += __shfl_xor_sync(0xffffffffu, s2, o);
        q2 += __shfl_xor_sync(0xffffffffu, q2, o);
    }
    float m1 = s1/CC, r1 = rsqrtf(q1/CC - m1*m1 + 1e-5f);
    float m2 = s2/CC, r2 = rsqrtf(q2/CC - m2*m2 + 1e-5f);
    if (lane == 0) g_lnst[row] = make_float2(m1, r1);
    #pragma unroll
    for (int j = 0; j < 8; ++j) {
        int c = j*32 + lane;
        size_t i = base + c;
        g_xt_bf[i]  = __float2bfloat16((v1[j] - m1)*r1*lg[c] + lb[c]);
        g_xct_bf[i] = __float2bfloat16((v2[j] - m2)*r2*lg[c] + lb[c]);
    }
}

__global__ void k_pool(const float* __restrict__ wp)
{
    int b = blockIdx.x, ch = blockIdx.y;
    int c = threadIdx.x;
    int n0 = ch*432;
    const __nv_bfloat16* base = g_xct_bf + ((size_t)b*NNT + n0)*CC + c;
    float acc = 0.f;
    #pragma unroll 4
    for (int n = 0; n < 432; ++n)
        acc += __bfloat162float(base[(size_t)n*CC]) * wp[n0+n];
    atomicAdd(&g_zero[ZOFF_POOL + b*CC + c], acc);
}

__global__ void k_gate(const float* __restrict__ bp, const float* __restrict__ w1,
                       const float* __restrict__ w2)
{
    __shared__ float ps[256], hs[64];
    int b = blockIdx.x, t = threadIdx.x;
    ps[t] = g_zero[ZOFF_POOL + b*CC + t] + bp[0];
    __syncthreads();
    if (t < 64) {
        float a = 0.f;
        for (int c = 0; c < 256; ++c) a += ps[c]*w1[c*64 + t];
        hs[t] = fmaxf(a, 0.f);
    }
    __syncthreads();
    float a = 0.f;
    for (int j = 0; j < 64; ++j) a += hs[j]*w2[j*256 + t];
    g_gate[b*CC + t] = 1.f/(1.f + expf(-a));
}

// bf16 HMMA GEMM with cp.async double buffering.
// blockIdx.z==1 -> (A2,Bw2,bias2,coff=128,gated). doqss: accumulate q sum-squares.
__global__ __launch_bounds__(256) void k_mma(
    const __nv_bfloat16* __restrict__ A, const __nv_bfloat16* __restrict__ A2,
    const __nv_bfloat16* __restrict__ Bw, const __nv_bfloat16* __restrict__ Bw2,
    const float* __restrict__ bias, const float* __restrict__ bias2,
    const float* __restrict__ gate,
    __nv_bfloat16* __restrict__ Cb, int Nld, int ldc, int doqss)
{
    __shared__ __align__(16) __nv_bfloat16 As[2][128][40];
    __shared__ __align__(16) __nv_bfloat16 Bs[2][32][136];
    int tid = threadIdx.x;
    int wid = tid >> 5, lane = tid & 31;
    int wm = wid >> 2;
    int wn = wid & 3;
    int m0 = blockIdx.y * 128;
    int n0 = blockIdx.x * 128;
    int coff = 0;
    const float* grow = nullptr;
    if (blockIdx.z == 1) {
        A = A2; Bw = Bw2; bias = bias2; coff = 128;
        grow = gate + (m0 / NNT)*CC;
    }

    float acc[4][4][4] = {};

    #pragma unroll
    for (int p = 0; p < 2; ++p) {
        int idx = p*256 + tid; int r = idx >> 2, sg = idx & 3;
        cpa16(&As[0][r][sg*8], A + (size_t)(m0 + r)*256 + sg*8);
    }
    #pragma unroll
    for (int p = 0; p < 2; ++p) {
        int idx = p*256 + tid; int r = idx >> 4, sg = idx & 15;
        cpa16(&Bs[0][r][sg*8], Bw + (size_t)r*Nld + n0 + sg*8);
    }
    cp_commit();

    for (int it = 0; it < 8; ++it) {
        int k0 = it*32, st = it & 1;
        if (it < 7) {
            int kn = k0 + 32, sn = st ^ 1;
            #pragma unroll
            for (int p = 0; p < 2; ++p) {
                int idx = p*256 + tid; int r = idx >> 2, sg = idx & 3;
                cpa16(&As[sn][r][sg*8], A + (size_t)(m0 + r)*256 + kn + sg*8);
            }
            #pragma unroll
            for (int p = 0; p < 2; ++p) {
                int idx = p*256 + tid; int r = idx >> 4, sg = idx & 15;
                cpa16(&Bs[sn][r][sg*8], Bw + (size_t)(kn + r)*Nld + n0 + sg*8);
            }
            cp_commit();
            cp_wait<1>();
        } else {
            cp_wait<0>();
        }
        __syncthreads();
        if (grow) {
            #pragma unroll
            for (int p = 0; p < 2; ++p) {
                int idx = p*256 + tid; int r = idx >> 2, sg = idx & 3;
                __nv_bfloat16* qp = &As[st][r][sg*8];
                #pragma unroll
                for (int j = 0; j < 8; ++j)
                    qp[j] = __float2bfloat16(__bfloat162float(qp[j])*grow[k0+sg*8+j]);
            }
            __syncthreads();
        }
        #pragma unroll
        for (int kk = 0; kk < 2; ++kk) {
            unsigned int af[4][4];
            #pragma unroll
            for (int mt = 0; mt < 4; ++mt)
                ldm_x4(af[mt], &As[st][wm*64 + mt*16 + (lane & 15)][kk*16 + (lane >> 4)*8]);
            unsigned int bfr[2][4];
            #pragma unroll
            for (int g2 = 0; g2 < 2; ++g2)
                ldm_x4_t(bfr[g2], &Bs[st][kk*16 + (lane & 15)][wn*32 + g2*16 + (lane >> 4)*8]);
            #pragma unroll
            for (int mt = 0; mt < 4; ++mt)
                #pragma unroll
                for (int nt = 0; nt < 4; ++nt)
                    mma16816(acc[mt][nt], af[mt],
                             bfr[nt>>1][(nt&1)*2], bfr[nt>>1][(nt&1)*2+1]);
        }
        __syncthreads();
    }
    // fused q sum-of-squares (qkv launch, first 256 output cols)
    if (doqss && n0 < 256) {
        int b = m0 / NNT;
        #pragma unroll
        for (int nt = 0; nt < 4; ++nt) {
            float s0 = 0.f, s1 = 0.f;
            #pragma unroll
            for (int mt = 0; mt < 4; ++mt) {
                #pragma unroll
                for (int h = 0; h < 2; ++h) {
                    float a0 = acc[mt][nt][h*2+0], a1 = acc[mt][nt][h*2+1];
                    s0 += a0*a0; s1 += a1*a1;
                }
            }
            #pragma unroll
            for (int o = 4; o <= 16; o <<= 1) {
                s0 += __shfl_xor_sync(0xffffffffu, s0, o);
                s1 += __shfl_xor_sync(0xffffffffu, s1, o);
            }
            if ((lane >> 2) == 0) {
                int col = n0 + wn*32 + nt*8 + (lane & 3)*2;
                atomicAdd(&g_zero[ZOFF_QSS + b*256 + col],   s0);
                atomicAdd(&g_zero[ZOFF_QSS + b*256 + col+1], s1);
            }
        }
    }
    #pragma unroll
    for (int mt = 0; mt < 4; ++mt) {
        int row0 = m0 + wm*64 + mt*16 + (lane >> 2);
        #pragma unroll
        for (int nt = 0; nt < 4; ++nt) {
            int col = wn*32 + nt*8 + (lane & 3)*2;
            #pragma unroll
            for (int h = 0; h < 2; ++h) {
                int r = row0 + h*8;
                float v0 = acc[mt][nt][h*2+0];
                float v1 = acc[mt][nt][h*2+1];
                if (bias) { v0 += bias[n0+col]; v1 += bias[n0+col+1]; }
                __nv_bfloat16* p = Cb + (size_t)r*ldc + coff + n0 + col;
                p[0] = __float2bfloat16(v0); p[1] = __float2bfloat16(v1);
            }
        }
    }
}

// K/V low-rank projection via tensor cores (unchanged from R5)
__global__ __launch_bounds__(256) void k_kvmma()
{
    int b = blockIdx.x >> 1, which = blockIdx.x & 1;
    int n0 = blockIdx.y * 512;
    int coff = 256*(which+1);
    __shared__ __align__(16) __nv_bfloat16 Ks[32][264];
    __shared__ __align__(16) __nv_bfloat16 Es[32][72];
    int tid = threadIdx.x, lane = tid & 31, wid = tid >> 5;
    int m0w = wid*32;
    float acc[2][8][4] = {};

    for (int c = 0; c < 16; ++c) {
        int nt0 = n0 + c*32;
        #pragma unroll
        for (int v = 0; v < 4; ++v) {
            int idx = v*256 + tid; int r = idx >> 5, sg = idx & 31;
            *(uint4*)&Ks[r][sg*8] =
                *(const uint4*)(g_qkv_bf + ((size_t)(b*NNT + nt0 + r))*768 + coff + sg*8);
        }
        {
            int r = tid >> 3, sg = tid & 7;
            *(uint4*)&Es[r][sg*8] = *(const uint4*)(g_we_bf + (size_t)(nt0 + r)*64 + sg*8);
        }
        __syncthreads();
        #pragma unroll
        for (int kk = 0; kk < 32; kk += 16) {
            unsigned int af[2][4];
            #pragma unroll
            for (int mt = 0; mt < 2; ++mt)
                ldm_x4_t(af[mt], &Ks[kk + (lane & 7) + ((lane >> 4) << 3)]
                                    [m0w + mt*16 + ((lane >> 3) & 1)*8]);
            unsigned int bfr[4][4];
            #pragma unroll
            for (int ng = 0; ng < 4; ++ng)
                ldm_x4_t(bfr[ng], &Es[kk + (lane & 15)][ng*16 + (lane >> 4)*8]);
            #pragma unroll
            for (int mt = 0; mt < 2; ++mt)
                #pragma unroll
                for (int nt = 0; nt < 8; ++nt)
                    mma16816(acc[mt][nt], af[mt],
                             bfr[nt>>1][(nt&1)*2], bfr[nt>>1][(nt&1)*2+1]);
        }
        __syncthreads();
    }
    float* out = &g_zero[ZOFF_KP + which*32768 + b*16384];
    #pragma unroll
    for (int mt = 0; mt < 2; ++mt) {
        int m = m0w + mt*16 + (lane >> 2);
        #pragma unroll
        for (int nt = 0; nt < 8; ++nt) {
            int p = nt*8 + (lane & 3)*2;
            atomicAdd(&out[m*64 + p],       acc[mt][nt][0]);
            atomicAdd(&out[m*64 + p + 1],   acc[mt][nt][1]);
            atomicAdd(&out[(m+8)*64 + p],   acc[mt][nt][2]);
            atomicAdd(&out[(m+8)*64 + p+1], acc[mt][nt][3]);
        }
    }
}

// fused attention tile: q-normalize, HMMA qn@kproj, softmax, HMMA v@probs^T,
// direct scrambled store. qrn computed in-block from fused qss.
__global__ __launch_bounds__(256) void k_attn(const float* __restrict__ be,
                                              const float* __restrict__ temp)
{
    int bh = blockIdx.y; int b = bh >> 2, h = bh & 3;
    int n0 = blockIdx.x*64;
    __shared__ __align__(16) __nv_bfloat16 sA[64][72];  // qn -> v
    __shared__ __align__(16) __nv_bfloat16 sB[64][72];  // kproj -> probs^T
    __shared__ float ss[64][68];
    __shared__ float qr[64];
    int tid = threadIdx.x;
    int wid = tid >> 5, lane = tid & 31;
    int wm = wid & 1, wn = wid >> 1;
    const float* kbase = &g_zero[ZOFF_KP + bh*4096];
    const float* vbase = &g_zero[ZOFF_VP + bh*4096];

    if (tid < 64)
        qr[tid] = 1.f / fmaxf(sqrtf(g_zero[ZOFF_QSS + b*256 + h*64 + tid]), 1e-12f);
    // kproj -> sB[d][p] (+be), bf16
    #pragma unroll
    for (int v = 0; v < 4; ++v) {
        int i4 = v*256 + tid; int d = i4 >> 4, pp = (i4 & 15)*4;
        float4 kv = *(const float4*)(kbase + d*64 + pp);
        sB[d][pp]   = __float2bfloat16(kv.x + be[pp]);
        sB[d][pp+1] = __float2bfloat16(kv.y + be[pp+1]);
        sB[d][pp+2] = __float2bfloat16(kv.z + be[pp+2]);
        sB[d][pp+3] = __float2bfloat16(kv.w + be[pp+3]);
    }
    __syncthreads();
    // qn -> sA[n][d]
    #pragma unroll
    for (int l = 0; l < 2; ++l) {
        int i8 = l*256 + tid; int r = i8 >> 3, sg = (i8 & 7)*8;
        uint4 v = *(const uint4*)(g_qkv_bf + ((size_t)(b*NNT + n0 + r))*768 + h*64 + sg);
        const __nv_bfloat162* hh = (const __nv_bfloat162*)&v;
        __nv_bfloat16 outv[8];
        #pragma unroll
        for (int j = 0; j < 4; ++j) {
            float2 f = __bfloat1622float2(hh[j]);
            outv[j*2]   = __float2bfloat16(f.x * qr[sg + j*2]);
            outv[j*2+1] = __float2bfloat16(f.y * qr[sg + j*2+1]);
        }
        *(uint4*)&sA[r][sg] = *(uint4*)outv;
    }
    __syncthreads();
    // GEMM1: scores[n][p] = qn @ kproj
    float acc1[2][2][4] = {};
    #pragma unroll
    for (int kk = 0; kk < 64; kk += 16) {
        unsigned int af[2][4];
        #pragma unroll
        for (int mt = 0; mt < 2; ++mt)
            ldm_x4(af[mt], &sA[wm*32 + mt*16 + (lane & 15)][kk + (lane >> 4)*8]);
        unsigned int bfr[4];
        ldm_x4_t(bfr, &sB[kk + (lane & 15)][wn*16 + (lane >> 4)*8]);
        #pragma unroll
        for (int mt = 0; mt < 2; ++mt)
            #pragma unroll
            for (int nt = 0; nt < 2; ++nt)
                mma16816(acc1[mt][nt], af[mt], bfr[nt*2], bfr[nt*2+1]);
    }
    float ts = temp[h];
    #pragma unroll
    for (int mt = 0; mt < 2; ++mt) {
        int r = wm*32 + mt*16 + (lane >> 2);
        #pragma unroll
        for (int nt = 0; nt < 2; ++nt) {
            int c = wn*16 + nt*8 + (lane & 3)*2;
            ss[r][c]     = acc1[mt][nt][0]*ts;
            ss[r][c+1]   = acc1[mt][nt][1]*ts;
            ss[r+8][c]   = acc1[mt][nt][2]*ts;
            ss[r+8][c+1] = acc1[mt][nt][3]*ts;
        }
    }
    __syncthreads();
    // v -> sA[d][p] (+be); softmax -> probs^T in sB[p][n]
    #pragma unroll
    for (int v = 0; v < 4; ++v) {
        int i4 = v*256 + tid; int d = i4 >> 4, pp = (i4 & 15)*4;
        float4 vv = *(const float4*)(vbase + d*64 + pp);
        sA[d][pp]   = __float2bfloat16(vv.x + be[pp]);
        sA[d][pp+1] = __float2bfloat16(vv.y + be[pp+1]);
        sA[d][pp+2] = __float2bfloat16(vv.z + be[pp+2]);
        sA[d][pp+3] = __float2bfloat16(vv.w + be[pp+3]);
    }
    {
        int row = tid >> 2, g4 = (tid & 3)*16;
        float e[16];
        float mx = -1e30f;
        #pragma unroll
        for (int p = 0; p < 16; ++p) { e[p] = ss[row][g4+p]; mx = fmaxf(mx, e[p]); }
        mx = fmaxf(mx, __shfl_xor_sync(0xffffffffu, mx, 1));
        mx = fmaxf(mx, __shfl_xor_sync(0xffffffffu, mx, 2));
        float sum = 0.f;
        #pragma unroll
        for (int p = 0; p < 16; ++p) { e[p] = __expf(e[p] - mx); sum += e[p]; }
        sum += __shfl_xor_sync(0xffffffffu, sum, 1);
        sum += __shfl_xor_sync(0xffffffffu, sum, 2);
        float inv = 1.f/sum;
        #pragma unroll
        for (int p = 0; p < 16; ++p)
            sB[g4+p][row] = __float2bfloat16(e[p]*inv);
    }
    __syncthreads();
    // GEMM2: out[d][n] = v[d][p] @ probs^T[p][n]
    float acc2[2][2][4] = {};
    #pragma unroll
    for (int kk = 0; kk < 64; kk += 16) {
        unsigned int af[2][4];
        #pragma unroll
        for (int mt = 0; mt < 2; ++mt)
            ldm_x4(af[mt], &sA[wm*32 + mt*16 + (lane & 15)][kk + (lane >> 4)*8]);
        unsigned int bfr[4];
        ldm_x4_t(bfr, &sB[kk + (lane & 15)][wn*16 + (lane >> 4)*8]);
        #pragma unroll
        for (int mt = 0; mt < 2; ++mt)
            #pragma unroll
            for (int nt = 0; nt < 2; ++nt)
                mma16816(acc2[mt][nt], af[mt], bfr[nt*2], bfr[nt*2+1]);
    }
    // scrambled store: g_sa[b][(d*4+h)*NNT + n]
    __nv_bfloat16* sabase = g_sa_bf + (size_t)b*NNT*CC;
    #pragma unroll
    for (int mt = 0; mt < 2; ++mt) {
        int d0 = wm*32 + mt*16 + (lane >> 2);
        #pragma unroll
        for (int nt = 0; nt < 2; ++nt) {
            int nc = n0 + wn*16 + nt*8 + (lane & 3)*2;
            *(__nv_bfloat162*)&sabase[(size_t)(d0*4 + h)*NNT + nc] =
                __floats2bfloat162_rn(acc2[mt][nt][0], acc2[mt][nt][1]);
            *(__nv_bfloat162*)&sabase[(size_t)((d0+8)*4 + h)*NNT + nc] =
                __floats2bfloat162_rn(acc2[mt][nt][2], acc2[mt][nt][3]);
        }
    }
}

// out[b,c,n] = x_n + gamma*x_att (x_n recomputed from xt_pre + stats)
__global__ void k_final(const float* __restrict__ lg, const float* __restrict__ lb,
                        const float* __restrict__ gamma, float* __restrict__ out)
{
    __shared__ float t1[32][33];
    int n0 = blockIdx.x*32, c0 = blockIdx.y*32, b = blockIdx.z;
    int tx = threadIdx.x, ty = threadIdx.y;
    float lgc = lg[c0+tx], lbc = lb[c0+tx], gmc = gamma[c0+tx];
    for (int yy = ty; yy < 32; yy += 8) {
        size_t s = ((size_t)b*NNT + n0 + yy)*CC + c0 + tx;
        float2 st = g_lnst[(size_t)b*NNT + n0 + yy];
        float xn = (g_xt[s] - st.x)*st.y*lgc + lbc;
        t1[yy][tx] = xn + gmc*__bfloat162float(g_xcpre[s]);
    }
    __syncthreads();
    for (int yy = ty; yy < 32; yy += 8)
        out[(size_t)(b*CC + c0 + yy)*NNT + n0 + tx] = t1[tx][yy];
}

// ---------------- launch ----------------
extern "C" void kernel_launch(void* const* d_in, const int* in_sizes, int n_in,
                              void* d_out, int out_size)
{
    const float* x      = (const float*)d_in[0];
    const float* pos    = (const float*)d_in[1];
    const float* ln_g   = (const float*)d_in[2];
    const float* ln_b   = (const float*)d_in[3];
    const float* gamma  = (const float*)d_in[4];
    const float* temp2  = (const float*)d_in[5];
    const float* w_qkv  = (const float*)d_in[6];
    const float* w_e    = (const float*)d_in[7];
    const float* b_e    = (const float*)d_in[8];
    const float* w_pool = (const float*)d_in[9];
    const float* b_pool = (const float*)d_in[10];
    const float* w_fc1  = (const float*)d_in[11];
    const float* w_fc2  = (const float*)d_in[12];
    const float* b_out1 = (const float*)d_in[14];
    const float* b_out2 = (const float*)d_in[16];
    const float* w_c1   = (const float*)d_in[17];
    const float* b_c1   = (const float*)d_in[18];
    const float* w_c2   = (const float*)d_in[19];
    const float* b_c2   = (const float*)d_in[20];

    __nv_bfloat16 *p_h1b, *p_c2b, *p_xtbf, *p_xctbf, *p_qkvbf, *p_sabf, *p_xcpre;
    __nv_bfloat16 *p_wq, *p_w1, *p_w2;
    float *p_gate;
    float2 *p_st1, *p_st2;
    cudaGetSymbolAddress((void**)&p_h1b,   g_h1b);
    cudaGetSymbolAddress((void**)&p_c2b,   g_c2b);
    cudaGetSymbolAddress((void**)&p_xtbf,  g_xt_bf);
    cudaGetSymbolAddress((void**)&p_xctbf, g_xct_bf);
    cudaGetSymbolAddress((void**)&p_qkvbf, g_qkv_bf);
    cudaGetSymbolAddress((void**)&p_sabf,  g_sa_bf);
    cudaGetSymbolAddress((void**)&p_xcpre, g_xcpre);
    cudaGetSymbolAddress((void**)&p_wq,    g_wqkv_bf);
    cudaGetSymbolAddress((void**)&p_w1,    g_wo1_bf);
    cudaGetSymbolAddress((void**)&p_w2,    g_wo2_bf);
    cudaGetSymbolAddress((void**)&p_gate,  g_gate);
    cudaGetSymbolAddress((void**)&p_st1,   g_st1);
    cudaGetSymbolAddress((void**)&p_st2,   g_st2);

    k_zero <<<(ZTOT+255)/256, 256>>>();
    k_wcvt <<<(NNT*64+255)/256, 256>>>(w_qkv, (const float*)d_in[13],
                                       (const float*)d_in[15], w_e);
    // MHCResBlock
    k_conv <<<dim3(54,16), 256>>>(x, (const __nv_bfloat16*)0, w_c1, b_c1, p_h1b, (const float2*)0);
    k_stats<<<512, 256>>>(p_h1b, p_st1);
    k_conv <<<dim3(54,16), 256>>>((const float*)0, p_h1b, w_c2, b_c2, p_c2b, p_st1);
    k_stats<<<512, 256>>>(p_c2b, p_st2);
    // tokens + LN
    k_trans<<<dim3(432,8,BB), dim3(32,8)>>>(x, pos);
    k_ln   <<<MTOT/8, 256>>>(ln_g, ln_b);
    // channel attention gate
    k_pool <<<dim3(BB,32), 256>>>(w_pool);
    k_gate <<<BB, 256>>>(b_pool, w_fc1, w_fc2);
    // qkv (pipelined bf16 HMMA + fused q sum-squares)
    k_mma  <<<dim3(6,216,1), 256>>>(p_xtbf, (const __nv_bfloat16*)0, p_wq,
                                    (const __nv_bfloat16*)0, (const float*)0,
                                    (const float*)0, (const float*)0,
                                    p_qkvbf, 768, 768, 1);
    // low-rank K/V projection (tensor cores, split-N atomics)
    k_kvmma<<<dim3(4,27), 256>>>();
    // spatial attention (HMMA both GEMMs + scramble)
    k_attn <<<dim3(216, BB*NHH), 256>>>(b_e, temp2);
    // both output projections in one launch (z=0: SA, z=1: CA gated)
    k_mma  <<<dim3(1,216,2), 256>>>(p_sabf, p_xctbf, p_w1, p_w2,
                                    b_out1, b_out2, p_gate,
                                    p_xcpre, 128, 256, 0);
    // residual + gamma, transpose to [B,C,N]
    k_final<<<dim3(432,8,BB), dim3(32,8)>>>(ln_g, ln_b, gamma, (float*)d_out);
}

// round 7
// speedup vs baseline: 2.8334x; 1.1046x over previous
#include <cuda_runtime.h>
#include <cuda_bf16.h>
#include <cstdint>
#include <math.h>

#define BB 2
#define CC 256
#define NNT 13824
#define NHH 4
#define MTOT (BB*NNT)

// ---------------- scratch ----------------
__device__ __nv_bfloat16 g_h1b[BB*CC*NNT];            // conv1 out
__device__ __nv_bfloat16 g_c2b[BB*CC*NNT];            // conv2 raw out
__device__ __nv_bfloat16 g_att[BB*NNT*CC];            // concat(SA,CA) out [n,c]
__device__ __nv_bfloat16 g_xt_bf [BB*NNT*CC];         // x_n bf16 (qkv A)
__device__ __nv_bfloat16 g_xct_bf[BB*NNT*CC];         // xc_n bf16
__device__ __nv_bfloat16 g_qkv_bf[(size_t)BB*NNT*768];
__device__ __nv_bfloat16 g_sa_bf [BB*NNT*CC];         // scrambled x_SA
__device__ __nv_bfloat16 g_wqkv_bf[256*768];
__device__ __nv_bfloat16 g_wo1_bf [256*128];
__device__ __nv_bfloat16 g_wo2_bf [256*128];
__device__ __nv_bfloat16 g_we_bf  [NNT*64];
#define ZOFF_POOL 0
#define ZOFF_QSS  512
#define ZOFF_CS1S 1024
#define ZOFF_CS1Q 1536
#define ZOFF_CS2S 2048
#define ZOFF_CS2Q 2560
#define ZOFF_KP   3072
#define ZOFF_VP   35840
#define ZTOT      68608
__device__ float g_zero[ZTOT];
__device__ float g_gate[BB*CC];

// ---------------- asm helpers ----------------
__device__ __forceinline__ void ldm_x4(unsigned int (&r)[4], const void* p) {
    unsigned int a = (unsigned int)__cvta_generic_to_shared(p);
    asm volatile("ldmatrix.sync.aligned.m8n8.x4.shared.b16 {%0,%1,%2,%3}, [%4];"
        : "=r"(r[0]),"=r"(r[1]),"=r"(r[2]),"=r"(r[3]) : "r"(a));
}
__device__ __forceinline__ void ldm_x4_t(unsigned int (&r)[4], const void* p) {
    unsigned int a = (unsigned int)__cvta_generic_to_shared(p);
    asm volatile("ldmatrix.sync.aligned.m8n8.x4.trans.shared.b16 {%0,%1,%2,%3}, [%4];"
        : "=r"(r[0]),"=r"(r[1]),"=r"(r[2]),"=r"(r[3]) : "r"(a));
}
__device__ __forceinline__ void mma16816(float (&d)[4], const unsigned int (&a)[4],
                                         unsigned int b0, unsigned int b1) {
    asm volatile("mma.sync.aligned.m16n8k16.row.col.f32.bf16.bf16.f32 "
        "{%0,%1,%2,%3},{%4,%5,%6,%7},{%8,%9},{%0,%1,%2,%3};"
        : "+f"(d[0]),"+f"(d[1]),"+f"(d[2]),"+f"(d[3])
        : "r"(a[0]),"r"(a[1]),"r"(a[2]),"r"(a[3]),"r"(b0),"r"(b1));
}
__device__ __forceinline__ void cpa16(void* dst, const void* src) {
    unsigned int d = (unsigned int)__cvta_generic_to_shared(dst);
    asm volatile("cp.async.cg.shared.global [%0], [%1], 16;" :: "r"(d), "l"(src));
}
__device__ __forceinline__ void cp_commit() { asm volatile("cp.async.commit_group;"); }
template<int N> __device__ __forceinline__ void cp_wait() {
    asm volatile("cp.async.wait_group %0;" :: "n"(N));
}

// ---------------- kernels ----------------
// zero scratch + convert weights to bf16
__global__ void k_init(const float* __restrict__ wq, const float* __restrict__ w1,
                       const float* __restrict__ w2, const float* __restrict__ we)
{
    int i = blockIdx.x*256 + threadIdx.x;
    if (i < ZTOT) g_zero[i] = 0.f;
    if (i < 196608) g_wqkv_bf[i] = __float2bfloat16(wq[i]);
    if (i < 32768)  { g_wo1_bf[i] = __float2bfloat16(w1[i]);
                      g_wo2_bf[i] = __float2bfloat16(w2[i]); }
    if (i < NNT*64) g_we_bf[i] = __float2bfloat16(we[i]);
}

// grouped 1x1x1 conv; conv2 normalizes+lrelu's its input from (sum,ssq);
// both emit per-channel (sum, sumsq) of their fp32 outputs via atomics.
__global__ __launch_bounds__(256) void k_conv(
    const float* __restrict__ srcf, const __nv_bfloat16* __restrict__ srcb,
    const float* __restrict__ w, const float* __restrict__ bias,
    __nv_bfloat16* __restrict__ dst,
    const float* __restrict__ sin_s, const float* __restrict__ sin_q,
    float* __restrict__ sout_s, float* __restrict__ sout_q)
{
    int bg = blockIdx.y; int b = bg >> 3; int g = bg & 7;
    int n  = blockIdx.x*256 + threadIdx.x;
    int tid = threadIdx.x, lane = tid & 31, wid = tid >> 5;
    __shared__ float ws[1024];
    __shared__ float sm[32], sr[32];
    __shared__ float sacc[32][257];
    int cbase = b*CC + g*32;
    for (int i = tid; i < 1024; i += 256) ws[i] = w[g*1024 + i];
    if (srcb && tid < 32) {
        float s = sin_s[cbase+tid], q = sin_q[cbase+tid];
        float m = s*(1.f/NNT);
        sm[tid] = m;
        sr[tid] = rsqrtf(q*(1.f/NNT) - m*m + 1e-5f);
    }
    __syncthreads();
    float acc[32];
    #pragma unroll
    for (int o = 0; o < 32; ++o) acc[o] = bias[g*32+o];
    bool useb = (srcb != nullptr);
    #pragma unroll 8
    for (int i = 0; i < 32; ++i) {
        float v;
        if (useb) {
            v = __bfloat162float(srcb[(size_t)(cbase+i)*NNT + n]);
            v = (v - sm[i])*sr[i];
            v = v >= 0.f ? v : 0.01f*v;
        } else {
            v = srcf[(size_t)(cbase+i)*NNT + n];
        }
        #pragma unroll
        for (int o = 0; o < 32; ++o) acc[o] += v*ws[i*32+o];
    }
    #pragma unroll 4
    for (int o = 0; o < 32; ++o)
        dst[(size_t)(cbase+o)*NNT + n] = __float2bfloat16(acc[o]);
    // fused stats epilogue
    #pragma unroll
    for (int o = 0; o < 32; ++o) sacc[o][tid] = acc[o];
    __syncthreads();
    #pragma unroll
    for (int k = 0; k < 4; ++k) {
        int ch = wid*4 + k;
        float s = 0.f, q = 0.f;
        #pragma unroll
        for (int j = 0; j < 8; ++j) {
            float v = sacc[ch][lane + 32*j];
            s += v; q += v*v;
        }
        #pragma unroll
        for (int o = 16; o; o >>= 1) {
            s += __shfl_xor_sync(0xffffffffu, s, o);
            q += __shfl_xor_sync(0xffffffffu, q, o);
        }
        if (lane == 0) {
            atomicAdd(&sout_s[cbase+ch], s);
            atomicAdd(&sout_q[cbase+ch], q);
        }
    }
}

// mega-fused: xc = lrelu(inorm(conv2)+x); +pos; LN both streams (warp/token);
// writes x_n fp32 straight into d_out [c,n], bf16 x_n/xc_n, pool partials.
__global__ __launch_bounds__(256) void k_megaln(
    const float* __restrict__ x, const float* __restrict__ pos,
    const float* __restrict__ lg, const float* __restrict__ lb,
    const float* __restrict__ wp, float* __restrict__ dout)
{
    extern __shared__ float dsm[];
    float* xs    = dsm;             // 256*33
    float* cs    = xs + 8448;       // 256*33
    float* stm   = cs + 8448;       // 256
    float* str   = stm + 256;
    float* lgs   = str + 256;
    float* lbs   = lgs + 256;
    float* pools = lbs + 256;       // 256
    int tid = threadIdx.x, tx = tid & 31, ty = tid >> 5;
    int lane = tid & 31, w = tid >> 5;
    int n0 = blockIdx.x*32, b = blockIdx.y;
    {
        float s = g_zero[ZOFF_CS2S + b*256 + tid];
        float q = g_zero[ZOFF_CS2Q + b*256 + tid];
        float m = s*(1.f/NNT);
        stm[tid] = m;
        str[tid] = rsqrtf(q*(1.f/NNT) - m*m + 1e-5f);
        lgs[tid] = lg[tid]; lbs[tid] = lb[tid];
        pools[tid] = 0.f;
    }
    __syncthreads();
    for (int cc = ty; cc < 256; cc += 8) {
        size_t s = (size_t)(b*CC + cc)*NNT + n0 + tx;
        float xv = x[s];
        float hv = (__bfloat162float(g_c2b[s]) - stm[cc])*str[cc] + xv;
        xs[cc*33 + tx] = xv;
        cs[cc*33 + tx] = hv >= 0.f ? hv : 0.01f*hv;
    }
    __syncthreads();
    for (int t8 = 0; t8 < 4; ++t8) {
        int tok = w + t8*8;
        const float* prow = pos + (size_t)(n0 + tok)*CC;
        float v1[8], v2[8];
        float s1 = 0.f, q1 = 0.f, s2 = 0.f, q2 = 0.f;
        #pragma unroll
        for (int j = 0; j < 8; ++j) {
            int c = lane + 32*j;
            float p = prow[c];
            float a  = xs[c*33 + tok] + p;
            float d2 = cs[c*33 + tok] + p;
            v1[j] = a; v2[j] = d2;
            s1 += a; q1 += a*a; s2 += d2; q2 += d2*d2;
        }
        #pragma unroll
        for (int o = 16; o; o >>= 1) {
            s1 += __shfl_xor_sync(0xffffffffu, s1, o);
            q1 += __shfl_xor_sync(0xffffffffu, q1, o);
            s2 += __shfl_xor_sync(0xffffffffu, s2, o);
            q2 += __shfl_xor_sync(0xffffffffu, q2, o);
        }
        float m1 = s1*(1.f/CC), r1 = rsqrtf(q1*(1.f/CC) - m1*m1 + 1e-5f);
        float m2 = s2*(1.f/CC), r2 = rsqrtf(q2*(1.f/CC) - m2*m2 + 1e-5f);
        float wpt = wp[n0 + tok];
        size_t gbase = ((size_t)b*NNT + n0 + tok)*CC;
        #pragma unroll
        for (int j = 0; j < 8; ++j) {
            int c = lane + 32*j;
            float o1 = (v1[j] - m1)*r1*lgs[c] + lbs[c];
            float o2 = (v2[j] - m2)*r2*lgs[c] + lbs[c];
            g_xt_bf [gbase + c] = __float2bfloat16(o1);
            g_xct_bf[gbase + c] = __float2bfloat16(o2);
            xs[c*33 + tok] = o1;                 // x_n fp32 for output
            atomicAdd(&pools[c], o2*wpt);
        }
    }
    __syncthreads();
    for (int cc = ty; cc < 256; cc += 8)
        dout[(size_t)(b*CC + cc)*NNT + n0 + tx] = xs[cc*33 + tx];
    atomicAdd(&g_zero[ZOFF_POOL + b*256 + tid], pools[tid]);
}

__global__ void k_gate(const float* __restrict__ bp, const float* __restrict__ w1,
                       const float* __restrict__ w2)
{
    __shared__ float ps[256], hs[64];
    int b = blockIdx.x, t = threadIdx.x;
    ps[t] = g_zero[ZOFF_POOL + b*CC + t] + bp[0];
    __syncthreads();
    if (t < 64) {
        float a = 0.f;
        for (int c = 0; c < 256; ++c) a += ps[c]*w1[c*64 + t];
        hs[t] = fmaxf(a, 0.f);
    }
    __syncthreads();
    float a = 0.f;
    for (int j = 0; j < 64; ++j) a += hs[j]*w2[j*256 + t];
    g_gate[b*CC + t] = 1.f/(1.f + expf(-a));
}

// bf16 HMMA GEMM with cp.async double buffering.
__global__ __launch_bounds__(256) void k_mma(
    const __nv_bfloat16* __restrict__ A, const __nv_bfloat16* __restrict__ A2,
    const __nv_bfloat16* __restrict__ Bw, const __nv_bfloat16* __restrict__ Bw2,
    const float* __restrict__ bias, const float* __restrict__ bias2,
    const float* __restrict__ gate,
    __nv_bfloat16* __restrict__ Cb, int Nld, int ldc, int doqss)
{
    __shared__ __align__(16) __nv_bfloat16 As[2][128][40];
    __shared__ __align__(16) __nv_bfloat16 Bs[2][32][136];
    int tid = threadIdx.x;
    int wid = tid >> 5, lane = tid & 31;
    int wm = wid >> 2;
    int wn = wid & 3;
    int m0 = blockIdx.y * 128;
    int n0 = blockIdx.x * 128;
    int coff = 0;
    const float* grow = nullptr;
    if (blockIdx.z == 1) {
        A = A2; Bw = Bw2; bias = bias2; coff = 128;
        grow = gate + (m0 / NNT)*CC;
    }

    float acc[4][4][4] = {};

    #pragma unroll
    for (int p = 0; p < 2; ++p) {
        int idx = p*256 + tid; int r = idx >> 2, sg = idx & 3;
        cpa16(&As[0][r][sg*8], A + (size_t)(m0 + r)*256 + sg*8);
    }
    #pragma unroll
    for (int p = 0; p < 2; ++p) {
        int idx = p*256 + tid; int r = idx >> 4, sg = idx & 15;
        cpa16(&Bs[0][r][sg*8], Bw + (size_t)r*Nld + n0 + sg*8);
    }
    cp_commit();

    for (int it = 0; it < 8; ++it) {
        int k0 = it*32, st = it & 1;
        if (it < 7) {
            int kn = k0 + 32, sn = st ^ 1;
            #pragma unroll
            for (int p = 0; p < 2; ++p) {
                int idx = p*256 + tid; int r = idx >> 2, sg = idx & 3;
                cpa16(&As[sn][r][sg*8], A + (size_t)(m0 + r)*256 + kn + sg*8);
            }
            #pragma unroll
            for (int p = 0; p < 2; ++p) {
                int idx = p*256 + tid; int r = idx >> 4, sg = idx & 15;
                cpa16(&Bs[sn][r][sg*8], Bw + (size_t)(kn + r)*Nld + n0 + sg*8);
            }
            cp_commit();
            cp_wait<1>();
        } else {
            cp_wait<0>();
        }
        __syncthreads();
        if (grow) {
            #pragma unroll
            for (int p = 0; p < 2; ++p) {
                int idx = p*256 + tid; int r = idx >> 2, sg = idx & 3;
                __nv_bfloat16* qp = &As[st][r][sg*8];
                #pragma unroll
                for (int j = 0; j < 8; ++j)
                    qp[j] = __float2bfloat16(__bfloat162float(qp[j])*grow[k0+sg*8+j]);
            }
            __syncthreads();
        }
        #pragma unroll
        for (int kk = 0; kk < 2; ++kk) {
            unsigned int af[4][4];
            #pragma unroll
            for (int mt = 0; mt < 4; ++mt)
                ldm_x4(af[mt], &As[st][wm*64 + mt*16 + (lane & 15)][kk*16 + (lane >> 4)*8]);
            unsigned int bfr[2][4];
            #pragma unroll
            for (int g2 = 0; g2 < 2; ++g2)
                ldm_x4_t(bfr[g2], &Bs[st][kk*16 + (lane & 15)][wn*32 + g2*16 + (lane >> 4)*8]);
            #pragma unroll
            for (int mt = 0; mt < 4; ++mt)
                #pragma unroll
                for (int nt = 0; nt < 4; ++nt)
                    mma16816(acc[mt][nt], af[mt],
                             bfr[nt>>1][(nt&1)*2], bfr[nt>>1][(nt&1)*2+1]);
        }
        __syncthreads();
    }
    if (doqss && n0 < 256) {
        int b = m0 / NNT;
        #pragma unroll
        for (int nt = 0; nt < 4; ++nt) {
            float s0 = 0.f, s1 = 0.f;
            #pragma unroll
            for (int mt = 0; mt < 4; ++mt) {
                #pragma unroll
                for (int h = 0; h < 2; ++h) {
                    float a0 = acc[mt][nt][h*2+0], a1 = acc[mt][nt][h*2+1];
                    s0 += a0*a0; s1 += a1*a1;
                }
            }
            #pragma unroll
            for (int o = 4; o <= 16; o <<= 1) {
                s0 += __shfl_xor_sync(0xffffffffu, s0, o);
                s1 += __shfl_xor_sync(0xffffffffu, s1, o);
            }
            if ((lane >> 2) == 0) {
                int col = n0 + wn*32 + nt*8 + (lane & 3)*2;
                atomicAdd(&g_zero[ZOFF_QSS + b*256 + col],   s0);
                atomicAdd(&g_zero[ZOFF_QSS + b*256 + col+1], s1);
            }
        }
    }
    #pragma unroll
    for (int mt = 0; mt < 4; ++mt) {
        int row0 = m0 + wm*64 + mt*16 + (lane >> 2);
        #pragma unroll
        for (int nt = 0; nt < 4; ++nt) {
            int col = wn*32 + nt*8 + (lane & 3)*2;
            #pragma unroll
            for (int h = 0; h < 2; ++h) {
                int r = row0 + h*8;
                float v0 = acc[mt][nt][h*2+0];
                float v1 = acc[mt][nt][h*2+1];
                if (bias) { v0 += bias[n0+col]; v1 += bias[n0+col+1]; }
                __nv_bfloat16* p = Cb + (size_t)r*ldc + coff + n0 + col;
                p[0] = __float2bfloat16(v0); p[1] = __float2bfloat16(v1);
            }
        }
    }
}

// K/V low-rank projection via tensor cores
__global__ __launch_bounds__(256) void k_kvmma()
{
    int b = blockIdx.x >> 1, which = blockIdx.x & 1;
    int n0 = blockIdx.y * 512;
    int coff = 256*(which+1);
    __shared__ __align__(16) __nv_bfloat16 Ks[32][264];
    __shared__ __align__(16) __nv_bfloat16 Es[32][72];
    int tid = threadIdx.x, lane = tid & 31, wid = tid >> 5;
    int m0w = wid*32;
    float acc[2][8][4] = {};

    for (int c = 0; c < 16; ++c) {
        int nt0 = n0 + c*32;
        #pragma unroll
        for (int v = 0; v < 4; ++v) {
            int idx = v*256 + tid; int r = idx >> 5, sg = idx & 31;
            *(uint4*)&Ks[r][sg*8] =
                *(const uint4*)(g_qkv_bf + ((size_t)(b*NNT + nt0 + r))*768 + coff + sg*8);
        }
        {
            int r = tid >> 3, sg = tid & 7;
            *(uint4*)&Es[r][sg*8] = *(const uint4*)(g_we_bf + (size_t)(nt0 + r)*64 + sg*8);
        }
        __syncthreads();
        #pragma unroll
        for (int kk = 0; kk < 32; kk += 16) {
            unsigned int af[2][4];
            #pragma unroll
            for (int mt = 0; mt < 2; ++mt)
                ldm_x4_t(af[mt], &Ks[kk + (lane & 7) + ((lane >> 4) << 3)]
                                    [m0w + mt*16 + ((lane >> 3) & 1)*8]);
            unsigned int bfr[4][4];
            #pragma unroll
            for (int ng = 0; ng < 4; ++ng)
                ldm_x4_t(bfr[ng], &Es[kk + (lane & 15)][ng*16 + (lane >> 4)*8]);
            #pragma unroll
            for (int mt = 0; mt < 2; ++mt)
                #pragma unroll
                for (int nt = 0; nt < 8; ++nt)
                    mma16816(acc[mt][nt], af[mt],
                             bfr[nt>>1][(nt&1)*2], bfr[nt>>1][(nt&1)*2+1]);
        }
        __syncthreads();
    }
    float* out = &g_zero[ZOFF_KP + which*32768 + b*16384];
    #pragma unroll
    for (int mt = 0; mt < 2; ++mt) {
        int m = m0w + mt*16 + (lane >> 2);
        #pragma unroll
        for (int nt = 0; nt < 8; ++nt) {
            int p = nt*8 + (lane & 3)*2;
            atomicAdd(&out[m*64 + p],       acc[mt][nt][0]);
            atomicAdd(&out[m*64 + p + 1],   acc[mt][nt][1]);
            atomicAdd(&out[(m+8)*64 + p],   acc[mt][nt][2]);
            atomicAdd(&out[(m+8)*64 + p+1], acc[mt][nt][3]);
        }
    }
}

// fused attention tile (HMMA both GEMMs), scrambled bf16 store
__global__ __launch_bounds__(256) void k_attn(const float* __restrict__ be,
                                              const float* __restrict__ temp)
{
    int bh = blockIdx.y; int b = bh >> 2, h = bh & 3;
    int n0 = blockIdx.x*64;
    __shared__ __align__(16) __nv_bfloat16 sA[64][72];
    __shared__ __align__(16) __nv_bfloat16 sB[64][72];
    __shared__ float ss[64][68];
    __shared__ float qr[64];
    int tid = threadIdx.x;
    int wid = tid >> 5, lane = tid & 31;
    int wm = wid & 1, wn = wid >> 1;
    const float* kbase = &g_zero[ZOFF_KP + bh*4096];
    const float* vbase = &g_zero[ZOFF_VP + bh*4096];

    if (tid < 64)
        qr[tid] = 1.f / fmaxf(sqrtf(g_zero[ZOFF_QSS + b*256 + h*64 + tid]), 1e-12f);
    #pragma unroll
    for (int v = 0; v < 4; ++v) {
        int i4 = v*256 + tid; int d = i4 >> 4, pp = (i4 & 15)*4;
        float4 kv = *(const float4*)(kbase + d*64 + pp);
        sB[d][pp]   = __float2bfloat16(kv.x + be[pp]);
        sB[d][pp+1] = __float2bfloat16(kv.y + be[pp+1]);
        sB[d][pp+2] = __float2bfloat16(kv.z + be[pp+2]);
        sB[d][pp+3] = __float2bfloat16(kv.w + be[pp+3]);
    }
    __syncthreads();
    #pragma unroll
    for (int l = 0; l < 2; ++l) {
        int i8 = l*256 + tid; int r = i8 >> 3, sg = (i8 & 7)*8;
        uint4 v = *(const uint4*)(g_qkv_bf + ((size_t)(b*NNT + n0 + r))*768 + h*64 + sg);
        const __nv_bfloat162* hh = (const __nv_bfloat162*)&v;
        __nv_bfloat16 outv[8];
        #pragma unroll
        for (int j = 0; j < 4; ++j) {
            float2 f = __bfloat1622float2(hh[j]);
            outv[j*2]   = __float2bfloat16(f.x * qr[sg + j*2]);
            outv[j*2+1] = __float2bfloat16(f.y * qr[sg + j*2+1]);
        }
        *(uint4*)&sA[r][sg] = *(uint4*)outv;
    }
    __syncthreads();
    float acc1[2][2][4] = {};
    #pragma unroll
    for (int kk = 0; kk < 64; kk += 16) {
        unsigned int af[2][4];
        #pragma unroll
        for (int mt = 0; mt < 2; ++mt)
            ldm_x4(af[mt], &sA[wm*32 + mt*16 + (lane & 15)][kk + (lane >> 4)*8]);
        unsigned int bfr[4];
        ldm_x4_t(bfr, &sB[kk + (lane & 15)][wn*16 + (lane >> 4)*8]);
        #pragma unroll
        for (int mt = 0; mt < 2; ++mt)
            #pragma unroll
            for (int nt = 0; nt < 2; ++nt)
                mma16816(acc1[mt][nt], af[mt], bfr[nt*2], bfr[nt*2+1]);
    }
    float ts = temp[h];
    #pragma unroll
    for (int mt = 0; mt < 2; ++mt) {
        int r = wm*32 + mt*16 + (lane >> 2);
        #pragma unroll
        for (int nt = 0; nt < 2; ++nt) {
            int c = wn*16 + nt*8 + (lane & 3)*2;
            ss[r][c]     = acc1[mt][nt][0]*ts;
            ss[r][c+1]   = acc1[mt][nt][1]*ts;
            ss[r+8][c]   = acc1[mt][nt][2]*ts;
            ss[r+8][c+1] = acc1[mt][nt][3]*ts;
        }
    }
    __syncthreads();
    #pragma unroll
    for (int v = 0; v < 4; ++v) {
        int i4 = v*256 + tid; int d = i4 >> 4, pp = (i4 & 15)*4;
        float4 vv = *(const float4*)(vbase + d*64 + pp);
        sA[d][pp]   = __float2bfloat16(vv.x + be[pp]);
        sA[d][pp+1] = __float2bfloat16(vv.y + be[pp+1]);
        sA[d][pp+2] = __float2bfloat16(vv.z + be[pp+2]);
        sA[d][pp+3] = __float2bfloat16(vv.w + be[pp+3]);
    }
    {
        int row = tid >> 2, g4 = (tid & 3)*16;
        float e[16];
        float mx = -1e30f;
        #pragma unroll
        for (int p = 0; p < 16; ++p) { e[p] = ss[row][g4+p]; mx = fmaxf(mx, e[p]); }
        mx = fmaxf(mx, __shfl_xor_sync(0xffffffffu, mx, 1));
        mx = fmaxf(mx, __shfl_xor_sync(0xffffffffu, mx, 2));
        float sum = 0.f;
        #pragma unroll
        for (int p = 0; p < 16; ++p) { e[p] = __expf(e[p] - mx); sum += e[p]; }
        sum += __shfl_xor_sync(0xffffffffu, sum, 1);
        sum += __shfl_xor_sync(0xffffffffu, sum, 2);
        float inv = 1.f/sum;
        #pragma unroll
        for (int p = 0; p < 16; ++p)
            sB[g4+p][row] = __float2bfloat16(e[p]*inv);
    }
    __syncthreads();
    float acc2[2][2][4] = {};
    #pragma unroll
    for (int kk = 0; kk < 64; kk += 16) {
        unsigned int af[2][4];
        #pragma unroll
        for (int mt = 0; mt < 2; ++mt)
            ldm_x4(af[mt], &sA[wm*32 + mt*16 + (lane & 15)][kk + (lane >> 4)*8]);
        unsigned int bfr[4];
        ldm_x4_t(bfr, &sB[kk + (lane & 15)][wn*16 + (lane >> 4)*8]);
        #pragma unroll
        for (int mt = 0; mt < 2; ++mt)
            #pragma unroll
            for (int nt = 0; nt < 2; ++nt)
                mma16816(acc2[mt][nt], af[mt], bfr[nt*2], bfr[nt*2+1]);
    }
    __nv_bfloat16* sabase = g_sa_bf + (size_t)b*NNT*CC;
    #pragma unroll
    for (int mt = 0; mt < 2; ++mt) {
        int d0 = wm*32 + mt*16 + (lane >> 2);
        #pragma unroll
        for (int nt = 0; nt < 2; ++nt) {
            int nc = n0 + wn*16 + nt*8 + (lane & 3)*2;
            *(__nv_bfloat162*)&sabase[(size_t)(d0*4 + h)*NNT + nc] =
                __floats2bfloat162_rn(acc2[mt][nt][0], acc2[mt][nt][1]);
            *(__nv_bfloat162*)&sabase[(size_t)((d0+8)*4 + h)*NNT + nc] =
                __floats2bfloat162_rn(acc2[mt][nt][2], acc2[mt][nt][3]);
        }
    }
}

// d_out[b,c,n] += gamma[c]*att[b,n,c]
__global__ void k_final(const float* __restrict__ gamma, float* __restrict__ out)
{
    __shared__ float t1[32][33];
    int n0 = blockIdx.x*32, c0 = blockIdx.y*32, b = blockIdx.z;
    int tx = threadIdx.x, ty = threadIdx.y;
    float gm = gamma[c0+tx];
    for (int yy = ty; yy < 32; yy += 8)
        t1[yy][tx] = gm*__bfloat162float(
            g_att[((size_t)b*NNT + n0 + yy)*CC + c0 + tx]);
    __syncthreads();
    for (int yy = ty; yy < 32; yy += 8) {
        size_t o = (size_t)(b*CC + c0 + yy)*NNT + n0 + tx;
        out[o] += t1[tx][yy];
    }
}

// ---------------- launch ----------------
extern "C" void kernel_launch(void* const* d_in, const int* in_sizes, int n_in,
                              void* d_out, int out_size)
{
    const float* x      = (const float*)d_in[0];
    const float* pos    = (const float*)d_in[1];
    const float* ln_g   = (const float*)d_in[2];
    const float* ln_b   = (const float*)d_in[3];
    const float* gamma  = (const float*)d_in[4];
    const float* temp2  = (const float*)d_in[5];
    const float* w_qkv  = (const float*)d_in[6];
    const float* w_e    = (const float*)d_in[7];
    const float* b_e    = (const float*)d_in[8];
    const float* w_pool = (const float*)d_in[9];
    const float* b_pool = (const float*)d_in[10];
    const float* w_fc1  = (const float*)d_in[11];
    const float* w_fc2  = (const float*)d_in[12];
    const float* b_out1 = (const float*)d_in[14];
    const float* b_out2 = (const float*)d_in[16];
    const float* w_c1   = (const float*)d_in[17];
    const float* b_c1   = (const float*)d_in[18];
    const float* w_c2   = (const float*)d_in[19];
    const float* b_c2   = (const float*)d_in[20];

    __nv_bfloat16 *p_h1b, *p_c2b, *p_xtbf, *p_xctbf, *p_sabf, *p_attb;
    __nv_bfloat16 *p_wq, *p_w1, *p_w2, *p_qkvbf;
    float *p_gate, *p_zero;
    cudaGetSymbolAddress((void**)&p_h1b,   g_h1b);
    cudaGetSymbolAddress((void**)&p_c2b,   g_c2b);
    cudaGetSymbolAddress((void**)&p_xtbf,  g_xt_bf);
    cudaGetSymbolAddress((void**)&p_xctbf, g_xct_bf);
    cudaGetSymbolAddress((void**)&p_qkvbf, g_qkv_bf);
    cudaGetSymbolAddress((void**)&p_sabf,  g_sa_bf);
    cudaGetSymbolAddress((void**)&p_attb,  g_att);
    cudaGetSymbolAddress((void**)&p_wq,    g_wqkv_bf);
    cudaGetSymbolAddress((void**)&p_w1,    g_wo1_bf);
    cudaGetSymbolAddress((void**)&p_w2,    g_wo2_bf);
    cudaGetSymbolAddress((void**)&p_gate,  g_gate);
    cudaGetSymbolAddress((void**)&p_zero,  g_zero);

    static int s_attr_done = 0;
    if (!s_attr_done) {
        cudaFuncSetAttribute(k_megaln,
            cudaFuncAttributeMaxDynamicSharedMemorySize, 73728);
        s_attr_done = 1;
    }

    k_init <<<3456, 256>>>(w_qkv, (const float*)d_in[13],
                           (const float*)d_in[15], w_e);
    // MHCResBlock with fused stats
    k_conv <<<dim3(54,16), 256>>>(x, (const __nv_bfloat16*)0, w_c1, b_c1, p_h1b,
                                  (const float*)0, (const float*)0,
                                  p_zero + ZOFF_CS1S, p_zero + ZOFF_CS1Q);
    k_conv <<<dim3(54,16), 256>>>((const float*)0, p_h1b, w_c2, b_c2, p_c2b,
                                  p_zero + ZOFF_CS1S, p_zero + ZOFF_CS1Q,
                                  p_zero + ZOFF_CS2S, p_zero + ZOFF_CS2Q);
    // mega-fused transpose + xc + double-LN + pool + d_out(x_n)
    k_megaln<<<dim3(432, BB), 256, 73728>>>(x, pos, ln_g, ln_b, w_pool,
                                            (float*)d_out);
    // channel-attention gate
    k_gate <<<BB, 256>>>(b_pool, w_fc1, w_fc2);
    // qkv (pipelined bf16 HMMA + fused q sum-squares)
    k_mma  <<<dim3(6,216,1), 256>>>(p_xtbf, (const __nv_bfloat16*)0, p_wq,
                                    (const __nv_bfloat16*)0, (const float*)0,
                                    (const float*)0, (const float*)0,
                                    p_qkvbf, 768, 768, 1);
    // low-rank K/V projection
    k_kvmma<<<dim3(4,27), 256>>>();
    // spatial attention
    k_attn <<<dim3(216, BB*NHH), 256>>>(b_e, temp2);
    // both output projections (z=0: SA, z=1: CA gated) into g_att [n,c]
    k_mma  <<<dim3(1,216,2), 256>>>(p_sabf, p_xctbf, p_w1, p_w2,
                                    b_out1, b_out2, p_gate,
                                    p_attb, 128, 256, 0);
    // d_out += gamma * att^T
    k_final<<<dim3(432,8,BB), dim3(32,8)>>>(gamma, (float*)d_out);
}

// round 8
// speedup vs baseline: 2.9130x; 1.0281x over previous
#include <cuda_runtime.h>
#include <cuda_bf16.h>
#include <cstdint>
#include <math.h>

#define BB 2
#define CC 256
#define NNT 13824
#define NHH 4
#define MTOT (BB*NNT)

// ---------------- scratch ----------------
__device__ __nv_bfloat16 g_h1b[BB*CC*NNT];            // conv1 out
__device__ __nv_bfloat16 g_c2b[BB*CC*NNT];            // conv2 raw out
__device__ __nv_bfloat16 g_att[BB*NNT*CC];            // concat(SA,CA) out [n,c]
__device__ __nv_bfloat16 g_xt_bf [BB*NNT*CC];         // x_n bf16 (qkv A)
__device__ __nv_bfloat16 g_xct_bf[BB*NNT*CC];         // xc_n bf16
__device__ __nv_bfloat16 g_qkv_bf[(size_t)BB*NNT*768];
__device__ __nv_bfloat16 g_sa_bf [BB*NNT*CC];         // scrambled x_SA
__device__ __nv_bfloat16 g_wqkv_bf[256*768];
__device__ __nv_bfloat16 g_wo1_bf [256*128];
__device__ __nv_bfloat16 g_wo2_bf [256*128];
__device__ __nv_bfloat16 g_we_bf  [NNT*64];
#define ZOFF_POOL 0
#define ZOFF_QSS  512
#define ZOFF_CS1S 1024
#define ZOFF_CS1Q 1536
#define ZOFF_CS2S 2048
#define ZOFF_CS2Q 2560
#define ZOFF_KP   3072
#define ZOFF_VP   35840
#define ZTOT      68608
__device__ float g_zero[ZTOT];
__device__ float g_gate[BB*CC];

// ---------------- asm helpers ----------------
__device__ __forceinline__ void ldm_x4(unsigned int (&r)[4], const void* p) {
    unsigned int a = (unsigned int)__cvta_generic_to_shared(p);
    asm volatile("ldmatrix.sync.aligned.m8n8.x4.shared.b16 {%0,%1,%2,%3}, [%4];"
        : "=r"(r[0]),"=r"(r[1]),"=r"(r[2]),"=r"(r[3]) : "r"(a));
}
__device__ __forceinline__ void ldm_x4_t(unsigned int (&r)[4], const void* p) {
    unsigned int a = (unsigned int)__cvta_generic_to_shared(p);
    asm volatile("ldmatrix.sync.aligned.m8n8.x4.trans.shared.b16 {%0,%1,%2,%3}, [%4];"
        : "=r"(r[0]),"=r"(r[1]),"=r"(r[2]),"=r"(r[3]) : "r"(a));
}
__device__ __forceinline__ void mma16816(float (&d)[4], const unsigned int (&a)[4],
                                         unsigned int b0, unsigned int b1) {
    asm volatile("mma.sync.aligned.m16n8k16.row.col.f32.bf16.bf16.f32 "
        "{%0,%1,%2,%3},{%4,%5,%6,%7},{%8,%9},{%0,%1,%2,%3};"
        : "+f"(d[0]),"+f"(d[1]),"+f"(d[2]),"+f"(d[3])
        : "r"(a[0]),"r"(a[1]),"r"(a[2]),"r"(a[3]),"r"(b0),"r"(b1));
}
__device__ __forceinline__ void cpa16(void* dst, const void* src) {
    unsigned int d = (unsigned int)__cvta_generic_to_shared(dst);
    asm volatile("cp.async.cg.shared.global [%0], [%1], 16;" :: "r"(d), "l"(src));
}
__device__ __forceinline__ void cp_commit() { asm volatile("cp.async.commit_group;"); }
template<int N> __device__ __forceinline__ void cp_wait() {
    asm volatile("cp.async.wait_group %0;" :: "n"(N));
}

// ---------------- kernels ----------------
__global__ void k_init(const float* __restrict__ wq, const float* __restrict__ w1,
                       const float* __restrict__ w2, const float* __restrict__ we)
{
    int i = blockIdx.x*256 + threadIdx.x;
    if (i < ZTOT) g_zero[i] = 0.f;
    if (i < 196608) g_wqkv_bf[i] = __float2bfloat16(wq[i]);
    if (i < 32768)  { g_wo1_bf[i] = __float2bfloat16(w1[i]);
                      g_wo2_bf[i] = __float2bfloat16(w2[i]); }
    if (i < NNT*64) g_we_bf[i] = __float2bfloat16(we[i]);
}

// grouped 1x1x1 conv; conv2 normalizes+lrelu's its input from (sum,ssq);
// both emit per-channel (sum, sumsq) of their fp32 outputs via atomics.
__global__ __launch_bounds__(256) void k_conv(
    const float* __restrict__ srcf, const __nv_bfloat16* __restrict__ srcb,
    const float* __restrict__ w, const float* __restrict__ bias,
    __nv_bfloat16* __restrict__ dst,
    const float* __restrict__ sin_s, const float* __restrict__ sin_q,
    float* __restrict__ sout_s, float* __restrict__ sout_q)
{
    int bg = blockIdx.y; int b = bg >> 3; int g = bg & 7;
    int n  = blockIdx.x*256 + threadIdx.x;
    int tid = threadIdx.x, lane = tid & 31, wid = tid >> 5;
    __shared__ float ws[1024];
    __shared__ float sm[32], sr[32];
    __shared__ float sacc[32][257];
    int cbase = b*CC + g*32;
    for (int i = tid; i < 1024; i += 256) ws[i] = w[g*1024 + i];
    if (srcb && tid < 32) {
        float s = sin_s[cbase+tid], q = sin_q[cbase+tid];
        float m = s*(1.f/NNT);
        sm[tid] = m;
        sr[tid] = rsqrtf(q*(1.f/NNT) - m*m + 1e-5f);
    }
    __syncthreads();
    float acc[32];
    #pragma unroll
    for (int o = 0; o < 32; ++o) acc[o] = bias[g*32+o];
    bool useb = (srcb != nullptr);
    #pragma unroll 8
    for (int i = 0; i < 32; ++i) {
        float v;
        if (useb) {
            v = __bfloat162float(srcb[(size_t)(cbase+i)*NNT + n]);
            v = (v - sm[i])*sr[i];
            v = v >= 0.f ? v : 0.01f*v;
        } else {
            v = srcf[(size_t)(cbase+i)*NNT + n];
        }
        #pragma unroll
        for (int o = 0; o < 32; ++o) acc[o] += v*ws[i*32+o];
    }
    #pragma unroll 4
    for (int o = 0; o < 32; ++o)
        dst[(size_t)(cbase+o)*NNT + n] = __float2bfloat16(acc[o]);
    #pragma unroll
    for (int o = 0; o < 32; ++o) sacc[o][tid] = acc[o];
    __syncthreads();
    #pragma unroll
    for (int k = 0; k < 4; ++k) {
        int ch = wid*4 + k;
        float s = 0.f, q = 0.f;
        #pragma unroll
        for (int j = 0; j < 8; ++j) {
            float v = sacc[ch][lane + 32*j];
            s += v; q += v*v;
        }
        #pragma unroll
        for (int o = 16; o; o >>= 1) {
            s += __shfl_xor_sync(0xffffffffu, s, o);
            q += __shfl_xor_sync(0xffffffffu, q, o);
        }
        if (lane == 0) {
            atomicAdd(&sout_s[cbase+ch], s);
            atomicAdd(&sout_q[cbase+ch], q);
        }
    }
}

// mega-fused: xc = lrelu(inorm(conv2)+x); +pos; LN both streams (warp/token);
// x_n fp32 -> d_out [c,n]; bf16 x_n/xc_n; pool partials (register-accumulated).
// dyn smem layout: xs[256*33] f32 | stm,str,lgs,lbs[256] | cs[256*34] bf16
// (cs region reused post-LN as pws[8][256] f32 for the pool reduction)
__global__ __launch_bounds__(256) void k_megaln(
    const float* __restrict__ x, const float* __restrict__ pos,
    const float* __restrict__ lg, const float* __restrict__ lb,
    const float* __restrict__ wp, float* __restrict__ dout)
{
    extern __shared__ float dsm[];
    float* xs  = dsm;                                  // 8448 f32
    float* stm = dsm + 8448;
    float* str = stm + 256;
    float* lgs = str + 256;
    float* lbs = lgs + 256;
    __nv_bfloat16* cs = (__nv_bfloat16*)(dsm + 9472);  // 8704 bf16
    int tid = threadIdx.x, tx = tid & 31, ty = tid >> 5;
    int lane = tid & 31, w = tid >> 5;
    int n0 = blockIdx.x*32, b = blockIdx.y;
    {
        float s = g_zero[ZOFF_CS2S + b*256 + tid];
        float q = g_zero[ZOFF_CS2Q + b*256 + tid];
        float m = s*(1.f/NNT);
        stm[tid] = m;
        str[tid] = rsqrtf(q*(1.f/NNT) - m*m + 1e-5f);
        lgs[tid] = lg[tid]; lbs[tid] = lb[tid];
    }
    __syncthreads();
    for (int cc = ty; cc < 256; cc += 8) {
        size_t s = (size_t)(b*CC + cc)*NNT + n0 + tx;
        float xv = x[s];
        float hv = (__bfloat162float(g_c2b[s]) - stm[cc])*str[cc] + xv;
        xs[cc*33 + tx] = xv;
        cs[cc*34 + tx] = __float2bfloat16(hv >= 0.f ? hv : 0.01f*hv);
    }
    __syncthreads();
    float pacc[8];
    #pragma unroll
    for (int j = 0; j < 8; ++j) pacc[j] = 0.f;
    for (int t8 = 0; t8 < 4; ++t8) {
        int tok = w + t8*8;
        const float* prow = pos + (size_t)(n0 + tok)*CC;
        float v1[8], v2[8];
        float s1 = 0.f, q1 = 0.f, s2 = 0.f, q2 = 0.f;
        #pragma unroll
        for (int j = 0; j < 8; ++j) {
            int c = lane + 32*j;
            float p = prow[c];
            float a  = xs[c*33 + tok] + p;
            float d2 = __bfloat162float(cs[c*34 + tok]) + p;
            v1[j] = a; v2[j] = d2;
            s1 += a; q1 += a*a; s2 += d2; q2 += d2*d2;
        }
        #pragma unroll
        for (int o = 16; o; o >>= 1) {
            s1 += __shfl_xor_sync(0xffffffffu, s1, o);
            q1 += __shfl_xor_sync(0xffffffffu, q1, o);
            s2 += __shfl_xor_sync(0xffffffffu, s2, o);
            q2 += __shfl_xor_sync(0xffffffffu, q2, o);
        }
        float m1 = s1*(1.f/CC), r1 = rsqrtf(q1*(1.f/CC) - m1*m1 + 1e-5f);
        float m2 = s2*(1.f/CC), r2 = rsqrtf(q2*(1.f/CC) - m2*m2 + 1e-5f);
        float wpt = wp[n0 + tok];
        size_t gbase = ((size_t)b*NNT + n0 + tok)*CC;
        #pragma unroll
        for (int j = 0; j < 8; ++j) {
            int c = lane + 32*j;
            float o1 = (v1[j] - m1)*r1*lgs[c] + lbs[c];
            float o2 = (v2[j] - m2)*r2*lgs[c] + lbs[c];
            g_xt_bf [gbase + c] = __float2bfloat16(o1);
            g_xct_bf[gbase + c] = __float2bfloat16(o2);
            xs[c*33 + tok] = o1;                 // x_n fp32 for output
            pacc[j] += o2*wpt;
        }
    }
    __syncthreads();                 // all LN reads of cs done
    float* pws = (float*)cs;         // overlay: pws[warp][channel]
    #pragma unroll
    for (int j = 0; j < 8; ++j) pws[w*256 + lane + 32*j] = pacc[j];
    __syncthreads();
    {
        float s = 0.f;
        #pragma unroll
        for (int ww = 0; ww < 8; ++ww) s += pws[ww*256 + tid];
        atomicAdd(&g_zero[ZOFF_POOL + b*256 + tid], s);
    }
    for (int cc = ty; cc < 256; cc += 8)
        dout[(size_t)(b*CC + cc)*NNT + n0 + tx] = xs[cc*33 + tx];
}

__global__ void k_gate(const float* __restrict__ bp, const float* __restrict__ w1,
                       const float* __restrict__ w2)
{
    __shared__ float ps[256], hs[64];
    int b = blockIdx.x, t = threadIdx.x;
    ps[t] = g_zero[ZOFF_POOL + b*CC + t] + bp[0];
    __syncthreads();
    if (t < 64) {
        float a = 0.f;
        for (int c = 0; c < 256; ++c) a += ps[c]*w1[c*64 + t];
        hs[t] = fmaxf(a, 0.f);
    }
    __syncthreads();
    float a = 0.f;
    for (int j = 0; j < 64; ++j) a += hs[j]*w2[j*256 + t];
    g_gate[b*CC + t] = 1.f/(1.f + expf(-a));
}

// bf16 HMMA GEMM with cp.async double buffering.
__global__ __launch_bounds__(256) void k_mma(
    const __nv_bfloat16* __restrict__ A, const __nv_bfloat16* __restrict__ A2,
    const __nv_bfloat16* __restrict__ Bw, const __nv_bfloat16* __restrict__ Bw2,
    const float* __restrict__ bias, const float* __restrict__ bias2,
    const float* __restrict__ gate,
    __nv_bfloat16* __restrict__ Cb, int Nld, int ldc, int doqss)
{
    __shared__ __align__(16) __nv_bfloat16 As[2][128][40];
    __shared__ __align__(16) __nv_bfloat16 Bs[2][32][136];
    int tid = threadIdx.x;
    int wid = tid >> 5, lane = tid & 31;
    int wm = wid >> 2;
    int wn = wid & 3;
    int m0 = blockIdx.y * 128;
    int n0 = blockIdx.x * 128;
    int coff = 0;
    const float* grow = nullptr;
    if (blockIdx.z == 1) {
        A = A2; Bw = Bw2; bias = bias2; coff = 128;
        grow = gate + (m0 / NNT)*CC;
    }

    float acc[4][4][4] = {};

    #pragma unroll
    for (int p = 0; p < 2; ++p) {
        int idx = p*256 + tid; int r = idx >> 2, sg = idx & 3;
        cpa16(&As[0][r][sg*8], A + (size_t)(m0 + r)*256 + sg*8);
    }
    #pragma unroll
    for (int p = 0; p < 2; ++p) {
        int idx = p*256 + tid; int r = idx >> 4, sg = idx & 15;
        cpa16(&Bs[0][r][sg*8], Bw + (size_t)r*Nld + n0 + sg*8);
    }
    cp_commit();

    for (int it = 0; it < 8; ++it) {
        int k0 = it*32, st = it & 1;
        if (it < 7) {
            int kn = k0 + 32, sn = st ^ 1;
            #pragma unroll
            for (int p = 0; p < 2; ++p) {
                int idx = p*256 + tid; int r = idx >> 2, sg = idx & 3;
                cpa16(&As[sn][r][sg*8], A + (size_t)(m0 + r)*256 + kn + sg*8);
            }
            #pragma unroll
            for (int p = 0; p < 2; ++p) {
                int idx = p*256 + tid; int r = idx >> 4, sg = idx & 15;
                cpa16(&Bs[sn][r][sg*8], Bw + (size_t)(kn + r)*Nld + n0 + sg*8);
            }
            cp_commit();
            cp_wait<1>();
        } else {
            cp_wait<0>();
        }
        __syncthreads();
        if (grow) {
            #pragma unroll
            for (int p = 0; p < 2; ++p) {
                int idx = p*256 + tid; int r = idx >> 2, sg = idx & 3;
                __nv_bfloat16* qp = &As[st][r][sg*8];
                #pragma unroll
                for (int j = 0; j < 8; ++j)
                    qp[j] = __float2bfloat16(__bfloat162float(qp[j])*grow[k0+sg*8+j]);
            }
            __syncthreads();
        }
        #pragma unroll
        for (int kk = 0; kk < 2; ++kk) {
            unsigned int af[4][4];
            #pragma unroll
            for (int mt = 0; mt < 4; ++mt)
                ldm_x4(af[mt], &As[st][wm*64 + mt*16 + (lane & 15)][kk*16 + (lane >> 4)*8]);
            unsigned int bfr[2][4];
            #pragma unroll
            for (int g2 = 0; g2 < 2; ++g2)
                ldm_x4_t(bfr[g2], &Bs[st][kk*16 + (lane & 15)][wn*32 + g2*16 + (lane >> 4)*8]);
            #pragma unroll
            for (int mt = 0; mt < 4; ++mt)
                #pragma unroll
                for (int nt = 0; nt < 4; ++nt)
                    mma16816(acc[mt][nt], af[mt],
                             bfr[nt>>1][(nt&1)*2], bfr[nt>>1][(nt&1)*2+1]);
        }
        __syncthreads();
    }
    if (doqss && n0 < 256) {
        int b = m0 / NNT;
        #pragma unroll
        for (int nt = 0; nt < 4; ++nt) {
            float s0 = 0.f, s1 = 0.f;
            #pragma unroll
            for (int mt = 0; mt < 4; ++mt) {
                #pragma unroll
                for (int h = 0; h < 2; ++h) {
                    float a0 = acc[mt][nt][h*2+0], a1 = acc[mt][nt][h*2+1];
                    s0 += a0*a0; s1 += a1*a1;
                }
            }
            #pragma unroll
            for (int o = 4; o <= 16; o <<= 1) {
                s0 += __shfl_xor_sync(0xffffffffu, s0, o);
                s1 += __shfl_xor_sync(0xffffffffu, s1, o);
            }
            if ((lane >> 2) == 0) {
                int col = n0 + wn*32 + nt*8 + (lane & 3)*2;
                atomicAdd(&g_zero[ZOFF_QSS + b*256 + col],   s0);
                atomicAdd(&g_zero[ZOFF_QSS + b*256 + col+1], s1);
            }
        }
    }
    #pragma unroll
    for (int mt = 0; mt < 4; ++mt) {
        int row0 = m0 + wm*64 + mt*16 + (lane >> 2);
        #pragma unroll
        for (int nt = 0; nt < 4; ++nt) {
            int col = wn*32 + nt*8 + (lane & 3)*2;
            #pragma unroll
            for (int h = 0; h < 2; ++h) {
                int r = row0 + h*8;
                float v0 = acc[mt][nt][h*2+0];
                float v1 = acc[mt][nt][h*2+1];
                if (bias) { v0 += bias[n0+col]; v1 += bias[n0+col+1]; }
                __nv_bfloat16* p = Cb + (size_t)r*ldc + coff + n0 + col;
                p[0] = __float2bfloat16(v0); p[1] = __float2bfloat16(v1);
            }
        }
    }
}

// K/V low-rank projection via tensor cores; split-N=54 for occupancy
__global__ __launch_bounds__(256) void k_kvmma()
{
    int b = blockIdx.x >> 1, which = blockIdx.x & 1;
    int n0 = blockIdx.y * 256;
    int coff = 256*(which+1);
    __shared__ __align__(16) __nv_bfloat16 Ks[32][264];
    __shared__ __align__(16) __nv_bfloat16 Es[32][72];
    int tid = threadIdx.x, lane = tid & 31, wid = tid >> 5;
    int m0w = wid*32;
    float acc[2][8][4] = {};

    for (int c = 0; c < 8; ++c) {
        int nt0 = n0 + c*32;
        #pragma unroll
        for (int v = 0; v < 4; ++v) {
            int idx = v*256 + tid; int r = idx >> 5, sg = idx & 31;
            *(uint4*)&Ks[r][sg*8] =
                *(const uint4*)(g_qkv_bf + ((size_t)(b*NNT + nt0 + r))*768 + coff + sg*8);
        }
        {
            int r = tid >> 3, sg = tid & 7;
            *(uint4*)&Es[r][sg*8] = *(const uint4*)(g_we_bf + (size_t)(nt0 + r)*64 + sg*8);
        }
        __syncthreads();
        #pragma unroll
        for (int kk = 0; kk < 32; kk += 16) {
            unsigned int af[2][4];
            #pragma unroll
            for (int mt = 0; mt < 2; ++mt)
                ldm_x4_t(af[mt], &Ks[kk + (lane & 7) + ((lane >> 4) << 3)]
                                    [m0w + mt*16 + ((lane >> 3) & 1)*8]);
            unsigned int bfr[4][4];
            #pragma unroll
            for (int ng = 0; ng < 4; ++ng)
                ldm_x4_t(bfr[ng], &Es[kk + (lane & 15)][ng*16 + (lane >> 4)*8]);
            #pragma unroll
            for (int mt = 0; mt < 2; ++mt)
                #pragma unroll
                for (int nt = 0; nt < 8; ++nt)
                    mma16816(acc[mt][nt], af[mt],
                             bfr[nt>>1][(nt&1)*2], bfr[nt>>1][(nt&1)*2+1]);
        }
        __syncthreads();
    }
    float* out = &g_zero[ZOFF_KP + which*32768 + b*16384];
    #pragma unroll
    for (int mt = 0; mt < 2; ++mt) {
        int m = m0w + mt*16 + (lane >> 2);
        #pragma unroll
        for (int nt = 0; nt < 8; ++nt) {
            int p = nt*8 + (lane & 3)*2;
            atomicAdd(&out[m*64 + p],       acc[mt][nt][0]);
            atomicAdd(&out[m*64 + p + 1],   acc[mt][nt][1]);
            atomicAdd(&out[(m+8)*64 + p],   acc[mt][nt][2]);
            atomicAdd(&out[(m+8)*64 + p+1], acc[mt][nt][3]);
        }
    }
}

// fused attention tile (HMMA both GEMMs), scrambled bf16 store
__global__ __launch_bounds__(256) void k_attn(const float* __restrict__ be,
                                              const float* __restrict__ temp)
{
    int bh = blockIdx.y; int b = bh >> 2, h = bh & 3;
    int n0 = blockIdx.x*64;
    __shared__ __align__(16) __nv_bfloat16 sA[64][72];
    __shared__ __align__(16) __nv_bfloat16 sB[64][72];
    __shared__ float ss[64][68];
    __shared__ float qr[64];
    int tid = threadIdx.x;
    int wid = tid >> 5, lane = tid & 31;
    int wm = wid & 1, wn = wid >> 1;
    const float* kbase = &g_zero[ZOFF_KP + bh*4096];
    const float* vbase = &g_zero[ZOFF_VP + bh*4096];

    if (tid < 64)
        qr[tid] = 1.f / fmaxf(sqrtf(g_zero[ZOFF_QSS + b*256 + h*64 + tid]), 1e-12f);
    #pragma unroll
    for (int v = 0; v < 4; ++v) {
        int i4 = v*256 + tid; int d = i4 >> 4, pp = (i4 & 15)*4;
        float4 kv = *(const float4*)(kbase + d*64 + pp);
        sB[d][pp]   = __float2bfloat16(kv.x + be[pp]);
        sB[d][pp+1] = __float2bfloat16(kv.y + be[pp+1]);
        sB[d][pp+2] = __float2bfloat16(kv.z + be[pp+2]);
        sB[d][pp+3] = __float2bfloat16(kv.w + be[pp+3]);
    }
    __syncthreads();
    #pragma unroll
    for (int l = 0; l < 2; ++l) {
        int i8 = l*256 + tid; int r = i8 >> 3, sg = (i8 & 7)*8;
        uint4 v = *(const uint4*)(g_qkv_bf + ((size_t)(b*NNT + n0 + r))*768 + h*64 + sg);
        const __nv_bfloat162* hh = (const __nv_bfloat162*)&v;
        __nv_bfloat16 outv[8];
        #pragma unroll
        for (int j = 0; j < 4; ++j) {
            float2 f = __bfloat1622float2(hh[j]);
            outv[j*2]   = __float2bfloat16(f.x * qr[sg + j*2]);
            outv[j*2+1] = __float2bfloat16(f.y * qr[sg + j*2+1]);
        }
        *(uint4*)&sA[r][sg] = *(uint4*)outv;
    }
    __syncthreads();
    float acc1[2][2][4] = {};
    #pragma unroll
    for (int kk = 0; kk < 64; kk += 16) {
        unsigned int af[2][4];
        #pragma unroll
        for (int mt = 0; mt < 2; ++mt)
            ldm_x4(af[mt], &sA[wm*32 + mt*16 + (lane & 15)][kk + (lane >> 4)*8]);
        unsigned int bfr[4];
        ldm_x4_t(bfr, &sB[kk + (lane & 15)][wn*16 + (lane >> 4)*8]);
        #pragma unroll
        for (int mt = 0; mt < 2; ++mt)
            #pragma unroll
            for (int nt = 0; nt < 2; ++nt)
                mma16816(acc1[mt][nt], af[mt], bfr[nt*2], bfr[nt*2+1]);
    }
    float ts = temp[h];
    #pragma unroll
    for (int mt = 0; mt < 2; ++mt) {
        int r = wm*32 + mt*16 + (lane >> 2);
        #pragma unroll
        for (int nt = 0; nt < 2; ++nt) {
            int c = wn*16 + nt*8 + (lane & 3)*2;
            ss[r][c]     = acc1[mt][nt][0]*ts;
            ss[r][c+1]   = acc1[mt][nt][1]*ts;
            ss[r+8][c]   = acc1[mt][nt][2]*ts;
            ss[r+8][c+1] = acc1[mt][nt][3]*ts;
        }
    }
    __syncthreads();
    #pragma unroll
    for (int v = 0; v < 4; ++v) {
        int i4 = v*256 + tid; int d = i4 >> 4, pp = (i4 & 15)*4;
        float4 vv = *(const float4*)(vbase + d*64 + pp);
        sA[d][pp]   = __float2bfloat16(vv.x + be[pp]);
        sA[d][pp+1] = __float2bfloat16(vv.y + be[pp+1]);
        sA[d][pp+2] = __float2bfloat16(vv.z + be[pp+2]);
        sA[d][pp+3] = __float2bfloat16(vv.w + be[pp+3]);
    }
    {
        int row = tid >> 2, g4 = (tid & 3)*16;
        float e[16];
        float mx = -1e30f;
        #pragma unroll
        for (int p = 0; p < 16; ++p) { e[p] = ss[row][g4+p]; mx = fmaxf(mx, e[p]); }
        mx = fmaxf(mx, __shfl_xor_sync(0xffffffffu, mx, 1));
        mx = fmaxf(mx, __shfl_xor_sync(0xffffffffu, mx, 2));
        float sum = 0.f;
        #pragma unroll
        for (int p = 0; p < 16; ++p) { e[p] = __expf(e[p] - mx); sum += e[p]; }
        sum += __shfl_xor_sync(0xffffffffu, sum, 1);
        sum += __shfl_xor_sync(0xffffffffu, sum, 2);
        float inv = 1.f/sum;
        #pragma unroll
        for (int p = 0; p < 16; ++p)
            sB[g4+p][row] = __float2bfloat16(e[p]*inv);
    }
    __syncthreads();
    float acc2[2][2][4] = {};
    #pragma unroll
    for (int kk = 0; kk < 64; kk += 16) {
        unsigned int af[2][4];
        #pragma unroll
        for (int mt = 0; mt < 2; ++mt)
            ldm_x4(af[mt], &sA[wm*32 + mt*16 + (lane & 15)][kk + (lane >> 4)*8]);
        unsigned int bfr[4];
        ldm_x4_t(bfr, &sB[kk + (lane & 15)][wn*16 + (lane >> 4)*8]);
        #pragma unroll
        for (int mt = 0; mt < 2; ++mt)
            #pragma unroll
            for (int nt = 0; nt < 2; ++nt)
                mma16816(acc2[mt][nt], af[mt], bfr[nt*2], bfr[nt*2+1]);
    }
    __nv_bfloat16* sabase = g_sa_bf + (size_t)b*NNT*CC;
    #pragma unroll
    for (int mt = 0; mt < 2; ++mt) {
        int d0 = wm*32 + mt*16 + (lane >> 2);
        #pragma unroll
        for (int nt = 0; nt < 2; ++nt) {
            int nc = n0 + wn*16 + nt*8 + (lane & 3)*2;
            *(__nv_bfloat162*)&sabase[(size_t)(d0*4 + h)*NNT + nc] =
                __floats2bfloat162_rn(acc2[mt][nt][0], acc2[mt][nt][1]);
            *(__nv_bfloat162*)&sabase[(size_t)((d0+8)*4 + h)*NNT + nc] =
                __floats2bfloat162_rn(acc2[mt][nt][2], acc2[mt][nt][3]);
        }
    }
}

// d_out[b,c,n] += gamma[c]*att[b,n,c]
__global__ void k_final(const float* __restrict__ gamma, float* __restrict__ out)
{
    __shared__ float t1[32][33];
    int n0 = blockIdx.x*32, c0 = blockIdx.y*32, b = blockIdx.z;
    int tx = threadIdx.x, ty = threadIdx.y;
    float gm = gamma[c0+tx];
    for (int yy = ty; yy < 32; yy += 8)
        t1[yy][tx] = gm*__bfloat162float(
            g_att[((size_t)b*NNT + n0 + yy)*CC + c0 + tx]);
    __syncthreads();
    for (int yy = ty; yy < 32; yy += 8) {
        size_t o = (size_t)(b*CC + c0 + yy)*NNT + n0 + tx;
        out[o] += t1[tx][yy];
    }
}

// ---------------- launch ----------------
extern "C" void kernel_launch(void* const* d_in, const int* in_sizes, int n_in,
                              void* d_out, int out_size)
{
    const float* x      = (const float*)d_in[0];
    const float* pos    = (const float*)d_in[1];
    const float* ln_g   = (const float*)d_in[2];
    const float* ln_b   = (const float*)d_in[3];
    const float* gamma  = (const float*)d_in[4];
    const float* temp2  = (const float*)d_in[5];
    const float* w_qkv  = (const float*)d_in[6];
    const float* w_e    = (const float*)d_in[7];
    const float* b_e    = (const float*)d_in[8];
    const float* w_pool = (const float*)d_in[9];
    const float* b_pool = (const float*)d_in[10];
    const float* w_fc1  = (const float*)d_in[11];
    const float* w_fc2  = (const float*)d_in[12];
    const float* b_out1 = (const float*)d_in[14];
    const float* b_out2 = (const float*)d_in[16];
    const float* w_c1   = (const float*)d_in[17];
    const float* b_c1   = (const float*)d_in[18];
    const float* w_c2   = (const float*)d_in[19];
    const float* b_c2   = (const float*)d_in[20];

    __nv_bfloat16 *p_h1b, *p_c2b, *p_xtbf, *p_xctbf, *p_sabf, *p_attb;
    __nv_bfloat16 *p_wq, *p_w1, *p_w2, *p_qkvbf;
    float *p_gate, *p_zero;
    cudaGetSymbolAddress((void**)&p_h1b,   g_h1b);
    cudaGetSymbolAddress((void**)&p_c2b,   g_c2b);
    cudaGetSymbolAddress((void**)&p_xtbf,  g_xt_bf);
    cudaGetSymbolAddress((void**)&p_xctbf, g_xct_bf);
    cudaGetSymbolAddress((void**)&p_qkvbf, g_qkv_bf);
    cudaGetSymbolAddress((void**)&p_sabf,  g_sa_bf);
    cudaGetSymbolAddress((void**)&p_attb,  g_att);
    cudaGetSymbolAddress((void**)&p_wq,    g_wqkv_bf);
    cudaGetSymbolAddress((void**)&p_w1,    g_wo1_bf);
    cudaGetSymbolAddress((void**)&p_w2,    g_wo2_bf);
    cudaGetSymbolAddress((void**)&p_gate,  g_gate);
    cudaGetSymbolAddress((void**)&p_zero,  g_zero);

    static int s_attr_done = 0;
    if (!s_attr_done) {
        cudaFuncSetAttribute(k_megaln,
            cudaFuncAttributeMaxDynamicSharedMemorySize, 55296);
        s_attr_done = 1;
    }

    k_init <<<3456, 256>>>(w_qkv, (const float*)d_in[13],
                           (const float*)d_in[15], w_e);
    // MHCResBlock with fused stats
    k_conv <<<dim3(54,16), 256>>>(x, (const __nv_bfloat16*)0, w_c1, b_c1, p_h1b,
                                  (const float*)0, (const float*)0,
                                  p_zero + ZOFF_CS1S, p_zero + ZOFF_CS1Q);
    k_conv <<<dim3(54,16), 256>>>((const float*)0, p_h1b, w_c2, b_c2, p_c2b,
                                  p_zero + ZOFF_CS1S, p_zero + ZOFF_CS1Q,
                                  p_zero + ZOFF_CS2S, p_zero + ZOFF_CS2Q);
    // mega-fused transpose + xc + double-LN + pool + d_out(x_n)
    k_megaln<<<dim3(432, BB), 256, 55296>>>(x, pos, ln_g, ln_b, w_pool,
                                            (float*)d_out);
    // channel-attention gate
    k_gate <<<BB, 256>>>(b_pool, w_fc1, w_fc2);
    // qkv (pipelined bf16 HMMA + fused q sum-squares)
    k_mma  <<<dim3(6,216,1), 256>>>(p_xtbf, (const __nv_bfloat16*)0, p_wq,
                                    (const __nv_bfloat16*)0, (const float*)0,
                                    (const float*)0, (const float*)0,
                                    p_qkvbf, 768, 768, 1);
    // low-rank K/V projection (split-N = 54)
    k_kvmma<<<dim3(4,54), 256>>>();
    // spatial attention
    k_attn <<<dim3(216, BB*NHH), 256>>>(b_e, temp2);
    // both output projections (z=0: SA, z=1: CA gated) into g_att [n,c]
    k_mma  <<<dim3(1,216,2), 256>>>(p_sabf, p_xctbf, p_w1, p_w2,
                                    b_out1, b_out2, p_gate,
                                    p_attb, 128, 256, 0);
    // d_out += gamma * att^T
    k_final<<<dim3(432,8,BB), dim3(32,8)>>>(gamma, (float*)d_out);
}

// round 9
// speedup vs baseline: 3.1435x; 1.0791x over previous
#include <cuda_runtime.h>
#include <cuda_bf16.h>
#include <cstdint>
#include <math.h>

#define BB 2
#define CC 256
#define NNT 13824
#define NHH 4
#define MTOT (BB*NNT)

// ---------------- scratch ----------------
__device__ __nv_bfloat16 g_h1b[BB*CC*NNT];            // conv1 out
__device__ __nv_bfloat16 g_c2b[BB*CC*NNT];            // conv2 raw out
__device__ __nv_bfloat16 g_xt_bf [BB*NNT*CC];         // x_n bf16 (qkv A)
__device__ __nv_bfloat16 g_xct_bf[BB*NNT*CC];         // xc_n bf16
__device__ __nv_bfloat16 g_qkv_bf[(size_t)BB*NNT*768];
__device__ __nv_bfloat16 g_sa_bf [BB*NNT*CC];         // scrambled x_SA
__device__ __nv_bfloat16 g_wqkv_bf[256*768];
__device__ __nv_bfloat16 g_wo1_bf [256*128];
__device__ __nv_bfloat16 g_wo2_bf [256*128];
__device__ __nv_bfloat16 g_we_bf  [NNT*64];
#define ZOFF_POOL 0
#define ZOFF_QSS  512
#define ZOFF_CS1S 1024
#define ZOFF_CS1Q 1536
#define ZOFF_CS2S 2048
#define ZOFF_CS2Q 2560
#define ZOFF_KP   3072
#define ZOFF_VP   35840
#define ZTOT      68608
__device__ float g_zero[ZTOT];
__device__ float g_gate[BB*CC];

// ---------------- asm helpers ----------------
__device__ __forceinline__ void ldm_x4(unsigned int (&r)[4], const void* p) {
    unsigned int a = (unsigned int)__cvta_generic_to_shared(p);
    asm volatile("ldmatrix.sync.aligned.m8n8.x4.shared.b16 {%0,%1,%2,%3}, [%4];"
        : "=r"(r[0]),"=r"(r[1]),"=r"(r[2]),"=r"(r[3]) : "r"(a));
}
__device__ __forceinline__ void ldm_x4_t(unsigned int (&r)[4], const void* p) {
    unsigned int a = (unsigned int)__cvta_generic_to_shared(p);
    asm volatile("ldmatrix.sync.aligned.m8n8.x4.trans.shared.b16 {%0,%1,%2,%3}, [%4];"
        : "=r"(r[0]),"=r"(r[1]),"=r"(r[2]),"=r"(r[3]) : "r"(a));
}
__device__ __forceinline__ void mma16816(float (&d)[4], const unsigned int (&a)[4],
                                         unsigned int b0, unsigned int b1) {
    asm volatile("mma.sync.aligned.m16n8k16.row.col.f32.bf16.bf16.f32 "
        "{%0,%1,%2,%3},{%4,%5,%6,%7},{%8,%9},{%0,%1,%2,%3};"
        : "+f"(d[0]),"+f"(d[1]),"+f"(d[2]),"+f"(d[3])
        : "r"(a[0]),"r"(a[1]),"r"(a[2]),"r"(a[3]),"r"(b0),"r"(b1));
}
__device__ __forceinline__ void cpa16(void* dst, const void* src) {
    unsigned int d = (unsigned int)__cvta_generic_to_shared(dst);
    asm volatile("cp.async.cg.shared.global [%0], [%1], 16;" :: "r"(d), "l"(src));
}
__device__ __forceinline__ void cp_commit() { asm volatile("cp.async.commit_group;"); }
template<int N> __device__ __forceinline__ void cp_wait() {
    asm volatile("cp.async.wait_group %0;" :: "n"(N));
}

// ---------------- kernels ----------------
__global__ void k_init(const float* __restrict__ wq, const float* __restrict__ w1,
                       const float* __restrict__ w2, const float* __restrict__ we)
{
    int i = blockIdx.x*256 + threadIdx.x;
    if (i < ZTOT) g_zero[i] = 0.f;
    if (i < 196608) g_wqkv_bf[i] = __float2bfloat16(wq[i]);
    if (i < 32768)  { g_wo1_bf[i] = __float2bfloat16(w1[i]);
                      g_wo2_bf[i] = __float2bfloat16(w2[i]); }
    if (i < NNT*64) g_we_bf[i] = __float2bfloat16(we[i]);
}

// grouped 1x1x1 conv; conv2 normalizes+lrelu's its input from (sum,ssq);
// both emit per-channel (sum, sumsq) of their fp32 outputs via atomics.
__global__ __launch_bounds__(256) void k_conv(
    const float* __restrict__ srcf, const __nv_bfloat16* __restrict__ srcb,
    const float* __restrict__ w, const float* __restrict__ bias,
    __nv_bfloat16* __restrict__ dst,
    const float* __restrict__ sin_s, const float* __restrict__ sin_q,
    float* __restrict__ sout_s, float* __restrict__ sout_q)
{
    int bg = blockIdx.y; int b = bg >> 3; int g = bg & 7;
    int n  = blockIdx.x*256 + threadIdx.x;
    int tid = threadIdx.x, lane = tid & 31, wid = tid >> 5;
    __shared__ float ws[1024];
    __shared__ float sm[32], sr[32];
    __shared__ float sacc[32][257];
    int cbase = b*CC + g*32;
    for (int i = tid; i < 1024; i += 256) ws[i] = w[g*1024 + i];
    if (srcb && tid < 32) {
        float s = sin_s[cbase+tid], q = sin_q[cbase+tid];
        float m = s*(1.f/NNT);
        sm[tid] = m;
        sr[tid] = rsqrtf(q*(1.f/NNT) - m*m + 1e-5f);
    }
    __syncthreads();
    float acc[32];
    #pragma unroll
    for (int o = 0; o < 32; ++o) acc[o] = bias[g*32+o];
    bool useb = (srcb != nullptr);
    #pragma unroll 8
    for (int i = 0; i < 32; ++i) {
        float v;
        if (useb) {
            v = __bfloat162float(srcb[(size_t)(cbase+i)*NNT + n]);
            v = (v - sm[i])*sr[i];
            v = v >= 0.f ? v : 0.01f*v;
        } else {
            v = srcf[(size_t)(cbase+i)*NNT + n];
        }
        #pragma unroll
        for (int o = 0; o < 32; ++o) acc[o] += v*ws[i*32+o];
    }
    #pragma unroll 4
    for (int o = 0; o < 32; ++o)
        dst[(size_t)(cbase+o)*NNT + n] = __float2bfloat16(acc[o]);
    #pragma unroll
    for (int o = 0; o < 32; ++o) sacc[o][tid] = acc[o];
    __syncthreads();
    #pragma unroll
    for (int k = 0; k < 4; ++k) {
        int ch = wid*4 + k;
        float s = 0.f, q = 0.f;
        #pragma unroll
        for (int j = 0; j < 8; ++j) {
            float v = sacc[ch][lane + 32*j];
            s += v; q += v*v;
        }
        #pragma unroll
        for (int o = 16; o; o >>= 1) {
            s += __shfl_xor_sync(0xffffffffu, s, o);
            q += __shfl_xor_sync(0xffffffffu, q, o);
        }
        if (lane == 0) {
            atomicAdd(&sout_s[cbase+ch], s);
            atomicAdd(&sout_q[cbase+ch], q);
        }
    }
}

// mega-fused: xc = lrelu(inorm(conv2)+x); +pos; LN both streams (warp/token);
// x_n fp32 -> d_out [c,n]; bf16 x_n/xc_n; pool partials (register-accumulated).
__global__ __launch_bounds__(256) void k_megaln(
    const float* __restrict__ x, const float* __restrict__ pos,
    const float* __restrict__ lg, const float* __restrict__ lb,
    const float* __restrict__ wp, float* __restrict__ dout)
{
    extern __shared__ float dsm[];
    float* xs  = dsm;                                  // 8448 f32
    float* stm = dsm + 8448;
    float* str = stm + 256;
    float* lgs = str + 256;
    float* lbs = lgs + 256;
    __nv_bfloat16* cs = (__nv_bfloat16*)(dsm + 9472);  // 8704 bf16
    int tid = threadIdx.x, tx = tid & 31, ty = tid >> 5;
    int lane = tid & 31, w = tid >> 5;
    int n0 = blockIdx.x*32, b = blockIdx.y;
    {
        float s = g_zero[ZOFF_CS2S + b*256 + tid];
        float q = g_zero[ZOFF_CS2Q + b*256 + tid];
        float m = s*(1.f/NNT);
        stm[tid] = m;
        str[tid] = rsqrtf(q*(1.f/NNT) - m*m + 1e-5f);
        lgs[tid] = lg[tid]; lbs[tid] = lb[tid];
    }
    __syncthreads();
    for (int cc = ty; cc < 256; cc += 8) {
        size_t s = (size_t)(b*CC + cc)*NNT + n0 + tx;
        float xv = x[s];
        float hv = (__bfloat162float(g_c2b[s]) - stm[cc])*str[cc] + xv;
        xs[cc*33 + tx] = xv;
        cs[cc*34 + tx] = __float2bfloat16(hv >= 0.f ? hv : 0.01f*hv);
    }
    __syncthreads();
    float pacc[8];
    #pragma unroll
    for (int j = 0; j < 8; ++j) pacc[j] = 0.f;
    for (int t8 = 0; t8 < 4; ++t8) {
        int tok = w + t8*8;
        const float* prow = pos + (size_t)(n0 + tok)*CC;
        float v1[8], v2[8];
        float s1 = 0.f, q1 = 0.f, s2 = 0.f, q2 = 0.f;
        #pragma unroll
        for (int j = 0; j < 8; ++j) {
            int c = lane + 32*j;
            float p = prow[c];
            float a  = xs[c*33 + tok] + p;
            float d2 = __bfloat162float(cs[c*34 + tok]) + p;
            v1[j] = a; v2[j] = d2;
            s1 += a; q1 += a*a; s2 += d2; q2 += d2*d2;
        }
        #pragma unroll
        for (int o = 16; o; o >>= 1) {
            s1 += __shfl_xor_sync(0xffffffffu, s1, o);
            q1 += __shfl_xor_sync(0xffffffffu, q1, o);
            s2 += __shfl_xor_sync(0xffffffffu, s2, o);
            q2 += __shfl_xor_sync(0xffffffffu, q2, o);
        }
        float m1 = s1*(1.f/CC), r1 = rsqrtf(q1*(1.f/CC) - m1*m1 + 1e-5f);
        float m2 = s2*(1.f/CC), r2 = rsqrtf(q2*(1.f/CC) - m2*m2 + 1e-5f);
        float wpt = wp[n0 + tok];
        size_t gbase = ((size_t)b*NNT + n0 + tok)*CC;
        #pragma unroll
        for (int j = 0; j < 8; ++j) {
            int c = lane + 32*j;
            float o1 = (v1[j] - m1)*r1*lgs[c] + lbs[c];
            float o2 = (v2[j] - m2)*r2*lgs[c] + lbs[c];
            g_xt_bf [gbase + c] = __float2bfloat16(o1);
            g_xct_bf[gbase + c] = __float2bfloat16(o2);
            xs[c*33 + tok] = o1;                 // x_n fp32 for output
            pacc[j] += o2*wpt;
        }
    }
    __syncthreads();
    float* pws = (float*)cs;
    #pragma unroll
    for (int j = 0; j < 8; ++j) pws[w*256 + lane + 32*j] = pacc[j];
    __syncthreads();
    {
        float s = 0.f;
        #pragma unroll
        for (int ww = 0; ww < 8; ++ww) s += pws[ww*256 + tid];
        atomicAdd(&g_zero[ZOFF_POOL + b*256 + tid], s);
    }
    for (int cc = ty; cc < 256; cc += 8)
        dout[(size_t)(b*CC + cc)*NNT + n0 + tx] = xs[cc*33 + tx];
}

__global__ void k_gate(const float* __restrict__ bp, const float* __restrict__ w1,
                       const float* __restrict__ w2)
{
    __shared__ float ps[256], hs[64];
    int b = blockIdx.x, t = threadIdx.x;
    ps[t] = g_zero[ZOFF_POOL + b*CC + t] + bp[0];
    __syncthreads();
    if (t < 64) {
        float a = 0.f;
        for (int c = 0; c < 256; ++c) a += ps[c]*w1[c*64 + t];
        hs[t] = fmaxf(a, 0.f);
    }
    __syncthreads();
    float a = 0.f;
    for (int j = 0; j < 64; ++j) a += hs[j]*w2[j*256 + t];
    g_gate[b*CC + t] = 1.f/(1.f + expf(-a));
}

// bf16 HMMA GEMM with cp.async double buffering.
// blockIdx.z==1 -> (A2,Bw2,bias2,coff=128,gated).
// If gfin != null: fused final epilogue  dout[b][coff+col][n] += gfin[c]*(acc+bias)
__global__ __launch_bounds__(256) void k_mma(
    const __nv_bfloat16* __restrict__ A, const __nv_bfloat16* __restrict__ A2,
    const __nv_bfloat16* __restrict__ Bw, const __nv_bfloat16* __restrict__ Bw2,
    const float* __restrict__ bias, const float* __restrict__ bias2,
    const float* __restrict__ gate,
    __nv_bfloat16* __restrict__ Cb, int Nld, int ldc, int doqss,
    float* __restrict__ dout, const float* __restrict__ gfin)
{
    __shared__ __align__(16) __nv_bfloat16 As[2][128][40];
    __shared__ __align__(16) __nv_bfloat16 Bs[2][32][136];
    int tid = threadIdx.x;
    int wid = tid >> 5, lane = tid & 31;
    int wm = wid >> 2;
    int wn = wid & 3;
    int m0 = blockIdx.y * 128;
    int n0 = blockIdx.x * 128;
    int coff = 0;
    const float* grow = nullptr;
    if (blockIdx.z == 1) {
        A = A2; Bw = Bw2; bias = bias2; coff = 128;
        grow = gate + (m0 / NNT)*CC;
    }

    float acc[4][4][4] = {};

    #pragma unroll
    for (int p = 0; p < 2; ++p) {
        int idx = p*256 + tid; int r = idx >> 2, sg = idx & 3;
        cpa16(&As[0][r][sg*8], A + (size_t)(m0 + r)*256 + sg*8);
    }
    #pragma unroll
    for (int p = 0; p < 2; ++p) {
        int idx = p*256 + tid; int r = idx >> 4, sg = idx & 15;
        cpa16(&Bs[0][r][sg*8], Bw + (size_t)r*Nld + n0 + sg*8);
    }
    cp_commit();

    for (int it = 0; it < 8; ++it) {
        int k0 = it*32, st = it & 1;
        if (it < 7) {
            int kn = k0 + 32, sn = st ^ 1;
            #pragma unroll
            for (int p = 0; p < 2; ++p) {
                int idx = p*256 + tid; int r = idx >> 2, sg = idx & 3;
                cpa16(&As[sn][r][sg*8], A + (size_t)(m0 + r)*256 + kn + sg*8);
            }
            #pragma unroll
            for (int p = 0; p < 2; ++p) {
                int idx = p*256 + tid; int r = idx >> 4, sg = idx & 15;
                cpa16(&Bs[sn][r][sg*8], Bw + (size_t)(kn + r)*Nld + n0 + sg*8);
            }
            cp_commit();
            cp_wait<1>();
        } else {
            cp_wait<0>();
        }
        __syncthreads();
        if (grow) {
            #pragma unroll
            for (int p = 0; p < 2; ++p) {
                int idx = p*256 + tid; int r = idx >> 2, sg = idx & 3;
                __nv_bfloat16* qp = &As[st][r][sg*8];
                #pragma unroll
                for (int j = 0; j < 8; ++j)
                    qp[j] = __float2bfloat16(__bfloat162float(qp[j])*grow[k0+sg*8+j]);
            }
            __syncthreads();
        }
        #pragma unroll
        for (int kk = 0; kk < 2; ++kk) {
            unsigned int af[4][4];
            #pragma unroll
            for (int mt = 0; mt < 4; ++mt)
                ldm_x4(af[mt], &As[st][wm*64 + mt*16 + (lane & 15)][kk*16 + (lane >> 4)*8]);
            unsigned int bfr[2][4];
            #pragma unroll
            for (int g2 = 0; g2 < 2; ++g2)
                ldm_x4_t(bfr[g2], &Bs[st][kk*16 + (lane & 15)][wn*32 + g2*16 + (lane >> 4)*8]);
            #pragma unroll
            for (int mt = 0; mt < 4; ++mt)
                #pragma unroll
                for (int nt = 0; nt < 4; ++nt)
                    mma16816(acc[mt][nt], af[mt],
                             bfr[nt>>1][(nt&1)*2], bfr[nt>>1][(nt&1)*2+1]);
        }
        __syncthreads();
    }
    if (doqss && n0 < 256) {
        int b = m0 / NNT;
        #pragma unroll
        for (int nt = 0; nt < 4; ++nt) {
            float s0 = 0.f, s1 = 0.f;
            #pragma unroll
            for (int mt = 0; mt < 4; ++mt) {
                #pragma unroll
                for (int h = 0; h < 2; ++h) {
                    float a0 = acc[mt][nt][h*2+0], a1 = acc[mt][nt][h*2+1];
                    s0 += a0*a0; s1 += a1*a1;
                }
            }
            #pragma unroll
            for (int o = 4; o <= 16; o <<= 1) {
                s0 += __shfl_xor_sync(0xffffffffu, s0, o);
                s1 += __shfl_xor_sync(0xffffffffu, s1, o);
            }
            if ((lane >> 2) == 0) {
                int col = n0 + wn*32 + nt*8 + (lane & 3)*2;
                atomicAdd(&g_zero[ZOFF_QSS + b*256 + col],   s0);
                atomicAdd(&g_zero[ZOFF_QSS + b*256 + col+1], s1);
            }
        }
    }
    if (gfin) {
        // fused residual epilogue: transpose 32-channel quarters via smem,
        // then coalesced float4 RMW into dout[b][coff+c][n].
        float* ts = (float*)As;               // 32 x 132 f32 overlay (16.9KB <= 20.5KB)
        const int TS = 132;
        int b = m0 / NNT;
        int n0t = m0 % NNT;
        #pragma unroll 1
        for (int q = 0; q < 4; ++q) {
            __syncthreads();
            if (wn == q) {
                #pragma unroll
                for (int mt = 0; mt < 4; ++mt) {
                    #pragma unroll
                    for (int nt = 0; nt < 4; ++nt) {
                        int ll = nt*8 + (lane & 3)*2;
                        float gm0 = gfin[coff + q*32 + ll];
                        float gm1 = gfin[coff + q*32 + ll + 1];
                        float b0 = bias[q*32 + ll], b1 = bias[q*32 + ll + 1];
                        #pragma unroll
                        for (int h = 0; h < 2; ++h) {
                            int rr = wm*64 + mt*16 + (lane >> 2) + h*8;
                            ts[ll*TS + rr]     = (acc[mt][nt][h*2+0] + b0)*gm0;
                            ts[(ll+1)*TS + rr] = (acc[mt][nt][h*2+1] + b1)*gm1;
                        }
                    }
                }
            }
            __syncthreads();
            // write: 8 warps x 4 channels each, 128 tokens per channel
            #pragma unroll
            for (int r = 0; r < 4; ++r) {
                int l2 = wid*4 + r;
                int c = coff + q*32 + l2;
                float* dp = dout + (size_t)(b*CC + c)*NNT + n0t;
                float4 dv = *(float4*)(dp + lane*4);
                dv.x += ts[l2*TS + lane*4 + 0];
                dv.y += ts[l2*TS + lane*4 + 1];
                dv.z += ts[l2*TS + lane*4 + 2];
                dv.w += ts[l2*TS + lane*4 + 3];
                *(float4*)(dp + lane*4) = dv;
            }
        }
        return;
    }
    #pragma unroll
    for (int mt = 0; mt < 4; ++mt) {
        int row0 = m0 + wm*64 + mt*16 + (lane >> 2);
        #pragma unroll
        for (int nt = 0; nt < 4; ++nt) {
            int col = wn*32 + nt*8 + (lane & 3)*2;
            #pragma unroll
            for (int h = 0; h < 2; ++h) {
                int r = row0 + h*8;
                float v0 = acc[mt][nt][h*2+0];
                float v1 = acc[mt][nt][h*2+1];
                if (bias) { v0 += bias[n0+col]; v1 += bias[n0+col+1]; }
                __nv_bfloat16* p = Cb + (size_t)r*ldc + coff + n0 + col;
                p[0] = __float2bfloat16(v0); p[1] = __float2bfloat16(v1);
            }
        }
    }
}

// K/V low-rank projection via tensor cores; split-N=54 for occupancy
__global__ __launch_bounds__(256) void k_kvmma()
{
    int b = blockIdx.x >> 1, which = blockIdx.x & 1;
    int n0 = blockIdx.y * 256;
    int coff = 256*(which+1);
    __shared__ __align__(16) __nv_bfloat16 Ks[32][264];
    __shared__ __align__(16) __nv_bfloat16 Es[32][72];
    int tid = threadIdx.x, lane = tid & 31, wid = tid >> 5;
    int m0w = wid*32;
    float acc[2][8][4] = {};

    for (int c = 0; c < 8; ++c) {
        int nt0 = n0 + c*32;
        #pragma unroll
        for (int v = 0; v < 4; ++v) {
            int idx = v*256 + tid; int r = idx >> 5, sg = idx & 31;
            *(uint4*)&Ks[r][sg*8] =
                *(const uint4*)(g_qkv_bf + ((size_t)(b*NNT + nt0 + r))*768 + coff + sg*8);
        }
        {
            int r = tid >> 3, sg = tid & 7;
            *(uint4*)&Es[r][sg*8] = *(const uint4*)(g_we_bf + (size_t)(nt0 + r)*64 + sg*8);
        }
        __syncthreads();
        #pragma unroll
        for (int kk = 0; kk < 32; kk += 16) {
            unsigned int af[2][4];
            #pragma unroll
            for (int mt = 0; mt < 2; ++mt)
                ldm_x4_t(af[mt], &Ks[kk + (lane & 7) + ((lane >> 4) << 3)]
                                    [m0w + mt*16 + ((lane >> 3) & 1)*8]);
            unsigned int bfr[4][4];
            #pragma unroll
            for (int ng = 0; ng < 4; ++ng)
                ldm_x4_t(bfr[ng], &Es[kk + (lane & 15)][ng*16 + (lane >> 4)*8]);
            #pragma unroll
            for (int mt = 0; mt < 2; ++mt)
                #pragma unroll
                for (int nt = 0; nt < 8; ++nt)
                    mma16816(acc[mt][nt], af[mt],
                             bfr[nt>>1][(nt&1)*2], bfr[nt>>1][(nt&1)*2+1]);
        }
        __syncthreads();
    }
    float* out = &g_zero[ZOFF_KP + which*32768 + b*16384];
    #pragma unroll
    for (int mt = 0; mt < 2; ++mt) {
        int m = m0w + mt*16 + (lane >> 2);
        #pragma unroll
        for (int nt = 0; nt < 8; ++nt) {
            int p = nt*8 + (lane & 3)*2;
            atomicAdd(&out[m*64 + p],       acc[mt][nt][0]);
            atomicAdd(&out[m*64 + p + 1],   acc[mt][nt][1]);
            atomicAdd(&out[(m+8)*64 + p],   acc[mt][nt][2]);
            atomicAdd(&out[(m+8)*64 + p+1], acc[mt][nt][3]);
        }
    }
}

// fused attention tile (HMMA both GEMMs), scrambled bf16 store
__global__ __launch_bounds__(256) void k_attn(const float* __restrict__ be,
                                              const float* __restrict__ temp)
{
    int bh = blockIdx.y; int b = bh >> 2, h = bh & 3;
    int n0 = blockIdx.x*64;
    __shared__ __align__(16) __nv_bfloat16 sA[64][72];
    __shared__ __align__(16) __nv_bfloat16 sB[64][72];
    __shared__ float ss[64][68];
    __shared__ float qr[64];
    int tid = threadIdx.x;
    int wid = tid >> 5, lane = tid & 31;
    int wm = wid & 1, wn = wid >> 1;
    const float* kbase = &g_zero[ZOFF_KP + bh*4096];
    const float* vbase = &g_zero[ZOFF_VP + bh*4096];

    if (tid < 64)
        qr[tid] = 1.f / fmaxf(sqrtf(g_zero[ZOFF_QSS + b*256 + h*64 + tid]), 1e-12f);
    #pragma unroll
    for (int v = 0; v < 4; ++v) {
        int i4 = v*256 + tid; int d = i4 >> 4, pp = (i4 & 15)*4;
        float4 kv = *(const float4*)(kbase + d*64 + pp);
        sB[d][pp]   = __float2bfloat16(kv.x + be[pp]);
        sB[d][pp+1] = __float2bfloat16(kv.y + be[pp+1]);
        sB[d][pp+2] = __float2bfloat16(kv.z + be[pp+2]);
        sB[d][pp+3] = __float2bfloat16(kv.w + be[pp+3]);
    }
    __syncthreads();
    #pragma unroll
    for (int l = 0; l < 2; ++l) {
        int i8 = l*256 + tid; int r = i8 >> 3, sg = (i8 & 7)*8;
        uint4 v = *(const uint4*)(g_qkv_bf + ((size_t)(b*NNT + n0 + r))*768 + h*64 + sg);
        const __nv_bfloat162* hh = (const __nv_bfloat162*)&v;
        __nv_bfloat16 outv[8];
        #pragma unroll
        for (int j = 0; j < 4; ++j) {
            float2 f = __bfloat1622float2(hh[j]);
            outv[j*2]   = __float2bfloat16(f.x * qr[sg + j*2]);
            outv[j*2+1] = __float2bfloat16(f.y * qr[sg + j*2+1]);
        }
        *(uint4*)&sA[r][sg] = *(uint4*)outv;
    }
    __syncthreads();
    float acc1[2][2][4] = {};
    #pragma unroll
    for (int kk = 0; kk < 64; kk += 16) {
        unsigned int af[2][4];
        #pragma unroll
        for (int mt = 0; mt < 2; ++mt)
            ldm_x4(af[mt], &sA[wm*32 + mt*16 + (lane & 15)][kk + (lane >> 4)*8]);
        unsigned int bfr[4];
        ldm_x4_t(bfr, &sB[kk + (lane & 15)][wn*16 + (lane >> 4)*8]);
        #pragma unroll
        for (int mt = 0; mt < 2; ++mt)
            #pragma unroll
            for (int nt = 0; nt < 2; ++nt)
                mma16816(acc1[mt][nt], af[mt], bfr[nt*2], bfr[nt*2+1]);
    }
    float ts = temp[h];
    #pragma unroll
    for (int mt = 0; mt < 2; ++mt) {
        int r = wm*32 + mt*16 + (lane >> 2);
        #pragma unroll
        for (int nt = 0; nt < 2; ++nt) {
            int c = wn*16 + nt*8 + (lane & 3)*2;
            ss[r][c]     = acc1[mt][nt][0]*ts;
            ss[r][c+1]   = acc1[mt][nt][1]*ts;
            ss[r+8][c]   = acc1[mt][nt][2]*ts;
            ss[r+8][c+1] = acc1[mt][nt][3]*ts;
        }
    }
    __syncthreads();
    #pragma unroll
    for (int v = 0; v < 4; ++v) {
        int i4 = v*256 + tid; int d = i4 >> 4, pp = (i4 & 15)*4;
        float4 vv = *(const float4*)(vbase + d*64 + pp);
        sA[d][pp]   = __float2bfloat16(vv.x + be[pp]);
        sA[d][pp+1] = __float2bfloat16(vv.y + be[pp+1]);
        sA[d][pp+2] = __float2bfloat16(vv.z + be[pp+2]);
        sA[d][pp+3] = __float2bfloat16(vv.w + be[pp+3]);
    }
    {
        int row = tid >> 2, g4 = (tid & 3)*16;
        float e[16];
        float mx = -1e30f;
        #pragma unroll
        for (int p = 0; p < 16; ++p) { e[p] = ss[row][g4+p]; mx = fmaxf(mx, e[p]); }
        mx = fmaxf(mx, __shfl_xor_sync(0xffffffffu, mx, 1));
        mx = fmaxf(mx, __shfl_xor_sync(0xffffffffu, mx, 2));
        float sum = 0.f;
        #pragma unroll
        for (int p = 0; p < 16; ++p) { e[p] = __expf(e[p] - mx); sum += e[p]; }
        sum += __shfl_xor_sync(0xffffffffu, sum, 1);
        sum += __shfl_xor_sync(0xffffffffu, sum, 2);
        float inv = 1.f/sum;
        #pragma unroll
        for (int p = 0; p < 16; ++p)
            sB[g4+p][row] = __float2bfloat16(e[p]*inv);
    }
    __syncthreads();
    float acc2[2][2][4] = {};
    #pragma unroll
    for (int kk = 0; kk < 64; kk += 16) {
        unsigned int af[2][4];
        #pragma unroll
        for (int mt = 0; mt < 2; ++mt)
            ldm_x4(af[mt], &sA[wm*32 + mt*16 + (lane & 15)][kk + (lane >> 4)*8]);
        unsigned int bfr[4];
        ldm_x4_t(bfr, &sB[kk + (lane & 15)][wn*16 + (lane >> 4)*8]);
        #pragma unroll
        for (int mt = 0; mt < 2; ++mt)
            #pragma unroll
            for (int nt = 0; nt < 2; ++nt)
                mma16816(acc2[mt][nt], af[mt], bfr[nt*2], bfr[nt*2+1]);
    }
    __nv_bfloat16* sabase = g_sa_bf + (size_t)b*NNT*CC;
    #pragma unroll
    for (int mt = 0; mt < 2; ++mt) {
        int d0 = wm*32 + mt*16 + (lane >> 2);
        #pragma unroll
        for (int nt = 0; nt < 2; ++nt) {
            int nc = n0 + wn*16 + nt*8 + (lane & 3)*2;
            *(__nv_bfloat162*)&sabase[(size_t)(d0*4 + h)*NNT + nc] =
                __floats2bfloat162_rn(acc2[mt][nt][0], acc2[mt][nt][1]);
            *(__nv_bfloat162*)&sabase[(size_t)((d0+8)*4 + h)*NNT + nc] =
                __floats2bfloat162_rn(acc2[mt][nt][2], acc2[mt][nt][3]);
        }
    }
}

// ---------------- launch ----------------
extern "C" void kernel_launch(void* const* d_in, const int* in_sizes, int n_in,
                              void* d_out, int out_size)
{
    const float* x      = (const float*)d_in[0];
    const float* pos    = (const float*)d_in[1];
    const float* ln_g   = (const float*)d_in[2];
    const float* ln_b   = (const float*)d_in[3];
    const float* gamma  = (const float*)d_in[4];
    const float* temp2  = (const float*)d_in[5];
    const float* w_qkv  = (const float*)d_in[6];
    const float* w_e    = (const float*)d_in[7];
    const float* b_e    = (const float*)d_in[8];
    const float* w_pool = (const float*)d_in[9];
    const float* b_pool = (const float*)d_in[10];
    const float* w_fc1  = (const float*)d_in[11];
    const float* w_fc2  = (const float*)d_in[12];
    const float* b_out1 = (const float*)d_in[14];
    const float* b_out2 = (const float*)d_in[16];
    const float* w_c1   = (const float*)d_in[17];
    const float* b_c1   = (const float*)d_in[18];
    const float* w_c2   = (const float*)d_in[19];
    const float* b_c2   = (const float*)d_in[20];

    __nv_bfloat16 *p_h1b, *p_c2b, *p_xtbf, *p_xctbf, *p_sabf;
    __nv_bfloat16 *p_wq, *p_w1, *p_w2, *p_qkvbf;
    float *p_gate, *p_zero;
    cudaGetSymbolAddress((void**)&p_h1b,   g_h1b);
    cudaGetSymbolAddress((void**)&p_c2b,   g_c2b);
    cudaGetSymbolAddress((void**)&p_xtbf,  g_xt_bf);
    cudaGetSymbolAddress((void**)&p_xctbf, g_xct_bf);
    cudaGetSymbolAddress((void**)&p_qkvbf, g_qkv_bf);
    cudaGetSymbolAddress((void**)&p_sabf,  g_sa_bf);
    cudaGetSymbolAddress((void**)&p_wq,    g_wqkv_bf);
    cudaGetSymbolAddress((void**)&p_w1,    g_wo1_bf);
    cudaGetSymbolAddress((void**)&p_w2,    g_wo2_bf);
    cudaGetSymbolAddress((void**)&p_gate,  g_gate);
    cudaGetSymbolAddress((void**)&p_zero,  g_zero);

    static int s_attr_done = 0;
    if (!s_attr_done) {
        cudaFuncSetAttribute(k_megaln,
            cudaFuncAttributeMaxDynamicSharedMemorySize, 55296);
        s_attr_done = 1;
    }

    k_init <<<3456, 256>>>(w_qkv, (const float*)d_in[13],
                           (const float*)d_in[15], w_e);
    // MHCResBlock with fused stats
    k_conv <<<dim3(54,16), 256>>>(x, (const __nv_bfloat16*)0, w_c1, b_c1, p_h1b,
                                  (const float*)0, (const float*)0,
                                  p_zero + ZOFF_CS1S, p_zero + ZOFF_CS1Q);
    k_conv <<<dim3(54,16), 256>>>((const float*)0, p_h1b, w_c2, b_c2, p_c2b,
                                  p_zero + ZOFF_CS1S, p_zero + ZOFF_CS1Q,
                                  p_zero + ZOFF_CS2S, p_zero + ZOFF_CS2Q);
    // mega-fused transpose + xc + double-LN + pool + d_out(x_n)
    k_megaln<<<dim3(432, BB), 256, 55296>>>(x, pos, ln_g, ln_b, w_pool,
                                            (float*)d_out);
    // channel-attention gate
    k_gate <<<BB, 256>>>(b_pool, w_fc1, w_fc2);
    // qkv (pipelined bf16 HMMA + fused q sum-squares)
    k_mma  <<<dim3(6,216,1), 256>>>(p_xtbf, (const __nv_bfloat16*)0, p_wq,
                                    (const __nv_bfloat16*)0, (const float*)0,
                                    (const float*)0, (const float*)0,
                                    p_qkvbf, 768, 768, 1,
                                    (float*)0, (const float*)0);
    // low-rank K/V projection (split-N = 54)
    k_kvmma<<<dim3(4,54), 256>>>();
    // spatial attention
    k_attn <<<dim3(216, BB*NHH), 256>>>(b_e, temp2);
    // both output projections with fused gamma-residual into d_out
    k_mma  <<<dim3(1,216,2), 256>>>(p_sabf, p_xctbf, p_w1, p_w2,
                                    b_out1, b_out2, p_gate,
                                    (__nv_bfloat16*)0, 128, 256, 0,
                                    (float*)d_out, gamma);
}

// round 10
// speedup vs baseline: 3.2853x; 1.0451x over previous
#include <cuda_runtime.h>
#include <cuda_bf16.h>
#include <cstdint>
#include <math.h>

#define BB 2
#define CC 256
#define NNT 13824
#define NHH 4
#define MTOT (BB*NNT)

// ---------------- scratch ----------------
__device__ __nv_bfloat16 g_h1b[BB*CC*NNT];            // conv1 out
__device__ __nv_bfloat16 g_c2b[BB*CC*NNT];            // conv2 raw out
__device__ __nv_bfloat16 g_xt_bf [BB*NNT*CC];         // x_n bf16 (qkv A)
__device__ __nv_bfloat16 g_xct_bf[BB*NNT*CC];         // xc_n bf16
__device__ __nv_bfloat16 g_qkv_bf[(size_t)BB*NNT*768];
__device__ __nv_bfloat16 g_sa_bf [BB*NNT*CC];         // scrambled x_SA
__device__ __nv_bfloat16 g_wqkv_bf[256*768];
__device__ __nv_bfloat16 g_wo1_bf [256*128];
__device__ __nv_bfloat16 g_wo2_bf [256*128];
__device__ __nv_bfloat16 g_we_bf  [NNT*64];
#define ZOFF_POOL 0
#define ZOFF_QSS  512
#define ZOFF_CS1S 1024
#define ZOFF_CS1Q 1536
#define ZOFF_CS2S 2048
#define ZOFF_CS2Q 2560
#define ZOFF_KP   3072
#define ZOFF_VP   35840
#define ZTOT      68608
__device__ float g_zero[ZTOT];
__device__ float g_gate[BB*CC];

// ---------------- asm helpers ----------------
__device__ __forceinline__ void ldm_x4(unsigned int (&r)[4], const void* p) {
    unsigned int a = (unsigned int)__cvta_generic_to_shared(p);
    asm volatile("ldmatrix.sync.aligned.m8n8.x4.shared.b16 {%0,%1,%2,%3}, [%4];"
        : "=r"(r[0]),"=r"(r[1]),"=r"(r[2]),"=r"(r[3]) : "r"(a));
}
__device__ __forceinline__ void ldm_x4_t(unsigned int (&r)[4], const void* p) {
    unsigned int a = (unsigned int)__cvta_generic_to_shared(p);
    asm volatile("ldmatrix.sync.aligned.m8n8.x4.trans.shared.b16 {%0,%1,%2,%3}, [%4];"
        : "=r"(r[0]),"=r"(r[1]),"=r"(r[2]),"=r"(r[3]) : "r"(a));
}
__device__ __forceinline__ void mma16816(float (&d)[4], const unsigned int (&a)[4],
                                         unsigned int b0, unsigned int b1) {
    asm volatile("mma.sync.aligned.m16n8k16.row.col.f32.bf16.bf16.f32 "
        "{%0,%1,%2,%3},{%4,%5,%6,%7},{%8,%9},{%0,%1,%2,%3};"
        : "+f"(d[0]),"+f"(d[1]),"+f"(d[2]),"+f"(d[3])
        : "r"(a[0]),"r"(a[1]),"r"(a[2]),"r"(a[3]),"r"(b0),"r"(b1));
}
__device__ __forceinline__ void cpa16(void* dst, const void* src) {
    unsigned int d = (unsigned int)__cvta_generic_to_shared(dst);
    asm volatile("cp.async.cg.shared.global [%0], [%1], 16;" :: "r"(d), "l"(src));
}
__device__ __forceinline__ void cp_commit() { asm volatile("cp.async.commit_group;"); }
template<int N> __device__ __forceinline__ void cp_wait() {
    asm volatile("cp.async.wait_group %0;" :: "n"(N));
}

// ---------------- kernels ----------------
__global__ void k_init(const float* __restrict__ wq, const float* __restrict__ w1,
                       const float* __restrict__ w2, const float* __restrict__ we)
{
    int i = blockIdx.x*256 + threadIdx.x;
    if (i < ZTOT) g_zero[i] = 0.f;
    if (i < 196608) g_wqkv_bf[i] = __float2bfloat16(wq[i]);
    if (i < 32768)  { g_wo1_bf[i] = __float2bfloat16(w1[i]);
                      g_wo2_bf[i] = __float2bfloat16(w2[i]); }
    if (i < NNT*64) g_we_bf[i] = __float2bfloat16(we[i]);
}

// grouped 1x1x1 conv; conv2 normalizes+lrelu's its input from (sum,ssq);
// both emit per-channel (sum, sumsq) of their fp32 outputs via atomics.
__global__ __launch_bounds__(256) void k_conv(
    const float* __restrict__ srcf, const __nv_bfloat16* __restrict__ srcb,
    const float* __restrict__ w, const float* __restrict__ bias,
    __nv_bfloat16* __restrict__ dst,
    const float* __restrict__ sin_s, const float* __restrict__ sin_q,
    float* __restrict__ sout_s, float* __restrict__ sout_q)
{
    int bg = blockIdx.y; int b = bg >> 3; int g = bg & 7;
    int n  = blockIdx.x*256 + threadIdx.x;
    int tid = threadIdx.x, lane = tid & 31, wid = tid >> 5;
    __shared__ float ws[1024];
    __shared__ float sm[32], sr[32];
    __shared__ float sacc[32][257];
    int cbase = b*CC + g*32;
    for (int i = tid; i < 1024; i += 256) ws[i] = w[g*1024 + i];
    if (srcb && tid < 32) {
        float s = sin_s[cbase+tid], q = sin_q[cbase+tid];
        float m = s*(1.f/NNT);
        sm[tid] = m;
        sr[tid] = rsqrtf(q*(1.f/NNT) - m*m + 1e-5f);
    }
    __syncthreads();
    float acc[32];
    #pragma unroll
    for (int o = 0; o < 32; ++o) acc[o] = bias[g*32+o];
    bool useb = (srcb != nullptr);
    #pragma unroll 16
    for (int i = 0; i < 32; ++i) {
        float v;
        if (useb) {
            v = __bfloat162float(srcb[(size_t)(cbase+i)*NNT + n]);
            v = (v - sm[i])*sr[i];
            v = v >= 0.f ? v : 0.01f*v;
        } else {
            v = srcf[(size_t)(cbase+i)*NNT + n];
        }
        #pragma unroll
        for (int o = 0; o < 32; ++o) acc[o] += v*ws[i*32+o];
    }
    #pragma unroll 4
    for (int o = 0; o < 32; ++o)
        dst[(size_t)(cbase+o)*NNT + n] = __float2bfloat16(acc[o]);
    #pragma unroll
    for (int o = 0; o < 32; ++o) sacc[o][tid] = acc[o];
    __syncthreads();
    #pragma unroll
    for (int k = 0; k < 4; ++k) {
        int ch = wid*4 + k;
        float s = 0.f, q = 0.f;
        #pragma unroll
        for (int j = 0; j < 8; ++j) {
            float v = sacc[ch][lane + 32*j];
            s += v; q += v*v;
        }
        #pragma unroll
        for (int o = 16; o; o >>= 1) {
            s += __shfl_xor_sync(0xffffffffu, s, o);
            q += __shfl_xor_sync(0xffffffffu, q, o);
        }
        if (lane == 0) {
            atomicAdd(&sout_s[cbase+ch], s);
            atomicAdd(&sout_q[cbase+ch], q);
        }
    }
}

// mega-fused: xc = lrelu(inorm(conv2)+x); +pos; LN both streams (warp/token);
// x_n fp32 -> d_out [c,n]; bf16x2 stores; pool partials register-accumulated.
__global__ __launch_bounds__(256) void k_megaln(
    const float* __restrict__ x, const float* __restrict__ pos,
    const float* __restrict__ lg, const float* __restrict__ lb,
    const float* __restrict__ wp, float* __restrict__ dout)
{
    extern __shared__ float dsm[];
    float* xs  = dsm;                                  // 8448 f32
    float* stm = dsm + 8448;
    float* str = stm + 256;
    float* lgs = str + 256;
    float* lbs = lgs + 256;
    __nv_bfloat16* cs = (__nv_bfloat16*)(dsm + 9472);  // 8704 bf16
    int tid = threadIdx.x, tx = tid & 31, ty = tid >> 5;
    int lane = tid & 31, w = tid >> 5;
    int n0 = blockIdx.x*32, b = blockIdx.y;
    {
        float s = g_zero[ZOFF_CS2S + b*256 + tid];
        float q = g_zero[ZOFF_CS2Q + b*256 + tid];
        float m = s*(1.f/NNT);
        stm[tid] = m;
        str[tid] = rsqrtf(q*(1.f/NNT) - m*m + 1e-5f);
        lgs[tid] = lg[tid]; lbs[tid] = lb[tid];
    }
    __syncthreads();
    for (int cc = ty; cc < 256; cc += 8) {
        size_t s = (size_t)(b*CC + cc)*NNT + n0 + tx;
        float xv = x[s];
        float hv = (__bfloat162float(g_c2b[s]) - stm[cc])*str[cc] + xv;
        xs[cc*33 + tx] = xv;
        cs[cc*34 + tx] = __float2bfloat16(hv >= 0.f ? hv : 0.01f*hv);
    }
    __syncthreads();
    float pacc[8];
    #pragma unroll
    for (int j = 0; j < 8; ++j) pacc[j] = 0.f;
    for (int t8 = 0; t8 < 4; ++t8) {
        int tok = w + t8*8;
        const float* prow = pos + (size_t)(n0 + tok)*CC;
        float v1[8], v2[8];
        float s1 = 0.f, q1 = 0.f, s2 = 0.f, q2 = 0.f;
        #pragma unroll
        for (int q = 0; q < 4; ++q) {
            int c0 = lane*2 + q*64;
            float2 p2 = *(const float2*)(prow + c0);
            float ax = xs[c0*33 + tok] + p2.x;
            float ay = xs[(c0+1)*33 + tok] + p2.y;
            float dx = __bfloat162float(cs[c0*34 + tok]) + p2.x;
            float dy = __bfloat162float(cs[(c0+1)*34 + tok]) + p2.y;
            v1[q*2] = ax; v1[q*2+1] = ay;
            v2[q*2] = dx; v2[q*2+1] = dy;
            s1 += ax + ay; q1 += ax*ax + ay*ay;
            s2 += dx + dy; q2 += dx*dx + dy*dy;
        }
        #pragma unroll
        for (int o = 16; o; o >>= 1) {
            s1 += __shfl_xor_sync(0xffffffffu, s1, o);
            q1 += __shfl_xor_sync(0xffffffffu, q1, o);
            s2 += __shfl_xor_sync(0xffffffffu, s2, o);
            q2 += __shfl_xor_sync(0xffffffffu, q2, o);
        }
        float m1 = s1*(1.f/CC), r1 = rsqrtf(q1*(1.f/CC) - m1*m1 + 1e-5f);
        float m2 = s2*(1.f/CC), r2 = rsqrtf(q2*(1.f/CC) - m2*m2 + 1e-5f);
        float wpt = wp[n0 + tok];
        size_t gbase = ((size_t)b*NNT + n0 + tok)*CC;
        #pragma unroll
        for (int q = 0; q < 4; ++q) {
            int c0 = lane*2 + q*64;
            float o1x = (v1[q*2]   - m1)*r1*lgs[c0]   + lbs[c0];
            float o1y = (v1[q*2+1] - m1)*r1*lgs[c0+1] + lbs[c0+1];
            float o2x = (v2[q*2]   - m2)*r2*lgs[c0]   + lbs[c0];
            float o2y = (v2[q*2+1] - m2)*r2*lgs[c0+1] + lbs[c0+1];
            *(__nv_bfloat162*)&g_xt_bf [gbase + c0] = __floats2bfloat162_rn(o1x, o1y);
            *(__nv_bfloat162*)&g_xct_bf[gbase + c0] = __floats2bfloat162_rn(o2x, o2y);
            xs[c0*33 + tok]     = o1x;
            xs[(c0+1)*33 + tok] = o1y;
            pacc[q*2]   += o2x*wpt;
            pacc[q*2+1] += o2y*wpt;
        }
    }
    __syncthreads();
    float* pws = (float*)cs;
    #pragma unroll
    for (int q = 0; q < 4; ++q) {
        int c0 = lane*2 + q*64;
        *(float2*)&pws[w*256 + c0] = make_float2(pacc[q*2], pacc[q*2+1]);
    }
    __syncthreads();
    {
        float s = 0.f;
        #pragma unroll
        for (int ww = 0; ww < 8; ++ww) s += pws[ww*256 + tid];
        atomicAdd(&g_zero[ZOFF_POOL + b*256 + tid], s);
    }
    for (int cc = ty; cc < 256; cc += 8)
        dout[(size_t)(b*CC + cc)*NNT + n0 + tx] = xs[cc*33 + tx];
}

__global__ void k_gate(const float* __restrict__ bp, const float* __restrict__ w1,
                       const float* __restrict__ w2)
{
    __shared__ float ps[256], hs[64];
    int b = blockIdx.x, t = threadIdx.x;
    ps[t] = g_zero[ZOFF_POOL + b*CC + t] + bp[0];
    __syncthreads();
    if (t < 64) {
        float a = 0.f;
        for (int c = 0; c < 256; ++c) a += ps[c]*w1[c*64 + t];
        hs[t] = fmaxf(a, 0.f);
    }
    __syncthreads();
    float a = 0.f;
    for (int j = 0; j < 64; ++j) a += hs[j]*w2[j*256 + t];
    g_gate[b*CC + t] = 1.f/(1.f + expf(-a));
}

// bf16 HMMA GEMM, K=64 chunks, cp.async double buffering, dynamic smem.
// dyn smem: As[2][128][72] then Bs[2][64][136] (bf16 elements)
#define AS_(st,r,c) smem_mma[(size_t)(st)*9216 + (r)*72 + (c)]
#define BS_(st,r,c) smem_mma[18432 + (size_t)(st)*8704 + (r)*136 + (c)]
__global__ __launch_bounds__(256) void k_mma(
    const __nv_bfloat16* __restrict__ A, const __nv_bfloat16* __restrict__ A2,
    const __nv_bfloat16* __restrict__ Bw, const __nv_bfloat16* __restrict__ Bw2,
    const float* __restrict__ bias, const float* __restrict__ bias2,
    const float* __restrict__ gate,
    __nv_bfloat16* __restrict__ Cb, int Nld, int ldc, int doqss,
    float* __restrict__ dout, const float* __restrict__ gfin)
{
    extern __shared__ __nv_bfloat16 smem_mma[];
    int tid = threadIdx.x;
    int wid = tid >> 5, lane = tid & 31;
    int wm = wid >> 2;
    int wn = wid & 3;
    int m0 = blockIdx.y * 128;
    int n0 = blockIdx.x * 128;
    int coff = 0;
    const float* grow = nullptr;
    if (blockIdx.z == 1) {
        A = A2; Bw = Bw2; bias = bias2; coff = 128;
        grow = gate + (m0 / NNT)*CC;
    }

    float acc[4][4][4] = {};

    #pragma unroll
    for (int p = 0; p < 4; ++p) {
        int idx = p*256 + tid; int r = idx >> 3, sg = idx & 7;
        cpa16(&AS_(0, r, sg*8), A + (size_t)(m0 + r)*256 + sg*8);
    }
    #pragma unroll
    for (int p = 0; p < 4; ++p) {
        int idx = p*256 + tid; int r = idx >> 4, sg = idx & 15;
        cpa16(&BS_(0, r, sg*8), Bw + (size_t)r*Nld + n0 + sg*8);
    }
    cp_commit();

    for (int it = 0; it < 4; ++it) {
        int k0 = it*64, st = it & 1;
        if (it < 3) {
            int kn = k0 + 64, sn = st ^ 1;
            #pragma unroll
            for (int p = 0; p < 4; ++p) {
                int idx = p*256 + tid; int r = idx >> 3, sg = idx & 7;
                cpa16(&AS_(sn, r, sg*8), A + (size_t)(m0 + r)*256 + kn + sg*8);
            }
            #pragma unroll
            for (int p = 0; p < 4; ++p) {
                int idx = p*256 + tid; int r = idx >> 4, sg = idx & 15;
                cpa16(&BS_(sn, r, sg*8), Bw + (size_t)(kn + r)*Nld + n0 + sg*8);
            }
            cp_commit();
            cp_wait<1>();
        } else {
            cp_wait<0>();
        }
        __syncthreads();
        if (grow) {
            #pragma unroll
            for (int p = 0; p < 4; ++p) {
                int idx = p*256 + tid; int r = idx >> 3, sg = idx & 7;
                __nv_bfloat16* qp = &AS_(st, r, sg*8);
                #pragma unroll
                for (int j = 0; j < 8; ++j)
                    qp[j] = __float2bfloat16(__bfloat162float(qp[j])*grow[k0+sg*8+j]);
            }
            __syncthreads();
        }
        #pragma unroll
        for (int kk = 0; kk < 4; ++kk) {
            unsigned int af[4][4];
            #pragma unroll
            for (int mt = 0; mt < 4; ++mt)
                ldm_x4(af[mt], &AS_(st, wm*64 + mt*16 + (lane & 15), kk*16 + (lane >> 4)*8));
            unsigned int bfr[2][4];
            #pragma unroll
            for (int g2 = 0; g2 < 2; ++g2)
                ldm_x4_t(bfr[g2], &BS_(st, kk*16 + (lane & 15), wn*32 + g2*16 + (lane >> 4)*8));
            #pragma unroll
            for (int mt = 0; mt < 4; ++mt)
                #pragma unroll
                for (int nt = 0; nt < 4; ++nt)
                    mma16816(acc[mt][nt], af[mt],
                             bfr[nt>>1][(nt&1)*2], bfr[nt>>1][(nt&1)*2+1]);
        }
        __syncthreads();
    }
    if (doqss && n0 < 256) {
        int b = m0 / NNT;
        #pragma unroll
        for (int nt = 0; nt < 4; ++nt) {
            float s0 = 0.f, s1 = 0.f;
            #pragma unroll
            for (int mt = 0; mt < 4; ++mt) {
                #pragma unroll
                for (int h = 0; h < 2; ++h) {
                    float a0 = acc[mt][nt][h*2+0], a1 = acc[mt][nt][h*2+1];
                    s0 += a0*a0; s1 += a1*a1;
                }
            }
            #pragma unroll
            for (int o = 4; o <= 16; o <<= 1) {
                s0 += __shfl_xor_sync(0xffffffffu, s0, o);
                s1 += __shfl_xor_sync(0xffffffffu, s1, o);
            }
            if ((lane >> 2) == 0) {
                int col = n0 + wn*32 + nt*8 + (lane & 3)*2;
                atomicAdd(&g_zero[ZOFF_QSS + b*256 + col],   s0);
                atomicAdd(&g_zero[ZOFF_QSS + b*256 + col+1], s1);
            }
        }
    }
    if (gfin) {
        float* ts = (float*)smem_mma;         // 32 x 132 f32 overlay
        const int TS = 132;
        int b = m0 / NNT;
        int n0t = m0 % NNT;
        #pragma unroll 1
        for (int q = 0; q < 4; ++q) {
            __syncthreads();
            if (wn == q) {
                #pragma unroll
                for (int mt = 0; mt < 4; ++mt) {
                    #pragma unroll
                    for (int nt = 0; nt < 4; ++nt) {
                        int ll = nt*8 + (lane & 3)*2;
                        float gm0 = gfin[coff + q*32 + ll];
                        float gm1 = gfin[coff + q*32 + ll + 1];
                        float b0 = bias[q*32 + ll], b1 = bias[q*32 + ll + 1];
                        #pragma unroll
                        for (int h = 0; h < 2; ++h) {
                            int rr = wm*64 + mt*16 + (lane >> 2) + h*8;
                            ts[ll*TS + rr]     = (acc[mt][nt][h*2+0] + b0)*gm0;
                            ts[(ll+1)*TS + rr] = (acc[mt][nt][h*2+1] + b1)*gm1;
                        }
                    }
                }
            }
            __syncthreads();
            #pragma unroll
            for (int r = 0; r < 4; ++r) {
                int l2 = wid*4 + r;
                int c = coff + q*32 + l2;
                float* dp = dout + (size_t)(b*CC + c)*NNT + n0t;
                float4 dv = *(float4*)(dp + lane*4);
                dv.x += ts[l2*TS + lane*4 + 0];
                dv.y += ts[l2*TS + lane*4 + 1];
                dv.z += ts[l2*TS + lane*4 + 2];
                dv.w += ts[l2*TS + lane*4 + 3];
                *(float4*)(dp + lane*4) = dv;
            }
        }
        return;
    }
    #pragma unroll
    for (int mt = 0; mt < 4; ++mt) {
        int row0 = m0 + wm*64 + mt*16 + (lane >> 2);
        #pragma unroll
        for (int nt = 0; nt < 4; ++nt) {
            int col = wn*32 + nt*8 + (lane & 3)*2;
            #pragma unroll
            for (int h = 0; h < 2; ++h) {
                int r = row0 + h*8;
                float v0 = acc[mt][nt][h*2+0];
                float v1 = acc[mt][nt][h*2+1];
                if (bias) { v0 += bias[n0+col]; v1 += bias[n0+col+1]; }
                __nv_bfloat16* p = Cb + (size_t)r*ldc + coff + n0 + col;
                p[0] = __float2bfloat16(v0); p[1] = __float2bfloat16(v1);
            }
        }
    }
}

// K/V low-rank projection via tensor cores; split-N=54 for occupancy
__global__ __launch_bounds__(256) void k_kvmma()
{
    int b = blockIdx.x >> 1, which = blockIdx.x & 1;
    int n0 = blockIdx.y * 256;
    int coff = 256*(which+1);
    __shared__ __align__(16) __nv_bfloat16 Ks[32][264];
    __shared__ __align__(16) __nv_bfloat16 Es[32][72];
    int tid = threadIdx.x, lane = tid & 31, wid = tid >> 5;
    int m0w = wid*32;
    float acc[2][8][4] = {};

    for (int c = 0; c < 8; ++c) {
        int nt0 = n0 + c*32;
        #pragma unroll
        for (int v = 0; v < 4; ++v) {
            int idx = v*256 + tid; int r = idx >> 5, sg = idx & 31;
            *(uint4*)&Ks[r][sg*8] =
                *(const uint4*)(g_qkv_bf + ((size_t)(b*NNT + nt0 + r))*768 + coff + sg*8);
        }
        {
            int r = tid >> 3, sg = tid & 7;
            *(uint4*)&Es[r][sg*8] = *(const uint4*)(g_we_bf + (size_t)(nt0 + r)*64 + sg*8);
        }
        __syncthreads();
        #pragma unroll
        for (int kk = 0; kk < 32; kk += 16) {
            unsigned int af[2][4];
            #pragma unroll
            for (int mt = 0; mt < 2; ++mt)
                ldm_x4_t(af[mt], &Ks[kk + (lane & 7) + ((lane >> 4) << 3)]
                                    [m0w + mt*16 + ((lane >> 3) & 1)*8]);
            unsigned int bfr[4][4];
            #pragma unroll
            for (int ng = 0; ng < 4; ++ng)
                ldm_x4_t(bfr[ng], &Es[kk + (lane & 15)][ng*16 + (lane >> 4)*8]);
            #pragma unroll
            for (int mt = 0; mt < 2; ++mt)
                #pragma unroll
                for (int nt = 0; nt < 8; ++nt)
                    mma16816(acc[mt][nt], af[mt],
                             bfr[nt>>1][(nt&1)*2], bfr[nt>>1][(nt&1)*2+1]);
        }
        __syncthreads();
    }
    float* out = &g_zero[ZOFF_KP + which*32768 + b*16384];
    #pragma unroll
    for (int mt = 0; mt < 2; ++mt) {
        int m = m0w + mt*16 + (lane >> 2);
        #pragma unroll
        for (int nt = 0; nt < 8; ++nt) {
            int p = nt*8 + (lane & 3)*2;
            atomicAdd(&out[m*64 + p],       acc[mt][nt][0]);
            atomicAdd(&out[m*64 + p + 1],   acc[mt][nt][1]);
            atomicAdd(&out[(m+8)*64 + p],   acc[mt][nt][2]);
            atomicAdd(&out[(m+8)*64 + p+1], acc[mt][nt][3]);
        }
    }
}

// fused attention tile (HMMA both GEMMs), scrambled bf16 store
__global__ __launch_bounds__(256) void k_attn(const float* __restrict__ be,
                                              const float* __restrict__ temp)
{
    int bh = blockIdx.y; int b = bh >> 2, h = bh & 3;
    int n0 = blockIdx.x*64;
    __shared__ __align__(16) __nv_bfloat16 sA[64][72];
    __shared__ __align__(16) __nv_bfloat16 sB[64][72];
    __shared__ float ss[64][68];
    __shared__ float qr[64];
    int tid = threadIdx.x;
    int wid = tid >> 5, lane = tid & 31;
    int wm = wid & 1, wn = wid >> 1;
    const float* kbase = &g_zero[ZOFF_KP + bh*4096];
    const float* vbase = &g_zero[ZOFF_VP + bh*4096];

    if (tid < 64)
        qr[tid] = 1.f / fmaxf(sqrtf(g_zero[ZOFF_QSS + b*256 + h*64 + tid]), 1e-12f);
    #pragma unroll
    for (int v = 0; v < 4; ++v) {
        int i4 = v*256 + tid; int d = i4 >> 4, pp = (i4 & 15)*4;
        float4 kv = *(const float4*)(kbase + d*64 + pp);
        sB[d][pp]   = __float2bfloat16(kv.x + be[pp]);
        sB[d][pp+1] = __float2bfloat16(kv.y + be[pp+1]);
        sB[d][pp+2] = __float2bfloat16(kv.z + be[pp+2]);
        sB[d][pp+3] = __float2bfloat16(kv.w + be[pp+3]);
    }
    __syncthreads();
    #pragma unroll
    for (int l = 0; l < 2; ++l) {
        int i8 = l*256 + tid; int r = i8 >> 3, sg = (i8 & 7)*8;
        uint4 v = *(const uint4*)(g_qkv_bf + ((size_t)(b*NNT + n0 + r))*768 + h*64 + sg);
        const __nv_bfloat162* hh = (const __nv_bfloat162*)&v;
        __nv_bfloat16 outv[8];
        #pragma unroll
        for (int j = 0; j < 4; ++j) {
            float2 f = __bfloat1622float2(hh[j]);
            outv[j*2]   = __float2bfloat16(f.x * qr[sg + j*2]);
            outv[j*2+1] = __float2bfloat16(f.y * qr[sg + j*2+1]);
        }
        *(uint4*)&sA[r][sg] = *(uint4*)outv;
    }
    __syncthreads();
    float acc1[2][2][4] = {};
    #pragma unroll
    for (int kk = 0; kk < 64; kk += 16) {
        unsigned int af[2][4];
        #pragma unroll
        for (int mt = 0; mt < 2; ++mt)
            ldm_x4(af[mt], &sA[wm*32 + mt*16 + (lane & 15)][kk + (lane >> 4)*8]);
        unsigned int bfr[4];
        ldm_x4_t(bfr, &sB[kk + (lane & 15)][wn*16 + (lane >> 4)*8]);
        #pragma unroll
        for (int mt = 0; mt < 2; ++mt)
            #pragma unroll
            for (int nt = 0; nt < 2; ++nt)
                mma16816(acc1[mt][nt], af[mt], bfr[nt*2], bfr[nt*2+1]);
    }
    float ts = temp[h];
    #pragma unroll
    for (int mt = 0; mt < 2; ++mt) {
        int r = wm*32 + mt*16 + (lane >> 2);
        #pragma unroll
        for (int nt = 0; nt < 2; ++nt) {
            int c = wn*16 + nt*8 + (lane & 3)*2;
            ss[r][c]     = acc1[mt][nt][0]*ts;
            ss[r][c+1]   = acc1[mt][nt][1]*ts;
            ss[r+8][c]   = acc1[mt][nt][2]*ts;
            ss[r+8][c+1] = acc1[mt][nt][3]*ts;
        }
    }
    __syncthreads();
    #pragma unroll
    for (int v = 0; v < 4; ++v) {
        int i4 = v*256 + tid; int d = i4 >> 4, pp = (i4 & 15)*4;
        float4 vv = *(const float4*)(vbase + d*64 + pp);
        sA[d][pp]   = __float2bfloat16(vv.x + be[pp]);
        sA[d][pp+1] = __float2bfloat16(vv.y + be[pp+1]);
        sA[d][pp+2] = __float2bfloat16(vv.z + be[pp+2]);
        sA[d][pp+3] = __float2bfloat16(vv.w + be[pp+3]);
    }
    {
        int row = tid >> 2, g4 = (tid & 3)*16;
        float e[16];
        float mx = -1e30f;
        #pragma unroll
        for (int p = 0; p < 16; ++p) { e[p] = ss[row][g4+p]; mx = fmaxf(mx, e[p]); }
        mx = fmaxf(mx, __shfl_xor_sync(0xffffffffu, mx, 1));
        mx = fmaxf(mx, __shfl_xor_sync(0xffffffffu, mx, 2));
        float sum = 0.f;
        #pragma unroll
        for (int p = 0; p < 16; ++p) { e[p] = __expf(e[p] - mx); sum += e[p]; }
        sum += __shfl_xor_sync(0xffffffffu, sum, 1);
        sum += __shfl_xor_sync(0xffffffffu, sum, 2);
        float inv = 1.f/sum;
        #pragma unroll
        for (int p = 0; p < 16; ++p)
            sB[g4+p][row] = __float2bfloat16(e[p]*inv);
    }
    __syncthreads();
    float acc2[2][2][4] = {};
    #pragma unroll
    for (int kk = 0; kk < 64; kk += 16) {
        unsigned int af[2][4];
        #pragma unroll
        for (int mt = 0; mt < 2; ++mt)
            ldm_x4(af[mt], &sA[wm*32 + mt*16 + (lane & 15)][kk + (lane >> 4)*8]);
        unsigned int bfr[4];
        ldm_x4_t(bfr, &sB[kk + (lane & 15)][wn*16 + (lane >> 4)*8]);
        #pragma unroll
        for (int mt = 0; mt < 2; ++mt)
            #pragma unroll
            for (int nt = 0; nt < 2; ++nt)
                mma16816(acc2[mt][nt], af[mt], bfr[nt*2], bfr[nt*2+1]);
    }
    __nv_bfloat16* sabase = g_sa_bf + (size_t)b*NNT*CC;
    #pragma unroll
    for (int mt = 0; mt < 2; ++mt) {
        int d0 = wm*32 + mt*16 + (lane >> 2);
        #pragma unroll
        for (int nt = 0; nt < 2; ++nt) {
            int nc = n0 + wn*16 + nt*8 + (lane & 3)*2;
            *(__nv_bfloat162*)&sabase[(size_t)(d0*4 + h)*NNT + nc] =
                __floats2bfloat162_rn(acc2[mt][nt][0], acc2[mt][nt][1]);
            *(__nv_bfloat162*)&sabase[(size_t)((d0+8)*4 + h)*NNT + nc] =
                __floats2bfloat162_rn(acc2[mt][nt][2], acc2[mt][nt][3]);
        }
    }
}

// ---------------- launch ----------------
extern "C" void kernel_launch(void* const* d_in, const int* in_sizes, int n_in,
                              void* d_out, int out_size)
{
    const float* x      = (const float*)d_in[0];
    const float* pos    = (const float*)d_in[1];
    const float* ln_g   = (const float*)d_in[2];
    const float* ln_b   = (const float*)d_in[3];
    const float* gamma  = (const float*)d_in[4];
    const float* temp2  = (const float*)d_in[5];
    const float* w_qkv  = (const float*)d_in[6];
    const float* w_e    = (const float*)d_in[7];
    const float* b_e    = (const float*)d_in[8];
    const float* w_pool = (const float*)d_in[9];
    const float* b_pool = (const float*)d_in[10];
    const float* w_fc1  = (const float*)d_in[11];
    const float* w_fc2  = (const float*)d_in[12];
    const float* b_out1 = (const float*)d_in[14];
    const float* b_out2 = (const float*)d_in[16];
    const float* w_c1   = (const float*)d_in[17];
    const float* b_c1   = (const float*)d_in[18];
    const float* w_c2   = (const float*)d_in[19];
    const float* b_c2   = (const float*)d_in[20];

    __nv_bfloat16 *p_h1b, *p_c2b, *p_xtbf, *p_xctbf, *p_sabf;
    __nv_bfloat16 *p_wq, *p_w1, *p_w2, *p_qkvbf;
    float *p_gate, *p_zero;
    cudaGetSymbolAddress((void**)&p_h1b,   g_h1b);
    cudaGetSymbolAddress((void**)&p_c2b,   g_c2b);
    cudaGetSymbolAddress((void**)&p_xtbf,  g_xt_bf);
    cudaGetSymbolAddress((void**)&p_xctbf, g_xct_bf);
    cudaGetSymbolAddress((void**)&p_qkvbf, g_qkv_bf);
    cudaGetSymbolAddress((void**)&p_sabf,  g_sa_bf);
    cudaGetSymbolAddress((void**)&p_wq,    g_wqkv_bf);
    cudaGetSymbolAddress((void**)&p_w1,    g_wo1_bf);
    cudaGetSymbolAddress((void**)&p_w2,    g_wo2_bf);
    cudaGetSymbolAddress((void**)&p_gate,  g_gate);
    cudaGetSymbolAddress((void**)&p_zero,  g_zero);

    static int s_attr_done = 0;
    if (!s_attr_done) {
        cudaFuncSetAttribute(k_megaln,
            cudaFuncAttributeMaxDynamicSharedMemorySize, 55296);
        cudaFuncSetAttribute(k_mma,
            cudaFuncAttributeMaxDynamicSharedMemorySize, 71680);
        s_attr_done = 1;
    }

    k_init <<<3456, 256>>>(w_qkv, (const float*)d_in[13],
                           (const float*)d_in[15], w_e);
    // MHCResBlock with fused stats
    k_conv <<<dim3(54,16), 256>>>(x, (const __nv_bfloat16*)0, w_c1, b_c1, p_h1b,
                                  (const float*)0, (const float*)0,
                                  p_zero + ZOFF_CS1S, p_zero + ZOFF_CS1Q);
    k_conv <<<dim3(54,16), 256>>>((const float*)0, p_h1b, w_c2, b_c2, p_c2b,
                                  p_zero + ZOFF_CS1S, p_zero + ZOFF_CS1Q,
                                  p_zero + ZOFF_CS2S, p_zero + ZOFF_CS2Q);
    // mega-fused transpose + xc + double-LN + pool + d_out(x_n)
    k_megaln<<<dim3(432, BB), 256, 55296>>>(x, pos, ln_g, ln_b, w_pool,
                                            (float*)d_out);
    // channel-attention gate
    k_gate <<<BB, 256>>>(b_pool, w_fc1, w_fc2);
    // qkv (pipelined bf16 HMMA, K=64 stages, fused q sum-squares)
    k_mma  <<<dim3(6,216,1), 256, 71680>>>(p_xtbf, (const __nv_bfloat16*)0, p_wq,
                                    (const __nv_bfloat16*)0, (const float*)0,
                                    (const float*)0, (const float*)0,
                                    p_qkvbf, 768, 768, 1,
                                    (float*)0, (const float*)0);
    // low-rank K/V projection (split-N = 54)
    k_kvmma<<<dim3(4,54), 256>>>();
    // spatial attention
    k_attn <<<dim3(216, BB*NHH), 256>>>(b_e, temp2);
    // both output projections with fused gamma-residual into d_out
    k_mma  <<<dim3(1,216,2), 256, 71680>>>(p_sabf, p_xctbf, p_w1, p_w2,
                                    b_out1, b_out2, p_gate,
                                    (__nv_bfloat16*)0, 128, 256, 0,
                                    (float*)d_out, gamma);
}

// round 11
// speedup vs baseline: 3.8238x; 1.1639x over previous
#include <cuda_runtime.h>
#include <cuda_bf16.h>
#include <cstdint>
#include <math.h>

#define BB 2
#define CC 256
#define NNT 13824
#define NHH 4
#define MTOT (BB*NNT)

// ---------------- scratch ----------------
__device__ __nv_bfloat16 g_h1b[BB*CC*NNT];            // conv1 out
__device__ __nv_bfloat16 g_c2b[BB*CC*NNT];            // conv2 raw out
__device__ __nv_bfloat16 g_xt_bf [BB*NNT*CC];         // x_n bf16 (qkv A)
__device__ __nv_bfloat16 g_xct_bf[BB*NNT*CC];         // xc_n bf16
__device__ __nv_bfloat16 g_qkv_bf[(size_t)BB*NNT*768];
__device__ __nv_bfloat16 g_sa_bf [BB*NNT*CC];         // scrambled x_SA
__device__ __nv_bfloat16 g_wqkv_bf[256*768];
__device__ __nv_bfloat16 g_wo1_bf [256*128];
__device__ __nv_bfloat16 g_wo2_bf [256*128];
__device__ __nv_bfloat16 g_we_bf  [NNT*64];
#define ZOFF_POOL 0
#define ZOFF_QSS  512
#define ZOFF_CS1S 1024
#define ZOFF_CS1Q 1536
#define ZOFF_CS2S 2048
#define ZOFF_CS2Q 2560
#define ZOFF_KP   3072
#define ZOFF_VP   35840
#define ZTOT      68608
__device__ float g_zero[ZTOT];
__device__ float g_gate[BB*CC];

// ---------------- asm helpers ----------------
__device__ __forceinline__ void ldm_x4(unsigned int (&r)[4], const void* p) {
    unsigned int a = (unsigned int)__cvta_generic_to_shared(p);
    asm volatile("ldmatrix.sync.aligned.m8n8.x4.shared.b16 {%0,%1,%2,%3}, [%4];"
        : "=r"(r[0]),"=r"(r[1]),"=r"(r[2]),"=r"(r[3]) : "r"(a));
}
__device__ __forceinline__ void ldm_x4_t(unsigned int (&r)[4], const void* p) {
    unsigned int a = (unsigned int)__cvta_generic_to_shared(p);
    asm volatile("ldmatrix.sync.aligned.m8n8.x4.trans.shared.b16 {%0,%1,%2,%3}, [%4];"
        : "=r"(r[0]),"=r"(r[1]),"=r"(r[2]),"=r"(r[3]) : "r"(a));
}
__device__ __forceinline__ void mma16816(float (&d)[4], const unsigned int (&a)[4],
                                         unsigned int b0, unsigned int b1) {
    asm volatile("mma.sync.aligned.m16n8k16.row.col.f32.bf16.bf16.f32 "
        "{%0,%1,%2,%3},{%4,%5,%6,%7},{%8,%9},{%0,%1,%2,%3};"
        : "+f"(d[0]),"+f"(d[1]),"+f"(d[2]),"+f"(d[3])
        : "r"(a[0]),"r"(a[1]),"r"(a[2]),"r"(a[3]),"r"(b0),"r"(b1));
}
__device__ __forceinline__ void cpa16(void* dst, const void* src) {
    unsigned int d = (unsigned int)__cvta_generic_to_shared(dst);
    asm volatile("cp.async.cg.shared.global [%0], [%1], 16;" :: "r"(d), "l"(src));
}
__device__ __forceinline__ void cp_commit() { asm volatile("cp.async.commit_group;"); }
template<int N> __device__ __forceinline__ void cp_wait() {
    asm volatile("cp.async.wait_group %0;" :: "n"(N));
}

// ---------------- kernels ----------------
__global__ void k_init(const float* __restrict__ wq, const float* __restrict__ w1,
                       const float* __restrict__ w2, const float* __restrict__ we)
{
    int i = blockIdx.x*256 + threadIdx.x;
    if (i < ZTOT) g_zero[i] = 0.f;
    if (i < 196608) g_wqkv_bf[i] = __float2bfloat16(wq[i]);
    if (i < 32768)  { g_wo1_bf[i] = __float2bfloat16(w1[i]);
                      g_wo2_bf[i] = __float2bfloat16(w2[i]); }
    if (i < NNT*64) g_we_bf[i] = __float2bfloat16(we[i]);
}

// grouped 1x1x1 conv via HMMA: out[oc][n] = W^T[oc][ic] @ in[ic][n] per (b,g).
// conv2 path applies instance-norm + lrelu on input; both emit per-channel
// (sum, sumsq) of the biased fp32 outputs via reduced atomics.
__global__ __launch_bounds__(256) void k_convmma(
    const float* __restrict__ srcf, const __nv_bfloat16* __restrict__ srcb,
    const float* __restrict__ w, const float* __restrict__ bias,
    __nv_bfloat16* __restrict__ dst,
    const float* __restrict__ sin_s, const float* __restrict__ sin_q,
    float* __restrict__ sout_s, float* __restrict__ sout_q)
{
    __shared__ __align__(16) __nv_bfloat16 Ws[32][40];   // A: [oc][ic]
    __shared__ __align__(16) __nv_bfloat16 Bs[32][520];  // B: [ic][tok]
    __shared__ float sm[32], sr[32], bss[32];
    __shared__ float sst[8][32][2];
    int bg = blockIdx.y; int b = bg >> 3; int g = bg & 7;
    int n0 = blockIdx.x*512;
    int tid = threadIdx.x, lane = tid & 31, wid = tid >> 5;
    int cbase = b*CC + g*32;

    // A tile (transposed weights) + bias + inorm params
    #pragma unroll
    for (int p = 0; p < 4; ++p) {
        int idx = p*256 + tid;             // idx = ic*32 + oc
        Ws[idx & 31][idx >> 5] = __float2bfloat16(w[g*1024 + idx]);
    }
    if (tid < 32) {
        bss[tid] = bias[g*32 + tid];
        if (srcb) {
            float s = sin_s[cbase+tid], q = sin_q[cbase+tid];
            float m = s*(1.f/NNT);
            sm[tid] = m;
            sr[tid] = rsqrtf(q*(1.f/NNT) - m*m + 1e-5f);
        }
    }
    __syncthreads();

    // B tile
    if (srcf) {
        #pragma unroll
        for (int p = 0; p < 16; ++p) {
            int idx = p*256 + tid;          // 4096 float4
            int row = idx >> 7, cq = idx & 127;
            float4 v = *(const float4*)(srcf + (size_t)(cbase+row)*NNT + n0 + cq*4);
            *(__nv_bfloat162*)&Bs[row][cq*4]   = __floats2bfloat162_rn(v.x, v.y);
            *(__nv_bfloat162*)&Bs[row][cq*4+2] = __floats2bfloat162_rn(v.z, v.w);
        }
    } else {
        #pragma unroll
        for (int p = 0; p < 8; ++p) {
            int idx = p*256 + tid;          // 2048 uint4
            int row = idx >> 6, sg = idx & 63;
            uint4 v = *(const uint4*)(srcb + (size_t)(cbase+row)*NNT + n0 + sg*8);
            const __nv_bfloat162* hh = (const __nv_bfloat162*)&v;
            float m = sm[row], r = sr[row];
            __nv_bfloat16 o[8];
            #pragma unroll
            for (int j = 0; j < 4; ++j) {
                float2 f = __bfloat1622float2(hh[j]);
                float fx = (f.x - m)*r; fx = fx >= 0.f ? fx : 0.01f*fx;
                float fy = (f.y - m)*r; fy = fy >= 0.f ? fy : 0.01f*fy;
                *(__nv_bfloat162*)&o[j*2] = __floats2bfloat162_rn(fx, fy);
            }
            *(uint4*)&Bs[row][sg*8] = *(uint4*)o;
        }
    }
    __syncthreads();

    // one K=32 HMMA pass: warp w handles tokens [w*64, w*64+64)
    float acc[2][8][4] = {};
    #pragma unroll
    for (int kk = 0; kk < 2; ++kk) {
        unsigned int af[2][4];
        #pragma unroll
        for (int mt = 0; mt < 2; ++mt)
            ldm_x4(af[mt], &Ws[mt*16 + (lane & 15)][kk*16 + (lane >> 4)*8]);
        unsigned int bfr[4][4];
        #pragma unroll
        for (int ng = 0; ng < 4; ++ng)
            ldm_x4_t(bfr[ng], &Bs[kk*16 + (lane & 15)][wid*64 + ng*16 + (lane >> 4)*8]);
        #pragma unroll
        for (int mt = 0; mt < 2; ++mt)
            #pragma unroll
            for (int nt = 0; nt < 8; ++nt)
                mma16816(acc[mt][nt], af[mt],
                         bfr[nt>>1][(nt&1)*2], bfr[nt>>1][(nt&1)*2+1]);
    }

    // epilogue: bias add, bf16 store, fp32 stats
    float ssum[2][2] = {}, ssq[2][2] = {};
    #pragma unroll
    for (int mt = 0; mt < 2; ++mt) {
        #pragma unroll
        for (int h = 0; h < 2; ++h) {
            int oc = mt*16 + (lane >> 2) + h*8;
            float bv = bss[oc];
            __nv_bfloat16* drow = dst + (size_t)(cbase+oc)*NNT + n0 + wid*64;
            #pragma unroll
            for (int nt = 0; nt < 8; ++nt) {
                float v0 = acc[mt][nt][h*2+0] + bv;
                float v1 = acc[mt][nt][h*2+1] + bv;
                *(__nv_bfloat162*)&drow[nt*8 + (lane & 3)*2] =
                    __floats2bfloat162_rn(v0, v1);
                ssum[mt][h] += v0 + v1;
                ssq [mt][h] += v0*v0 + v1*v1;
            }
        }
    }
    #pragma unroll
    for (int mt = 0; mt < 2; ++mt)
        #pragma unroll
        for (int h = 0; h < 2; ++h) {
            float s = ssum[mt][h], q = ssq[mt][h];
            s += __shfl_xor_sync(0xffffffffu, s, 1);
            q += __shfl_xor_sync(0xffffffffu, q, 1);
            s += __shfl_xor_sync(0xffffffffu, s, 2);
            q += __shfl_xor_sync(0xffffffffu, q, 2);
            if ((lane & 3) == 0) {
                int oc = mt*16 + (lane >> 2) + h*8;
                sst[wid][oc][0] = s;
                sst[wid][oc][1] = q;
            }
        }
    __syncthreads();
    if (tid < 64) {
        int oc = tid & 31, which = tid >> 5;
        float s = 0.f;
        #pragma unroll
        for (int ww = 0; ww < 8; ++ww) s += sst[ww][oc][which];
        atomicAdd(&(which ? sout_q : sout_s)[cbase+oc], s);
    }
}

// mega-fused: xc = lrelu(inorm(conv2)+x); +pos; LN both streams (warp/token);
// x_n fp32 -> d_out [c,n]; bf16x2 stores; pool partials register-accumulated.
__global__ __launch_bounds__(256) void k_megaln(
    const float* __restrict__ x, const float* __restrict__ pos,
    const float* __restrict__ lg, const float* __restrict__ lb,
    const float* __restrict__ wp, float* __restrict__ dout)
{
    extern __shared__ float dsm[];
    float* xs  = dsm;                                  // 8448 f32
    float* stm = dsm + 8448;
    float* str = stm + 256;
    float* lgs = str + 256;
    float* lbs = lgs + 256;
    __nv_bfloat16* cs = (__nv_bfloat16*)(dsm + 9472);  // 8704 bf16
    int tid = threadIdx.x, tx = tid & 31, ty = tid >> 5;
    int lane = tid & 31, w = tid >> 5;
    int n0 = blockIdx.x*32, b = blockIdx.y;
    {
        float s = g_zero[ZOFF_CS2S + b*256 + tid];
        float q = g_zero[ZOFF_CS2Q + b*256 + tid];
        float m = s*(1.f/NNT);
        stm[tid] = m;
        str[tid] = rsqrtf(q*(1.f/NNT) - m*m + 1e-5f);
        lgs[tid] = lg[tid]; lbs[tid] = lb[tid];
    }
    __syncthreads();
    for (int cc = ty; cc < 256; cc += 8) {
        size_t s = (size_t)(b*CC + cc)*NNT + n0 + tx;
        float xv = x[s];
        float hv = (__bfloat162float(g_c2b[s]) - stm[cc])*str[cc] + xv;
        xs[cc*33 + tx] = xv;
        cs[cc*34 + tx] = __float2bfloat16(hv >= 0.f ? hv : 0.01f*hv);
    }
    __syncthreads();
    float pacc[8];
    #pragma unroll
    for (int j = 0; j < 8; ++j) pacc[j] = 0.f;
    for (int t8 = 0; t8 < 4; ++t8) {
        int tok = w + t8*8;
        const float* prow = pos + (size_t)(n0 + tok)*CC;
        float v1[8], v2[8];
        float s1 = 0.f, q1 = 0.f, s2 = 0.f, q2 = 0.f;
        #pragma unroll
        for (int q = 0; q < 4; ++q) {
            int c0 = lane*2 + q*64;
            float2 p2 = *(const float2*)(prow + c0);
            float ax = xs[c0*33 + tok] + p2.x;
            float ay = xs[(c0+1)*33 + tok] + p2.y;
            float dx = __bfloat162float(cs[c0*34 + tok]) + p2.x;
            float dy = __bfloat162float(cs[(c0+1)*34 + tok]) + p2.y;
            v1[q*2] = ax; v1[q*2+1] = ay;
            v2[q*2] = dx; v2[q*2+1] = dy;
            s1 += ax + ay; q1 += ax*ax + ay*ay;
            s2 += dx + dy; q2 += dx*dx + dy*dy;
        }
        #pragma unroll
        for (int o = 16; o; o >>= 1) {
            s1 += __shfl_xor_sync(0xffffffffu, s1, o);
            q1 += __shfl_xor_sync(0xffffffffu, q1, o);
            s2 += __shfl_xor_sync(0xffffffffu, s2, o);
            q2 += __shfl_xor_sync(0xffffffffu, q2, o);
        }
        float m1 = s1*(1.f/CC), r1 = rsqrtf(q1*(1.f/CC) - m1*m1 + 1e-5f);
        float m2 = s2*(1.f/CC), r2 = rsqrtf(q2*(1.f/CC) - m2*m2 + 1e-5f);
        float wpt = wp[n0 + tok];
        size_t gbase = ((size_t)b*NNT + n0 + tok)*CC;
        #pragma unroll
        for (int q = 0; q < 4; ++q) {
            int c0 = lane*2 + q*64;
            float o1x = (v1[q*2]   - m1)*r1*lgs[c0]   + lbs[c0];
            float o1y = (v1[q*2+1] - m1)*r1*lgs[c0+1] + lbs[c0+1];
            float o2x = (v2[q*2]   - m2)*r2*lgs[c0]   + lbs[c0];
            float o2y = (v2[q*2+1] - m2)*r2*lgs[c0+1] + lbs[c0+1];
            *(__nv_bfloat162*)&g_xt_bf [gbase + c0] = __floats2bfloat162_rn(o1x, o1y);
            *(__nv_bfloat162*)&g_xct_bf[gbase + c0] = __floats2bfloat162_rn(o2x, o2y);
            xs[c0*33 + tok]     = o1x;
            xs[(c0+1)*33 + tok] = o1y;
            pacc[q*2]   += o2x*wpt;
            pacc[q*2+1] += o2y*wpt;
        }
    }
    __syncthreads();
    float* pws = (float*)cs;
    #pragma unroll
    for (int q = 0; q < 4; ++q) {
        int c0 = lane*2 + q*64;
        *(float2*)&pws[w*256 + c0] = make_float2(pacc[q*2], pacc[q*2+1]);
    }
    __syncthreads();
    {
        float s = 0.f;
        #pragma unroll
        for (int ww = 0; ww < 8; ++ww) s += pws[ww*256 + tid];
        atomicAdd(&g_zero[ZOFF_POOL + b*256 + tid], s);
    }
    for (int cc = ty; cc < 256; cc += 8)
        dout[(size_t)(b*CC + cc)*NNT + n0 + tx] = xs[cc*33 + tx];
}

__global__ void k_gate(const float* __restrict__ bp, const float* __restrict__ w1,
                       const float* __restrict__ w2)
{
    __shared__ float ps[256], hs[64];
    int b = blockIdx.x, t = threadIdx.x;
    ps[t] = g_zero[ZOFF_POOL + b*CC + t] + bp[0];
    __syncthreads();
    if (t < 64) {
        float a = 0.f;
        for (int c = 0; c < 256; ++c) a += ps[c]*w1[c*64 + t];
        hs[t] = fmaxf(a, 0.f);
    }
    __syncthreads();
    float a = 0.f;
    for (int j = 0; j < 64; ++j) a += hs[j]*w2[j*256 + t];
    g_gate[b*CC + t] = 1.f/(1.f + expf(-a));
}

// bf16 HMMA GEMM, K=64 chunks, cp.async double buffering, dynamic smem.
#define AS_(st,r,c) smem_mma[(size_t)(st)*9216 + (r)*72 + (c)]
#define BS_(st,r,c) smem_mma[18432 + (size_t)(st)*8704 + (r)*136 + (c)]
__global__ __launch_bounds__(256) void k_mma(
    const __nv_bfloat16* __restrict__ A, const __nv_bfloat16* __restrict__ A2,
    const __nv_bfloat16* __restrict__ Bw, const __nv_bfloat16* __restrict__ Bw2,
    const float* __restrict__ bias, const float* __restrict__ bias2,
    const float* __restrict__ gate,
    __nv_bfloat16* __restrict__ Cb, int Nld, int ldc, int doqss,
    float* __restrict__ dout, const float* __restrict__ gfin)
{
    extern __shared__ __nv_bfloat16 smem_mma[];
    int tid = threadIdx.x;
    int wid = tid >> 5, lane = tid & 31;
    int wm = wid >> 2;
    int wn = wid & 3;
    int m0 = blockIdx.y * 128;
    int n0 = blockIdx.x * 128;
    int coff = 0;
    const float* grow = nullptr;
    if (blockIdx.z == 1) {
        A = A2; Bw = Bw2; bias = bias2; coff = 128;
        grow = gate + (m0 / NNT)*CC;
    }

    float acc[4][4][4] = {};

    #pragma unroll
    for (int p = 0; p < 4; ++p) {
        int idx = p*256 + tid; int r = idx >> 3, sg = idx & 7;
        cpa16(&AS_(0, r, sg*8), A + (size_t)(m0 + r)*256 + sg*8);
    }
    #pragma unroll
    for (int p = 0; p < 4; ++p) {
        int idx = p*256 + tid; int r = idx >> 4, sg = idx & 15;
        cpa16(&BS_(0, r, sg*8), Bw + (size_t)r*Nld + n0 + sg*8);
    }
    cp_commit();

    for (int it = 0; it < 4; ++it) {
        int k0 = it*64, st = it & 1;
        if (it < 3) {
            int kn = k0 + 64, sn = st ^ 1;
            #pragma unroll
            for (int p = 0; p < 4; ++p) {
                int idx = p*256 + tid; int r = idx >> 3, sg = idx & 7;
                cpa16(&AS_(sn, r, sg*8), A + (size_t)(m0 + r)*256 + kn + sg*8);
            }
            #pragma unroll
            for (int p = 0; p < 4; ++p) {
                int idx = p*256 + tid; int r = idx >> 4, sg = idx & 15;
                cpa16(&BS_(sn, r, sg*8), Bw + (size_t)(kn + r)*Nld + n0 + sg*8);
            }
            cp_commit();
            cp_wait<1>();
        } else {
            cp_wait<0>();
        }
        __syncthreads();
        if (grow) {
            #pragma unroll
            for (int p = 0; p < 4; ++p) {
                int idx = p*256 + tid; int r = idx >> 3, sg = idx & 7;
                __nv_bfloat16* qp = &AS_(st, r, sg*8);
                #pragma unroll
                for (int j = 0; j < 8; ++j)
                    qp[j] = __float2bfloat16(__bfloat162float(qp[j])*grow[k0+sg*8+j]);
            }
            __syncthreads();
        }
        #pragma unroll
        for (int kk = 0; kk < 4; ++kk) {
            unsigned int af[4][4];
            #pragma unroll
            for (int mt = 0; mt < 4; ++mt)
                ldm_x4(af[mt], &AS_(st, wm*64 + mt*16 + (lane & 15), kk*16 + (lane >> 4)*8));
            unsigned int bfr[2][4];
            #pragma unroll
            for (int g2 = 0; g2 < 2; ++g2)
                ldm_x4_t(bfr[g2], &BS_(st, kk*16 + (lane & 15), wn*32 + g2*16 + (lane >> 4)*8));
            #pragma unroll
            for (int mt = 0; mt < 4; ++mt)
                #pragma unroll
                for (int nt = 0; nt < 4; ++nt)
                    mma16816(acc[mt][nt], af[mt],
                             bfr[nt>>1][(nt&1)*2], bfr[nt>>1][(nt&1)*2+1]);
        }
        __syncthreads();
    }
    if (doqss && n0 < 256) {
        int b = m0 / NNT;
        #pragma unroll
        for (int nt = 0; nt < 4; ++nt) {
            float s0 = 0.f, s1 = 0.f;
            #pragma unroll
            for (int mt = 0; mt < 4; ++mt) {
                #pragma unroll
                for (int h = 0; h < 2; ++h) {
                    float a0 = acc[mt][nt][h*2+0], a1 = acc[mt][nt][h*2+1];
                    s0 += a0*a0; s1 += a1*a1;
                }
            }
            #pragma unroll
            for (int o = 4; o <= 16; o <<= 1) {
                s0 += __shfl_xor_sync(0xffffffffu, s0, o);
                s1 += __shfl_xor_sync(0xffffffffu, s1, o);
            }
            if ((lane >> 2) == 0) {
                int col = n0 + wn*32 + nt*8 + (lane & 3)*2;
                atomicAdd(&g_zero[ZOFF_QSS + b*256 + col],   s0);
                atomicAdd(&g_zero[ZOFF_QSS + b*256 + col+1], s1);
            }
        }
    }
    if (gfin) {
        float* ts = (float*)smem_mma;
        const int TS = 132;
        int b = m0 / NNT;
        int n0t = m0 % NNT;
        #pragma unroll 1
        for (int q = 0; q < 4; ++q) {
            __syncthreads();
            if (wn == q) {
                #pragma unroll
                for (int mt = 0; mt < 4; ++mt) {
                    #pragma unroll
                    for (int nt = 0; nt < 4; ++nt) {
                        int ll = nt*8 + (lane & 3)*2;
                        float gm0 = gfin[coff + q*32 + ll];
                        float gm1 = gfin[coff + q*32 + ll + 1];
                        float b0 = bias[q*32 + ll], b1 = bias[q*32 + ll + 1];
                        #pragma unroll
                        for (int h = 0; h < 2; ++h) {
                            int rr = wm*64 + mt*16 + (lane >> 2) + h*8;
                            ts[ll*TS + rr]     = (acc[mt][nt][h*2+0] + b0)*gm0;
                            ts[(ll+1)*TS + rr] = (acc[mt][nt][h*2+1] + b1)*gm1;
                        }
                    }
                }
            }
            __syncthreads();
            #pragma unroll
            for (int r = 0; r < 4; ++r) {
                int l2 = wid*4 + r;
                int c = coff + q*32 + l2;
                float* dp = dout + (size_t)(b*CC + c)*NNT + n0t;
                float4 dv = *(float4*)(dp + lane*4);
                dv.x += ts[l2*TS + lane*4 + 0];
                dv.y += ts[l2*TS + lane*4 + 1];
                dv.z += ts[l2*TS + lane*4 + 2];
                dv.w += ts[l2*TS + lane*4 + 3];
                *(float4*)(dp + lane*4) = dv;
            }
        }
        return;
    }
    #pragma unroll
    for (int mt = 0; mt < 4; ++mt) {
        int row0 = m0 + wm*64 + mt*16 + (lane >> 2);
        #pragma unroll
        for (int nt = 0; nt < 4; ++nt) {
            int col = wn*32 + nt*8 + (lane & 3)*2;
            #pragma unroll
            for (int h = 0; h < 2; ++h) {
                int r = row0 + h*8;
                float v0 = acc[mt][nt][h*2+0];
                float v1 = acc[mt][nt][h*2+1];
                if (bias) { v0 += bias[n0+col]; v1 += bias[n0+col+1]; }
                __nv_bfloat16* p = Cb + (size_t)r*ldc + coff + n0 + col;
                p[0] = __float2bfloat16(v0); p[1] = __float2bfloat16(v1);
            }
        }
    }
}

// K/V low-rank projection via tensor cores; split-N=54 for occupancy
__global__ __launch_bounds__(256) void k_kvmma()
{
    int b = blockIdx.x >> 1, which = blockIdx.x & 1;
    int n0 = blockIdx.y * 256;
    int coff = 256*(which+1);
    __shared__ __align__(16) __nv_bfloat16 Ks[32][264];
    __shared__ __align__(16) __nv_bfloat16 Es[32][72];
    int tid = threadIdx.x, lane = tid & 31, wid = tid >> 5;
    int m0w = wid*32;
    float acc[2][8][4] = {};

    for (int c = 0; c < 8; ++c) {
        int nt0 = n0 + c*32;
        #pragma unroll
        for (int v = 0; v < 4; ++v) {
            int idx = v*256 + tid; int r = idx >> 5, sg = idx & 31;
            *(uint4*)&Ks[r][sg*8] =
                *(const uint4*)(g_qkv_bf + ((size_t)(b*NNT + nt0 + r))*768 + coff + sg*8);
        }
        {
            int r = tid >> 3, sg = tid & 7;
            *(uint4*)&Es[r][sg*8] = *(const uint4*)(g_we_bf + (size_t)(nt0 + r)*64 + sg*8);
        }
        __syncthreads();
        #pragma unroll
        for (int kk = 0; kk < 32; kk += 16) {
            unsigned int af[2][4];
            #pragma unroll
            for (int mt = 0; mt < 2; ++mt)
                ldm_x4_t(af[mt], &Ks[kk + (lane & 7) + ((lane >> 4) << 3)]
                                    [m0w + mt*16 + ((lane >> 3) & 1)*8]);
            unsigned int bfr[4][4];
            #pragma unroll
            for (int ng = 0; ng < 4; ++ng)
                ldm_x4_t(bfr[ng], &Es[kk + (lane & 15)][ng*16 + (lane >> 4)*8]);
            #pragma unroll
            for (int mt = 0; mt < 2; ++mt)
                #pragma unroll
                for (int nt = 0; nt < 8; ++nt)
                    mma16816(acc[mt][nt], af[mt],
                             bfr[nt>>1][(nt&1)*2], bfr[nt>>1][(nt&1)*2+1]);
        }
        __syncthreads();
    }
    float* out = &g_zero[ZOFF_KP + which*32768 + b*16384];
    #pragma unroll
    for (int mt = 0; mt < 2; ++mt) {
        int m = m0w + mt*16 + (lane >> 2);
        #pragma unroll
        for (int nt = 0; nt < 8; ++nt) {
            int p = nt*8 + (lane & 3)*2;
            atomicAdd(&out[m*64 + p],       acc[mt][nt][0]);
            atomicAdd(&out[m*64 + p + 1],   acc[mt][nt][1]);
            atomicAdd(&out[(m+8)*64 + p],   acc[mt][nt][2]);
            atomicAdd(&out[(m+8)*64 + p+1], acc[mt][nt][3]);
        }
    }
}

// fused attention tile (HMMA both GEMMs), scrambled bf16 store
__global__ __launch_bounds__(256) void k_attn(const float* __restrict__ be,
                                              const float* __restrict__ temp)
{
    int bh = blockIdx.y; int b = bh >> 2, h = bh & 3;
    int n0 = blockIdx.x*64;
    __shared__ __align__(16) __nv_bfloat16 sA[64][72];
    __shared__ __align__(16) __nv_bfloat16 sB[64][72];
    __shared__ float ss[64][68];
    __shared__ float qr[64];
    int tid = threadIdx.x;
    int wid = tid >> 5, lane = tid & 31;
    int wm = wid & 1, wn = wid >> 1;
    const float* kbase = &g_zero[ZOFF_KP + bh*4096];
    const float* vbase = &g_zero[ZOFF_VP + bh*4096];

    if (tid < 64)
        qr[tid] = 1.f / fmaxf(sqrtf(g_zero[ZOFF_QSS + b*256 + h*64 + tid]), 1e-12f);
    #pragma unroll
    for (int v = 0; v < 4; ++v) {
        int i4 = v*256 + tid; int d = i4 >> 4, pp = (i4 & 15)*4;
        float4 kv = *(const float4*)(kbase + d*64 + pp);
        sB[d][pp]   = __float2bfloat16(kv.x + be[pp]);
        sB[d][pp+1] = __float2bfloat16(kv.y + be[pp+1]);
        sB[d][pp+2] = __float2bfloat16(kv.z + be[pp+2]);
        sB[d][pp+3] = __float2bfloat16(kv.w + be[pp+3]);
    }
    __syncthreads();
    #pragma unroll
    for (int l = 0; l < 2; ++l) {
        int i8 = l*256 + tid; int r = i8 >> 3, sg = (i8 & 7)*8;
        uint4 v = *(const uint4*)(g_qkv_bf + ((size_t)(b*NNT + n0 + r))*768 + h*64 + sg);
        const __nv_bfloat162* hh = (const __nv_bfloat162*)&v;
        __nv_bfloat16 outv[8];
        #pragma unroll
        for (int j = 0; j < 4; ++j) {
            float2 f = __bfloat1622float2(hh[j]);
            outv[j*2]   = __float2bfloat16(f.x * qr[sg + j*2]);
            outv[j*2+1] = __float2bfloat16(f.y * qr[sg + j*2+1]);
        }
        *(uint4*)&sA[r][sg] = *(uint4*)outv;
    }
    __syncthreads();
    float acc1[2][2][4] = {};
    #pragma unroll
    for (int kk = 0; kk < 64; kk += 16) {
        unsigned int af[2][4];
        #pragma unroll
        for (int mt = 0; mt < 2; ++mt)
            ldm_x4(af[mt], &sA[wm*32 + mt*16 + (lane & 15)][kk + (lane >> 4)*8]);
        unsigned int bfr[4];
        ldm_x4_t(bfr, &sB[kk + (lane & 15)][wn*16 + (lane >> 4)*8]);
        #pragma unroll
        for (int mt = 0; mt < 2; ++mt)
            #pragma unroll
            for (int nt = 0; nt < 2; ++nt)
                mma16816(acc1[mt][nt], af[mt], bfr[nt*2], bfr[nt*2+1]);
    }
    float ts = temp[h];
    #pragma unroll
    for (int mt = 0; mt < 2; ++mt) {
        int r = wm*32 + mt*16 + (lane >> 2);
        #pragma unroll
        for (int nt = 0; nt < 2; ++nt) {
            int c = wn*16 + nt*8 + (lane & 3)*2;
            ss[r][c]     = acc1[mt][nt][0]*ts;
            ss[r][c+1]   = acc1[mt][nt][1]*ts;
            ss[r+8][c]   = acc1[mt][nt][2]*ts;
            ss[r+8][c+1] = acc1[mt][nt][3]*ts;
        }
    }
    __syncthreads();
    #pragma unroll
    for (int v = 0; v < 4; ++v) {
        int i4 = v*256 + tid; int d = i4 >> 4, pp = (i4 & 15)*4;
        float4 vv = *(const float4*)(vbase + d*64 + pp);
        sA[d][pp]   = __float2bfloat16(vv.x + be[pp]);
        sA[d][pp+1] = __float2bfloat16(vv.y + be[pp+1]);
        sA[d][pp+2] = __float2bfloat16(vv.z + be[pp+2]);
        sA[d][pp+3] = __float2bfloat16(vv.w + be[pp+3]);
    }
    {
        int row = tid >> 2, g4 = (tid & 3)*16;
        float e[16];
        float mx = -1e30f;
        #pragma unroll
        for (int p = 0; p < 16; ++p) { e[p] = ss[row][g4+p]; mx = fmaxf(mx, e[p]); }
        mx = fmaxf(mx, __shfl_xor_sync(0xffffffffu, mx, 1));
        mx = fmaxf(mx, __shfl_xor_sync(0xffffffffu, mx, 2));
        float sum = 0.f;
        #pragma unroll
        for (int p = 0; p < 16; ++p) { e[p] = __expf(e[p] - mx); sum += e[p]; }
        sum += __shfl_xor_sync(0xffffffffu, sum, 1);
        sum += __shfl_xor_sync(0xffffffffu, sum, 2);
        float inv = 1.f/sum;
        #pragma unroll
        for (int p = 0; p < 16; ++p)
            sB[g4+p][row] = __float2bfloat16(e[p]*inv);
    }
    __syncthreads();
    float acc2[2][2][4] = {};
    #pragma unroll
    for (int kk = 0; kk < 64; kk += 16) {
        unsigned int af[2][4];
        #pragma unroll
        for (int mt = 0; mt < 2; ++mt)
            ldm_x4(af[mt], &sA[wm*32 + mt*16 + (lane & 15)][kk + (lane >> 4)*8]);
        unsigned int bfr[4];
        ldm_x4_t(bfr, &sB[kk + (lane & 15)][wn*16 + (lane >> 4)*8]);
        #pragma unroll
        for (int mt = 0; mt < 2; ++mt)
            #pragma unroll
            for (int nt = 0; nt < 2; ++nt)
                mma16816(acc2[mt][nt], af[mt], bfr[nt*2], bfr[nt*2+1]);
    }
    __nv_bfloat16* sabase = g_sa_bf + (size_t)b*NNT*CC;
    #pragma unroll
    for (int mt = 0; mt < 2; ++mt) {
        int d0 = wm*32 + mt*16 + (lane >> 2);
        #pragma unroll
        for (int nt = 0; nt < 2; ++nt) {
            int nc = n0 + wn*16 + nt*8 + (lane & 3)*2;
            *(__nv_bfloat162*)&sabase[(size_t)(d0*4 + h)*NNT + nc] =
                __floats2bfloat162_rn(acc2[mt][nt][0], acc2[mt][nt][1]);
            *(__nv_bfloat162*)&sabase[(size_t)((d0+8)*4 + h)*NNT + nc] =
                __floats2bfloat162_rn(acc2[mt][nt][2], acc2[mt][nt][3]);
        }
    }
}

// ---------------- launch ----------------
extern "C" void kernel_launch(void* const* d_in, const int* in_sizes, int n_in,
                              void* d_out, int out_size)
{
    const float* x      = (const float*)d_in[0];
    const float* pos    = (const float*)d_in[1];
    const float* ln_g   = (const float*)d_in[2];
    const float* ln_b   = (const float*)d_in[3];
    const float* gamma  = (const float*)d_in[4];
    const float* temp2  = (const float*)d_in[5];
    const float* w_qkv  = (const float*)d_in[6];
    const float* w_e    = (const float*)d_in[7];
    const float* b_e    = (const float*)d_in[8];
    const float* w_pool = (const float*)d_in[9];
    const float* b_pool = (const float*)d_in[10];
    const float* w_fc1  = (const float*)d_in[11];
    const float* w_fc2  = (const float*)d_in[12];
    const float* b_out1 = (const float*)d_in[14];
    const float* b_out2 = (const float*)d_in[16];
    const float* w_c1   = (const float*)d_in[17];
    const float* b_c1   = (const float*)d_in[18];
    const float* w_c2   = (const float*)d_in[19];
    const float* b_c2   = (const float*)d_in[20];

    __nv_bfloat16 *p_h1b, *p_c2b, *p_xtbf, *p_xctbf, *p_sabf;
    __nv_bfloat16 *p_wq, *p_w1, *p_w2, *p_qkvbf;
    float *p_gate, *p_zero;
    cudaGetSymbolAddress((void**)&p_h1b,   g_h1b);
    cudaGetSymbolAddress((void**)&p_c2b,   g_c2b);
    cudaGetSymbolAddress((void**)&p_xtbf,  g_xt_bf);
    cudaGetSymbolAddress((void**)&p_xctbf, g_xct_bf);
    cudaGetSymbolAddress((void**)&p_qkvbf, g_qkv_bf);
    cudaGetSymbolAddress((void**)&p_sabf,  g_sa_bf);
    cudaGetSymbolAddress((void**)&p_wq,    g_wqkv_bf);
    cudaGetSymbolAddress((void**)&p_w1,    g_wo1_bf);
    cudaGetSymbolAddress((void**)&p_w2,    g_wo2_bf);
    cudaGetSymbolAddress((void**)&p_gate,  g_gate);
    cudaGetSymbolAddress((void**)&p_zero,  g_zero);

    static int s_attr_done = 0;
    if (!s_attr_done) {
        cudaFuncSetAttribute(k_megaln,
            cudaFuncAttributeMaxDynamicSharedMemorySize, 55296);
        cudaFuncSetAttribute(k_mma,
            cudaFuncAttributeMaxDynamicSharedMemorySize, 71680);
        s_attr_done = 1;
    }

    k_init <<<3456, 256>>>(w_qkv, (const float*)d_in[13],
                           (const float*)d_in[15], w_e);
    // MHCResBlock: grouped convs via HMMA with fused stats
    k_convmma<<<dim3(27,16), 256>>>(x, (const __nv_bfloat16*)0, w_c1, b_c1, p_h1b,
                                    (const float*)0, (const float*)0,
                                    p_zero + ZOFF_CS1S, p_zero + ZOFF_CS1Q);
    k_convmma<<<dim3(27,16), 256>>>((const float*)0, p_h1b, w_c2, b_c2, p_c2b,
                                    p_zero + ZOFF_CS1S, p_zero + ZOFF_CS1Q,
                                    p_zero + ZOFF_CS2S, p_zero + ZOFF_CS2Q);
    // mega-fused transpose + xc + double-LN + pool + d_out(x_n)
    k_megaln<<<dim3(432, BB), 256, 55296>>>(x, pos, ln_g, ln_b, w_pool,
                                            (float*)d_out);
    // channel-attention gate
    k_gate <<<BB, 256>>>(b_pool, w_fc1, w_fc2);
    // qkv (pipelined bf16 HMMA, K=64 stages, fused q sum-squares)
    k_mma  <<<dim3(6,216,1), 256, 71680>>>(p_xtbf, (const __nv_bfloat16*)0, p_wq,
                                    (const __nv_bfloat16*)0, (const float*)0,
                                    (const float*)0, (const float*)0,
                                    p_qkvbf, 768, 768, 1,
                                    (float*)0, (const float*)0);
    // low-rank K/V projection (split-N = 54)
    k_kvmma<<<dim3(4,54), 256>>>();
    // spatial attention
    k_attn <<<dim3(216, BB*NHH), 256>>>(b_e, temp2);
    // both output projections with fused gamma-residual into d_out
    k_mma  <<<dim3(1,216,2), 256, 71680>>>(p_sabf, p_xctbf, p_w1, p_w2,
                                    b_out1, b_out2, p_gate,
                                    (__nv_bfloat16*)0, 128, 256, 0,
                                    (float*)d_out, gamma);
}

// round 12
// speedup vs baseline: 4.5459x; 1.1889x over previous
#include <cuda_runtime.h>
#include <cuda_bf16.h>
#include <cstdint>
#include <math.h>

#define BB 2
#define CC 256
#define NNT 13824
#define NHH 4
#define MTOT (BB*NNT)

// ---------------- scratch ----------------
__device__ __nv_bfloat16 g_h1b[BB*CC*NNT];            // conv1 out
__device__ __nv_bfloat16 g_c2b[BB*CC*NNT];            // conv2 raw out
__device__ __nv_bfloat16 g_xt_bf [BB*NNT*CC];         // x_n bf16 (qkv A)
__device__ __nv_bfloat16 g_xct_bf[BB*NNT*CC];         // xc_n bf16
__device__ __nv_bfloat16 g_qkv_bf[(size_t)BB*NNT*768];// only q cols [0,256) written
__device__ __nv_bfloat16 g_sa_bf [BB*NNT*CC];         // scrambled x_SA
__device__ __nv_bfloat16 g_wqkv_bf[256*768];
__device__ __nv_bfloat16 g_wo1_bf [256*128];
__device__ __nv_bfloat16 g_wo2_bf [256*128];
__device__ __nv_bfloat16 g_we_bf  [NNT*64];
#define ZOFF_POOL 0
#define ZOFF_QSS  512
#define ZOFF_CS1S 1024
#define ZOFF_CS1Q 1536
#define ZOFF_CS2S 2048
#define ZOFF_CS2Q 2560
#define ZOFF_KP   3072
#define ZOFF_VP   35840
#define ZTOT      68608
__device__ float g_zero[ZTOT];
__device__ float g_gate[BB*CC];

// ---------------- asm helpers ----------------
__device__ __forceinline__ void ldm_x4(unsigned int (&r)[4], const void* p) {
    unsigned int a = (unsigned int)__cvta_generic_to_shared(p);
    asm volatile("ldmatrix.sync.aligned.m8n8.x4.shared.b16 {%0,%1,%2,%3}, [%4];"
        : "=r"(r[0]),"=r"(r[1]),"=r"(r[2]),"=r"(r[3]) : "r"(a));
}
__device__ __forceinline__ void ldm_x4_t(unsigned int (&r)[4], const void* p) {
    unsigned int a = (unsigned int)__cvta_generic_to_shared(p);
    asm volatile("ldmatrix.sync.aligned.m8n8.x4.trans.shared.b16 {%0,%1,%2,%3}, [%4];"
        : "=r"(r[0]),"=r"(r[1]),"=r"(r[2]),"=r"(r[3]) : "r"(a));
}
__device__ __forceinline__ void mma16816(float (&d)[4], const unsigned int (&a)[4],
                                         unsigned int b0, unsigned int b1) {
    asm volatile("mma.sync.aligned.m16n8k16.row.col.f32.bf16.bf16.f32 "
        "{%0,%1,%2,%3},{%4,%5,%6,%7},{%8,%9},{%0,%1,%2,%3};"
        : "+f"(d[0]),"+f"(d[1]),"+f"(d[2]),"+f"(d[3])
        : "r"(a[0]),"r"(a[1]),"r"(a[2]),"r"(a[3]),"r"(b0),"r"(b1));
}
__device__ __forceinline__ void cpa16(void* dst, const void* src) {
    unsigned int d = (unsigned int)__cvta_generic_to_shared(dst);
    asm volatile("cp.async.cg.shared.global [%0], [%1], 16;" :: "r"(d), "l"(src));
}
__device__ __forceinline__ void cp_commit() { asm volatile("cp.async.commit_group;"); }
template<int N> __device__ __forceinline__ void cp_wait() {
    asm volatile("cp.async.wait_group %0;" :: "n"(N));
}

// ---------------- kernels ----------------
__global__ void k_init(const float* __restrict__ wq, const float* __restrict__ w1,
                       const float* __restrict__ w2, const float* __restrict__ we)
{
    int i = blockIdx.x*256 + threadIdx.x;
    if (i < ZTOT) g_zero[i] = 0.f;
    if (i < 196608) g_wqkv_bf[i] = __float2bfloat16(wq[i]);
    if (i < 32768)  { g_wo1_bf[i] = __float2bfloat16(w1[i]);
                      g_wo2_bf[i] = __float2bfloat16(w2[i]); }
    if (i < NNT*64) g_we_bf[i] = __float2bfloat16(we[i]);
}

// grouped 1x1x1 conv via HMMA (from R11, unchanged)
__global__ __launch_bounds__(256) void k_convmma(
    const float* __restrict__ srcf, const __nv_bfloat16* __restrict__ srcb,
    const float* __restrict__ w, const float* __restrict__ bias,
    __nv_bfloat16* __restrict__ dst,
    const float* __restrict__ sin_s, const float* __restrict__ sin_q,
    float* __restrict__ sout_s, float* __restrict__ sout_q)
{
    __shared__ __align__(16) __nv_bfloat16 Ws[32][40];
    __shared__ __align__(16) __nv_bfloat16 Bs[32][520];
    __shared__ float sm[32], sr[32], bss[32];
    __shared__ float sst[8][32][2];
    int bg = blockIdx.y; int b = bg >> 3; int g = bg & 7;
    int n0 = blockIdx.x*512;
    int tid = threadIdx.x, lane = tid & 31, wid = tid >> 5;
    int cbase = b*CC + g*32;

    #pragma unroll
    for (int p = 0; p < 4; ++p) {
        int idx = p*256 + tid;
        Ws[idx & 31][idx >> 5] = __float2bfloat16(w[g*1024 + idx]);
    }
    if (tid < 32) {
        bss[tid] = bias[g*32 + tid];
        if (srcb) {
            float s = sin_s[cbase+tid], q = sin_q[cbase+tid];
            float m = s*(1.f/NNT);
            sm[tid] = m;
            sr[tid] = rsqrtf(q*(1.f/NNT) - m*m + 1e-5f);
        }
    }
    __syncthreads();

    if (srcf) {
        #pragma unroll
        for (int p = 0; p < 16; ++p) {
            int idx = p*256 + tid;
            int row = idx >> 7, cq = idx & 127;
            float4 v = *(const float4*)(srcf + (size_t)(cbase+row)*NNT + n0 + cq*4);
            *(__nv_bfloat162*)&Bs[row][cq*4]   = __floats2bfloat162_rn(v.x, v.y);
            *(__nv_bfloat162*)&Bs[row][cq*4+2] = __floats2bfloat162_rn(v.z, v.w);
        }
    } else {
        #pragma unroll
        for (int p = 0; p < 8; ++p) {
            int idx = p*256 + tid;
            int row = idx >> 6, sg = idx & 63;
            uint4 v = *(const uint4*)(srcb + (size_t)(cbase+row)*NNT + n0 + sg*8);
            const __nv_bfloat162* hh = (const __nv_bfloat162*)&v;
            float m = sm[row], r = sr[row];
            __nv_bfloat16 o[8];
            #pragma unroll
            for (int j = 0; j < 4; ++j) {
                float2 f = __bfloat1622float2(hh[j]);
                float fx = (f.x - m)*r; fx = fx >= 0.f ? fx : 0.01f*fx;
                float fy = (f.y - m)*r; fy = fy >= 0.f ? fy : 0.01f*fy;
                *(__nv_bfloat162*)&o[j*2] = __floats2bfloat162_rn(fx, fy);
            }
            *(uint4*)&Bs[row][sg*8] = *(uint4*)o;
        }
    }
    __syncthreads();

    float acc[2][8][4] = {};
    #pragma unroll
    for (int kk = 0; kk < 2; ++kk) {
        unsigned int af[2][4];
        #pragma unroll
        for (int mt = 0; mt < 2; ++mt)
            ldm_x4(af[mt], &Ws[mt*16 + (lane & 15)][kk*16 + (lane >> 4)*8]);
        unsigned int bfr[4][4];
        #pragma unroll
        for (int ng = 0; ng < 4; ++ng)
            ldm_x4_t(bfr[ng], &Bs[kk*16 + (lane & 15)][wid*64 + ng*16 + (lane >> 4)*8]);
        #pragma unroll
        for (int mt = 0; mt < 2; ++mt)
            #pragma unroll
            for (int nt = 0; nt < 8; ++nt)
                mma16816(acc[mt][nt], af[mt],
                         bfr[nt>>1][(nt&1)*2], bfr[nt>>1][(nt&1)*2+1]);
    }

    float ssum[2][2] = {}, ssq[2][2] = {};
    #pragma unroll
    for (int mt = 0; mt < 2; ++mt) {
        #pragma unroll
        for (int h = 0; h < 2; ++h) {
            int oc = mt*16 + (lane >> 2) + h*8;
            float bv = bss[oc];
            __nv_bfloat16* drow = dst + (size_t)(cbase+oc)*NNT + n0 + wid*64;
            #pragma unroll
            for (int nt = 0; nt < 8; ++nt) {
                float v0 = acc[mt][nt][h*2+0] + bv;
                float v1 = acc[mt][nt][h*2+1] + bv;
                *(__nv_bfloat162*)&drow[nt*8 + (lane & 3)*2] =
                    __floats2bfloat162_rn(v0, v1);
                ssum[mt][h] += v0 + v1;
                ssq [mt][h] += v0*v0 + v1*v1;
            }
        }
    }
    #pragma unroll
    for (int mt = 0; mt < 2; ++mt)
        #pragma unroll
        for (int h = 0; h < 2; ++h) {
            float s = ssum[mt][h], q = ssq[mt][h];
            s += __shfl_xor_sync(0xffffffffu, s, 1);
            q += __shfl_xor_sync(0xffffffffu, q, 1);
            s += __shfl_xor_sync(0xffffffffu, s, 2);
            q += __shfl_xor_sync(0xffffffffu, q, 2);
            if ((lane & 3) == 0) {
                int oc = mt*16 + (lane >> 2) + h*8;
                sst[wid][oc][0] = s;
                sst[wid][oc][1] = q;
            }
        }
    __syncthreads();
    if (tid < 64) {
        int oc = tid & 31, which = tid >> 5;
        float s = 0.f;
        #pragma unroll
        for (int ww = 0; ww < 8; ++ww) s += sst[ww][oc][which];
        atomicAdd(&(which ? sout_q : sout_s)[cbase+oc], s);
    }
}

// mega-fused LN kernel (from R10, unchanged)
__global__ __launch_bounds__(256) void k_megaln(
    const float* __restrict__ x, const float* __restrict__ pos,
    const float* __restrict__ lg, const float* __restrict__ lb,
    const float* __restrict__ wp, float* __restrict__ dout)
{
    extern __shared__ float dsm[];
    float* xs  = dsm;
    float* stm = dsm + 8448;
    float* str = stm + 256;
    float* lgs = str + 256;
    float* lbs = lgs + 256;
    __nv_bfloat16* cs = (__nv_bfloat16*)(dsm + 9472);
    int tid = threadIdx.x, tx = tid & 31, ty = tid >> 5;
    int lane = tid & 31, w = tid >> 5;
    int n0 = blockIdx.x*32, b = blockIdx.y;
    {
        float s = g_zero[ZOFF_CS2S + b*256 + tid];
        float q = g_zero[ZOFF_CS2Q + b*256 + tid];
        float m = s*(1.f/NNT);
        stm[tid] = m;
        str[tid] = rsqrtf(q*(1.f/NNT) - m*m + 1e-5f);
        lgs[tid] = lg[tid]; lbs[tid] = lb[tid];
    }
    __syncthreads();
    for (int cc = ty; cc < 256; cc += 8) {
        size_t s = (size_t)(b*CC + cc)*NNT + n0 + tx;
        float xv = x[s];
        float hv = (__bfloat162float(g_c2b[s]) - stm[cc])*str[cc] + xv;
        xs[cc*33 + tx] = xv;
        cs[cc*34 + tx] = __float2bfloat16(hv >= 0.f ? hv : 0.01f*hv);
    }
    __syncthreads();
    float pacc[8];
    #pragma unroll
    for (int j = 0; j < 8; ++j) pacc[j] = 0.f;
    for (int t8 = 0; t8 < 4; ++t8) {
        int tok = w + t8*8;
        const float* prow = pos + (size_t)(n0 + tok)*CC;
        float v1[8], v2[8];
        float s1 = 0.f, q1 = 0.f, s2 = 0.f, q2 = 0.f;
        #pragma unroll
        for (int q = 0; q < 4; ++q) {
            int c0 = lane*2 + q*64;
            float2 p2 = *(const float2*)(prow + c0);
            float ax = xs[c0*33 + tok] + p2.x;
            float ay = xs[(c0+1)*33 + tok] + p2.y;
            float dx = __bfloat162float(cs[c0*34 + tok]) + p2.x;
            float dy = __bfloat162float(cs[(c0+1)*34 + tok]) + p2.y;
            v1[q*2] = ax; v1[q*2+1] = ay;
            v2[q*2] = dx; v2[q*2+1] = dy;
            s1 += ax + ay; q1 += ax*ax + ay*ay;
            s2 += dx + dy; q2 += dx*dx + dy*dy;
        }
        #pragma unroll
        for (int o = 16; o; o >>= 1) {
            s1 += __shfl_xor_sync(0xffffffffu, s1, o);
            q1 += __shfl_xor_sync(0xffffffffu, q1, o);
            s2 += __shfl_xor_sync(0xffffffffu, s2, o);
            q2 += __shfl_xor_sync(0xffffffffu, q2, o);
        }
        float m1 = s1*(1.f/CC), r1 = rsqrtf(q1*(1.f/CC) - m1*m1 + 1e-5f);
        float m2 = s2*(1.f/CC), r2 = rsqrtf(q2*(1.f/CC) - m2*m2 + 1e-5f);
        float wpt = wp[n0 + tok];
        size_t gbase = ((size_t)b*NNT + n0 + tok)*CC;
        #pragma unroll
        for (int q = 0; q < 4; ++q) {
            int c0 = lane*2 + q*64;
            float o1x = (v1[q*2]   - m1)*r1*lgs[c0]   + lbs[c0];
            float o1y = (v1[q*2+1] - m1)*r1*lgs[c0+1] + lbs[c0+1];
            float o2x = (v2[q*2]   - m2)*r2*lgs[c0]   + lbs[c0];
            float o2y = (v2[q*2+1] - m2)*r2*lgs[c0+1] + lbs[c0+1];
            *(__nv_bfloat162*)&g_xt_bf [gbase + c0] = __floats2bfloat162_rn(o1x, o1y);
            *(__nv_bfloat162*)&g_xct_bf[gbase + c0] = __floats2bfloat162_rn(o2x, o2y);
            xs[c0*33 + tok]     = o1x;
            xs[(c0+1)*33 + tok] = o1y;
            pacc[q*2]   += o2x*wpt;
            pacc[q*2+1] += o2y*wpt;
        }
    }
    __syncthreads();
    float* pws = (float*)cs;
    #pragma unroll
    for (int q = 0; q < 4; ++q) {
        int c0 = lane*2 + q*64;
        *(float2*)&pws[w*256 + c0] = make_float2(pacc[q*2], pacc[q*2+1]);
    }
    __syncthreads();
    {
        float s = 0.f;
        #pragma unroll
        for (int ww = 0; ww < 8; ++ww) s += pws[ww*256 + tid];
        atomicAdd(&g_zero[ZOFF_POOL + b*256 + tid], s);
    }
    for (int cc = ty; cc < 256; cc += 8)
        dout[(size_t)(b*CC + cc)*NNT + n0 + tx] = xs[cc*33 + tx];
}

__global__ void k_gate(const float* __restrict__ bp, const float* __restrict__ w1,
                       const float* __restrict__ w2)
{
    __shared__ float ps[256], hs[64];
    int b = blockIdx.x, t = threadIdx.x;
    ps[t] = g_zero[ZOFF_POOL + b*CC + t] + bp[0];
    __syncthreads();
    if (t < 64) {
        float a = 0.f;
        for (int c = 0; c < 256; ++c) a += ps[c]*w1[c*64 + t];
        hs[t] = fmaxf(a, 0.f);
    }
    __syncthreads();
    float a = 0.f;
    for (int j = 0; j < 64; ++j) a += hs[j]*w2[j*256 + t];
    g_gate[b*CC + t] = 1.f/(1.f + expf(-a));
}

// bf16 HMMA GEMM, K=64 chunks, cp.async double buffering, dynamic smem.
// doqss==1 (qkv launch): q blocks (n0<256) do qss + store; kv blocks (n0>=256)
// skip the global store and instead run the fused low-rank K/V projection.
#define AS_(st,r,c) smem_mma[(size_t)(st)*9216 + (r)*72 + (c)]
#define BS_(st,r,c) smem_mma[18432 + (size_t)(st)*8704 + (r)*136 + (c)]
__global__ __launch_bounds__(256) void k_mma(
    const __nv_bfloat16* __restrict__ A, const __nv_bfloat16* __restrict__ A2,
    const __nv_bfloat16* __restrict__ Bw, const __nv_bfloat16* __restrict__ Bw2,
    const float* __restrict__ bias, const float* __restrict__ bias2,
    const float* __restrict__ gate,
    __nv_bfloat16* __restrict__ Cb, int Nld, int ldc, int doqss,
    float* __restrict__ dout, const float* __restrict__ gfin)
{
    extern __shared__ __nv_bfloat16 smem_mma[];
    int tid = threadIdx.x;
    int wid = tid >> 5, lane = tid & 31;
    int wm = wid >> 2;
    int wn = wid & 3;
    int m0 = blockIdx.y * 128;
    int n0 = blockIdx.x * 128;
    int coff = 0;
    const float* grow = nullptr;
    if (blockIdx.z == 1) {
        A = A2; Bw = Bw2; bias = bias2; coff = 128;
        grow = gate + (m0 / NNT)*CC;
    }

    float acc[4][4][4] = {};

    #pragma unroll
    for (int p = 0; p < 4; ++p) {
        int idx = p*256 + tid; int r = idx >> 3, sg = idx & 7;
        cpa16(&AS_(0, r, sg*8), A + (size_t)(m0 + r)*256 + sg*8);
    }
    #pragma unroll
    for (int p = 0; p < 4; ++p) {
        int idx = p*256 + tid; int r = idx >> 4, sg = idx & 15;
        cpa16(&BS_(0, r, sg*8), Bw + (size_t)r*Nld + n0 + sg*8);
    }
    cp_commit();

    for (int it = 0; it < 4; ++it) {
        int k0 = it*64, st = it & 1;
        if (it < 3) {
            int kn = k0 + 64, sn = st ^ 1;
            #pragma unroll
            for (int p = 0; p < 4; ++p) {
                int idx = p*256 + tid; int r = idx >> 3, sg = idx & 7;
                cpa16(&AS_(sn, r, sg*8), A + (size_t)(m0 + r)*256 + kn + sg*8);
            }
            #pragma unroll
            for (int p = 0; p < 4; ++p) {
                int idx = p*256 + tid; int r = idx >> 4, sg = idx & 15;
                cpa16(&BS_(sn, r, sg*8), Bw + (size_t)(kn + r)*Nld + n0 + sg*8);
            }
            cp_commit();
            cp_wait<1>();
        } else {
            cp_wait<0>();
        }
        __syncthreads();
        if (grow) {
            #pragma unroll
            for (int p = 0; p < 4; ++p) {
                int idx = p*256 + tid; int r = idx >> 3, sg = idx & 7;
                __nv_bfloat16* qp = &AS_(st, r, sg*8);
                #pragma unroll
                for (int j = 0; j < 8; ++j)
                    qp[j] = __float2bfloat16(__bfloat162float(qp[j])*grow[k0+sg*8+j]);
            }
            __syncthreads();
        }
        #pragma unroll
        for (int kk = 0; kk < 4; ++kk) {
            unsigned int af[4][4];
            #pragma unroll
            for (int mt = 0; mt < 4; ++mt)
                ldm_x4(af[mt], &AS_(st, wm*64 + mt*16 + (lane & 15), kk*16 + (lane >> 4)*8));
            unsigned int bfr[2][4];
            #pragma unroll
            for (int g2 = 0; g2 < 2; ++g2)
                ldm_x4_t(bfr[g2], &BS_(st, kk*16 + (lane & 15), wn*32 + g2*16 + (lane >> 4)*8));
            #pragma unroll
            for (int mt = 0; mt < 4; ++mt)
                #pragma unroll
                for (int nt = 0; nt < 4; ++nt)
                    mma16816(acc[mt][nt], af[mt],
                             bfr[nt>>1][(nt&1)*2], bfr[nt>>1][(nt&1)*2+1]);
        }
        __syncthreads();
    }
    if (doqss && n0 < 256) {
        int b = m0 / NNT;
        #pragma unroll
        for (int nt = 0; nt < 4; ++nt) {
            float s0 = 0.f, s1 = 0.f;
            #pragma unroll
            for (int mt = 0; mt < 4; ++mt) {
                #pragma unroll
                for (int h = 0; h < 2; ++h) {
                    float a0 = acc[mt][nt][h*2+0], a1 = acc[mt][nt][h*2+1];
                    s0 += a0*a0; s1 += a1*a1;
                }
            }
            #pragma unroll
            for (int o = 4; o <= 16; o <<= 1) {
                s0 += __shfl_xor_sync(0xffffffffu, s0, o);
                s1 += __shfl_xor_sync(0xffffffffu, s1, o);
            }
            if ((lane >> 2) == 0) {
                int col = n0 + wn*32 + nt*8 + (lane & 3)*2;
                atomicAdd(&g_zero[ZOFF_QSS + b*256 + col],   s0);
                atomicAdd(&g_zero[ZOFF_QSS + b*256 + col+1], s1);
            }
        }
    }
    if (doqss && n0 >= 256) {
        // fused low-rank K/V projection: out[d][p] += C^T[d][tok] @ we[tok][p]
        __nv_bfloat16* Cs = smem_mma;                 // [128][136] bf16 (34816 B)
        __nv_bfloat16* Es = smem_mma + 17408;         // [128][72]  bf16 (18432 B)
        int b = m0 / NNT;
        int n0t = m0 % NNT;
        int which = (n0 >= 512) ? 1 : 0;
        int dbase = n0 - 256 - which*256;
        // C tile -> smem, bf16 (same rounding the old global store had)
        #pragma unroll
        for (int mt = 0; mt < 4; ++mt) {
            int row0 = wm*64 + mt*16 + (lane >> 2);
            #pragma unroll
            for (int nt = 0; nt < 4; ++nt) {
                int col = wn*32 + nt*8 + (lane & 3)*2;
                #pragma unroll
                for (int h = 0; h < 2; ++h)
                    *(__nv_bfloat162*)&Cs[(row0 + h*8)*136 + col] =
                        __floats2bfloat162_rn(acc[mt][nt][h*2+0], acc[mt][nt][h*2+1]);
            }
        }
        // we tile [128 tok][64 p]
        #pragma unroll
        for (int p = 0; p < 4; ++p) {
            int idx = p*256 + tid; int r = idx >> 3, sg = idx & 7;
            *(uint4*)&Es[r*72 + sg*8] =
                *(const uint4*)(g_we_bf + (size_t)(n0t + r)*64 + sg*8);
        }
        __syncthreads();
        float a2[8][4] = {};
        #pragma unroll
        for (int kk = 0; kk < 128; kk += 16) {
            unsigned int af[4];
            ldm_x4_t(af, &Cs[(kk + (lane & 7) + ((lane >> 4) << 3))*136
                             + wid*16 + ((lane >> 3) & 1)*8]);
            unsigned int bfr[4][4];
            #pragma unroll
            for (int ng = 0; ng < 4; ++ng)
                ldm_x4_t(bfr[ng], &Es[(kk + (lane & 15))*72 + ng*16 + (lane >> 4)*8]);
            #pragma unroll
            for (int nt = 0; nt < 8; ++nt)
                mma16816(a2[nt], af, bfr[nt>>1][(nt&1)*2], bfr[nt>>1][(nt&1)*2+1]);
        }
        float* out = &g_zero[ZOFF_KP + which*32768 + b*16384];
        int m = dbase + wid*16 + (lane >> 2);
        #pragma unroll
        for (int nt = 0; nt < 8; ++nt) {
            int p = nt*8 + (lane & 3)*2;
            atomicAdd(&out[m*64 + p],       a2[nt][0]);
            atomicAdd(&out[m*64 + p + 1],   a2[nt][1]);
            atomicAdd(&out[(m+8)*64 + p],   a2[nt][2]);
            atomicAdd(&out[(m+8)*64 + p+1], a2[nt][3]);
        }
        return;
    }
    if (gfin) {
        float* ts = (float*)smem_mma;
        const int TS = 132;
        int b = m0 / NNT;
        int n0t = m0 % NNT;
        #pragma unroll 1
        for (int q = 0; q < 4; ++q) {
            __syncthreads();
            if (wn == q) {
                #pragma unroll
                for (int mt = 0; mt < 4; ++mt) {
                    #pragma unroll
                    for (int nt = 0; nt < 4; ++nt) {
                        int ll = nt*8 + (lane & 3)*2;
                        float gm0 = gfin[coff + q*32 + ll];
                        float gm1 = gfin[coff + q*32 + ll + 1];
                        float b0 = bias[q*32 + ll], b1 = bias[q*32 + ll + 1];
                        #pragma unroll
                        for (int h = 0; h < 2; ++h) {
                            int rr = wm*64 + mt*16 + (lane >> 2) + h*8;
                            ts[ll*TS + rr]     = (acc[mt][nt][h*2+0] + b0)*gm0;
                            ts[(ll+1)*TS + rr] = (acc[mt][nt][h*2+1] + b1)*gm1;
                        }
                    }
                }
            }
            __syncthreads();
            #pragma unroll
            for (int r = 0; r < 4; ++r) {
                int l2 = wid*4 + r;
                int c = coff + q*32 + l2;
                float* dp = dout + (size_t)(b*CC + c)*NNT + n0t;
                float4 dv = *(float4*)(dp + lane*4);
                dv.x += ts[l2*TS + lane*4 + 0];
                dv.y += ts[l2*TS + lane*4 + 1];
                dv.z += ts[l2*TS + lane*4 + 2];
                dv.w += ts[l2*TS + lane*4 + 3];
                *(float4*)(dp + lane*4) = dv;
            }
        }
        return;
    }
    #pragma unroll
    for (int mt = 0; mt < 4; ++mt) {
        int row0 = m0 + wm*64 + mt*16 + (lane >> 2);
        #pragma unroll
        for (int nt = 0; nt < 4; ++nt) {
            int col = wn*32 + nt*8 + (lane & 3)*2;
            #pragma unroll
            for (int h = 0; h < 2; ++h) {
                int r = row0 + h*8;
                float v0 = acc[mt][nt][h*2+0];
                float v1 = acc[mt][nt][h*2+1];
                if (bias) { v0 += bias[n0+col]; v1 += bias[n0+col+1]; }
                __nv_bfloat16* p = Cb + (size_t)r*ldc + coff + n0 + col;
                p[0] = __float2bfloat16(v0); p[1] = __float2bfloat16(v1);
            }
        }
    }
}

// fused attention tile (HMMA both GEMMs), scrambled bf16 store (unchanged)
__global__ __launch_bounds__(256) void k_attn(const float* __restrict__ be,
                                              const float* __restrict__ temp)
{
    int bh = blockIdx.y; int b = bh >> 2, h = bh & 3;
    int n0 = blockIdx.x*64;
    __shared__ __align__(16) __nv_bfloat16 sA[64][72];
    __shared__ __align__(16) __nv_bfloat16 sB[64][72];
    __shared__ float ss[64][68];
    __shared__ float qr[64];
    int tid = threadIdx.x;
    int wid = tid >> 5, lane = tid & 31;
    int wm = wid & 1, wn = wid >> 1;
    const float* kbase = &g_zero[ZOFF_KP + bh*4096];
    const float* vbase = &g_zero[ZOFF_VP + bh*4096];

    if (tid < 64)
        qr[tid] = 1.f / fmaxf(sqrtf(g_zero[ZOFF_QSS + b*256 + h*64 + tid]), 1e-12f);
    #pragma unroll
    for (int v = 0; v < 4; ++v) {
        int i4 = v*256 + tid; int d = i4 >> 4, pp = (i4 & 15)*4;
        float4 kv = *(const float4*)(kbase + d*64 + pp);
        sB[d][pp]   = __float2bfloat16(kv.x + be[pp]);
        sB[d][pp+1] = __float2bfloat16(kv.y + be[pp+1]);
        sB[d][pp+2] = __float2bfloat16(kv.z + be[pp+2]);
        sB[d][pp+3] = __float2bfloat16(kv.w + be[pp+3]);
    }
    __syncthreads();
    #pragma unroll
    for (int l = 0; l < 2; ++l) {
        int i8 = l*256 + tid; int r = i8 >> 3, sg = (i8 & 7)*8;
        uint4 v = *(const uint4*)(g_qkv_bf + ((size_t)(b*NNT + n0 + r))*768 + h*64 + sg);
        const __nv_bfloat162* hh = (const __nv_bfloat162*)&v;
        __nv_bfloat16 outv[8];
        #pragma unroll
        for (int j = 0; j < 4; ++j) {
            float2 f = __bfloat1622float2(hh[j]);
            outv[j*2]   = __float2bfloat16(f.x * qr[sg + j*2]);
            outv[j*2+1] = __float2bfloat16(f.y * qr[sg + j*2+1]);
        }
        *(uint4*)&sA[r][sg] = *(uint4*)outv;
    }
    __syncthreads();
    float acc1[2][2][4] = {};
    #pragma unroll
    for (int kk = 0; kk < 64; kk += 16) {
        unsigned int af[2][4];
        #pragma unroll
        for (int mt = 0; mt < 2; ++mt)
            ldm_x4(af[mt], &sA[wm*32 + mt*16 + (lane & 15)][kk + (lane >> 4)*8]);
        unsigned int bfr[4];
        ldm_x4_t(bfr, &sB[kk + (lane & 15)][wn*16 + (lane >> 4)*8]);
        #pragma unroll
        for (int mt = 0; mt < 2; ++mt)
            #pragma unroll
            for (int nt = 0; nt < 2; ++nt)
                mma16816(acc1[mt][nt], af[mt], bfr[nt*2], bfr[nt*2+1]);
    }
    float ts = temp[h];
    #pragma unroll
    for (int mt = 0; mt < 2; ++mt) {
        int r = wm*32 + mt*16 + (lane >> 2);
        #pragma unroll
        for (int nt = 0; nt < 2; ++nt) {
            int c = wn*16 + nt*8 + (lane & 3)*2;
            ss[r][c]     = acc1[mt][nt][0]*ts;
            ss[r][c+1]   = acc1[mt][nt][1]*ts;
            ss[r+8][c]   = acc1[mt][nt][2]*ts;
            ss[r+8][c+1] = acc1[mt][nt][3]*ts;
        }
    }
    __syncthreads();
    #pragma unroll
    for (int v = 0; v < 4; ++v) {
        int i4 = v*256 + tid; int d = i4 >> 4, pp = (i4 & 15)*4;
        float4 vv = *(const float4*)(vbase + d*64 + pp);
        sA[d][pp]   = __float2bfloat16(vv.x + be[pp]);
        sA[d][pp+1] = __float2bfloat16(vv.y + be[pp+1]);
        sA[d][pp+2] = __float2bfloat16(vv.z + be[pp+2]);
        sA[d][pp+3] = __float2bfloat16(vv.w + be[pp+3]);
    }
    {
        int row = tid >> 2, g4 = (tid & 3)*16;
        float e[16];
        float mx = -1e30f;
        #pragma unroll
        for (int p = 0; p < 16; ++p) { e[p] = ss[row][g4+p]; mx = fmaxf(mx, e[p]); }
        mx = fmaxf(mx, __shfl_xor_sync(0xffffffffu, mx, 1));
        mx = fmaxf(mx, __shfl_xor_sync(0xffffffffu, mx, 2));
        float sum = 0.f;
        #pragma unroll
        for (int p = 0; p < 16; ++p) { e[p] = __expf(e[p] - mx); sum += e[p]; }
        sum += __shfl_xor_sync(0xffffffffu, sum, 1);
        sum += __shfl_xor_sync(0xffffffffu, sum, 2);
        float inv = 1.f/sum;
        #pragma unroll
        for (int p = 0; p < 16; ++p)
            sB[g4+p][row] = __float2bfloat16(e[p]*inv);
    }
    __syncthreads();
    float acc2[2][2][4] = {};
    #pragma unroll
    for (int kk = 0; kk < 64; kk += 16) {
        unsigned int af[2][4];
        #pragma unroll
        for (int mt = 0; mt < 2; ++mt)
            ldm_x4(af[mt], &sA[wm*32 + mt*16 + (lane & 15)][kk + (lane >> 4)*8]);
        unsigned int bfr[4];
        ldm_x4_t(bfr, &sB[kk + (lane & 15)][wn*16 + (lane >> 4)*8]);
        #pragma unroll
        for (int mt = 0; mt < 2; ++mt)
            #pragma unroll
            for (int nt = 0; nt < 2; ++nt)
                mma16816(acc2[mt][nt], af[mt], bfr[nt*2], bfr[nt*2+1]);
    }
    __nv_bfloat16* sabase = g_sa_bf + (size_t)b*NNT*CC;
    #pragma unroll
    for (int mt = 0; mt < 2; ++mt) {
        int d0 = wm*32 + mt*16 + (lane >> 2);
        #pragma unroll
        for (int nt = 0; nt < 2; ++nt) {
            int nc = n0 + wn*16 + nt*8 + (lane & 3)*2;
            *(__nv_bfloat162*)&sabase[(size_t)(d0*4 + h)*NNT + nc] =
                __floats2bfloat162_rn(acc2[mt][nt][0], acc2[mt][nt][1]);
            *(__nv_bfloat162*)&sabase[(size_t)((d0+8)*4 + h)*NNT + nc] =
                __floats2bfloat162_rn(acc2[mt][nt][2], acc2[mt][nt][3]);
        }
    }
}

// ---------------- launch ----------------
extern "C" void kernel_launch(void* const* d_in, const int* in_sizes, int n_in,
                              void* d_out, int out_size)
{
    const float* x      = (const float*)d_in[0];
    const float* pos    = (const float*)d_in[1];
    const float* ln_g   = (const float*)d_in[2];
    const float* ln_b   = (const float*)d_in[3];
    const float* gamma  = (const float*)d_in[4];
    const float* temp2  = (const float*)d_in[5];
    const float* w_qkv  = (const float*)d_in[6];
    const float* w_e    = (const float*)d_in[7];
    const float* b_e    = (const float*)d_in[8];
    const float* w_pool = (const float*)d_in[9];
    const float* b_pool = (const float*)d_in[10];
    const float* w_fc1  = (const float*)d_in[11];
    const float* w_fc2  = (const float*)d_in[12];
    const float* b_out1 = (const float*)d_in[14];
    const float* b_out2 = (const float*)d_in[16];
    const float* w_c1   = (const float*)d_in[17];
    const float* b_c1   = (const float*)d_in[18];
    const float* w_c2   = (const float*)d_in[19];
    const float* b_c2   = (const float*)d_in[20];

    __nv_bfloat16 *p_h1b, *p_c2b, *p_xtbf, *p_xctbf, *p_sabf;
    __nv_bfloat16 *p_wq, *p_w1, *p_w2, *p_qkvbf;
    float *p_gate, *p_zero;
    cudaGetSymbolAddress((void**)&p_h1b,   g_h1b);
    cudaGetSymbolAddress((void**)&p_c2b,   g_c2b);
    cudaGetSymbolAddress((void**)&p_xtbf,  g_xt_bf);
    cudaGetSymbolAddress((void**)&p_xctbf, g_xct_bf);
    cudaGetSymbolAddress((void**)&p_qkvbf, g_qkv_bf);
    cudaGetSymbolAddress((void**)&p_sabf,  g_sa_bf);
    cudaGetSymbolAddress((void**)&p_wq,    g_wqkv_bf);
    cudaGetSymbolAddress((void**)&p_w1,    g_wo1_bf);
    cudaGetSymbolAddress((void**)&p_w2,    g_wo2_bf);
    cudaGetSymbolAddress((void**)&p_gate,  g_gate);
    cudaGetSymbolAddress((void**)&p_zero,  g_zero);

    static int s_attr_done = 0;
    if (!s_attr_done) {
        cudaFuncSetAttribute(k_megaln,
            cudaFuncAttributeMaxDynamicSharedMemorySize, 55296);
        cudaFuncSetAttribute(k_mma,
            cudaFuncAttributeMaxDynamicSharedMemorySize, 71680);
        s_attr_done = 1;
    }

    k_init <<<3456, 256>>>(w_qkv, (const float*)d_in[13],
                           (const float*)d_in[15], w_e);
    // MHCResBlock: grouped convs via HMMA with fused stats
    k_convmma<<<dim3(27,16), 256>>>(x, (const __nv_bfloat16*)0, w_c1, b_c1, p_h1b,
                                    (const float*)0, (const float*)0,
                                    p_zero + ZOFF_CS1S, p_zero + ZOFF_CS1Q);
    k_convmma<<<dim3(27,16), 256>>>((const float*)0, p_h1b, w_c2, b_c2, p_c2b,
                                    p_zero + ZOFF_CS1S, p_zero + ZOFF_CS1Q,
                                    p_zero + ZOFF_CS2S, p_zero + ZOFF_CS2Q);
    // mega-fused transpose + xc + double-LN + pool + d_out(x_n)
    k_megaln<<<dim3(432, BB), 256, 55296>>>(x, pos, ln_g, ln_b, w_pool,
                                            (float*)d_out);
    // channel-attention gate
    k_gate <<<BB, 256>>>(b_pool, w_fc1, w_fc2);
    // qkv (pipelined bf16 HMMA, fused q sum-squares + fused K/V low-rank proj)
    k_mma  <<<dim3(6,216,1), 256, 71680>>>(p_xtbf, (const __nv_bfloat16*)0, p_wq,
                                    (const __nv_bfloat16*)0, (const float*)0,
                                    (const float*)0, (const float*)0,
                                    p_qkvbf, 768, 768, 1,
                                    (float*)0, (const float*)0);
    // spatial attention
    k_attn <<<dim3(216, BB*NHH), 256>>>(b_e, temp2);
    // both output projections with fused gamma-residual into d_out
    k_mma  <<<dim3(1,216,2), 256, 71680>>>(p_sabf, p_xctbf, p_w1, p_w2,
                                    b_out1, b_out2, p_gate,
                                    (__nv_bfloat16*)0, 128, 256, 0,
                                    (float*)d_out, gamma);
}

// round 13
// speedup vs baseline: 4.9656x; 1.0923x over previous
#include <cuda_runtime.h>
#include <cuda_bf16.h>
#include <cstdint>
#include <math.h>

#define BB 2
#define CC 256
#define NNT 13824
#define NHH 4
#define MTOT (BB*NNT)

// ---------------- scratch ----------------
__device__ __nv_bfloat16 g_h1b[BB*CC*NNT];
__device__ __nv_bfloat16 g_c2b[BB*CC*NNT];
__device__ __nv_bfloat16 g_xt_bf [BB*NNT*CC];
__device__ __nv_bfloat16 g_xct_bf[BB*NNT*CC];
__device__ __nv_bfloat16 g_qkv_bf[(size_t)BB*NNT*768];
__device__ __nv_bfloat16 g_sa_bf [BB*NNT*CC];
__device__ __nv_bfloat16 g_wqkv_bf[256*768];
__device__ __nv_bfloat16 g_wo1_bf [256*128];
__device__ __nv_bfloat16 g_wo2_bf [256*128];
__device__ __nv_bfloat16 g_we_bf  [NNT*64];
#define ZOFF_POOL 0
#define ZOFF_QSS  512
#define ZOFF_CS1S 1024
#define ZOFF_CS1Q 1536
#define ZOFF_CS2S 2048
#define ZOFF_CS2Q 2560
#define ZOFF_KP   3072
#define ZOFF_VP   35840
#define ZTOT      68608
__device__ float g_zero[ZTOT];
__device__ float g_gate[BB*CC];

// ---------------- asm helpers ----------------
__device__ __forceinline__ void ldm_x4(unsigned int (&r)[4], const void* p) {
    unsigned int a = (unsigned int)__cvta_generic_to_shared(p);
    asm volatile("ldmatrix.sync.aligned.m8n8.x4.shared.b16 {%0,%1,%2,%3}, [%4];"
        : "=r"(r[0]),"=r"(r[1]),"=r"(r[2]),"=r"(r[3]) : "r"(a));
}
__device__ __forceinline__ void ldm_x4_t(unsigned int (&r)[4], const void* p) {
    unsigned int a = (unsigned int)__cvta_generic_to_shared(p);
    asm volatile("ldmatrix.sync.aligned.m8n8.x4.trans.shared.b16 {%0,%1,%2,%3}, [%4];"
        : "=r"(r[0]),"=r"(r[1]),"=r"(r[2]),"=r"(r[3]) : "r"(a));
}
__device__ __forceinline__ void mma16816(float (&d)[4], const unsigned int (&a)[4],
                                         unsigned int b0, unsigned int b1) {
    asm volatile("mma.sync.aligned.m16n8k16.row.col.f32.bf16.bf16.f32 "
        "{%0,%1,%2,%3},{%4,%5,%6,%7},{%8,%9},{%0,%1,%2,%3};"
        : "+f"(d[0]),"+f"(d[1]),"+f"(d[2]),"+f"(d[3])
        : "r"(a[0]),"r"(a[1]),"r"(a[2]),"r"(a[3]),"r"(b0),"r"(b1));
}
__device__ __forceinline__ void cpa16(void* dst, const void* src) {
    unsigned int d = (unsigned int)__cvta_generic_to_shared(dst);
    asm volatile("cp.async.cg.shared.global [%0], [%1], 16;" :: "r"(d), "l"(src));
}
__device__ __forceinline__ void cp_commit() { asm volatile("cp.async.commit_group;"); }
template<int N> __device__ __forceinline__ void cp_wait() {
    asm volatile("cp.async.wait_group %0;" :: "n"(N));
}

// ---------------- kernels ----------------
__global__ void k_init(const float* __restrict__ wq, const float* __restrict__ w1,
                       const float* __restrict__ w2, const float* __restrict__ we)
{
    int i = blockIdx.x*256 + threadIdx.x;
    if (i < ZTOT) g_zero[i] = 0.f;
    if (i < 196608) g_wqkv_bf[i] = __float2bfloat16(wq[i]);
    if (i < 32768)  { g_wo1_bf[i] = __float2bfloat16(w1[i]);
                      g_wo2_bf[i] = __float2bfloat16(w2[i]); }
    if (i < NNT*64) g_we_bf[i] = __float2bfloat16(we[i]);
}

// grouped 1x1x1 conv via HMMA (unchanged)
__global__ __launch_bounds__(256) void k_convmma(
    const float* __restrict__ srcf, const __nv_bfloat16* __restrict__ srcb,
    const float* __restrict__ w, const float* __restrict__ bias,
    __nv_bfloat16* __restrict__ dst,
    const float* __restrict__ sin_s, const float* __restrict__ sin_q,
    float* __restrict__ sout_s, float* __restrict__ sout_q)
{
    __shared__ __align__(16) __nv_bfloat16 Ws[32][40];
    __shared__ __align__(16) __nv_bfloat16 Bs[32][520];
    __shared__ float sm[32], sr[32], bss[32];
    __shared__ float sst[8][32][2];
    int bg = blockIdx.y; int b = bg >> 3; int g = bg & 7;
    int n0 = blockIdx.x*512;
    int tid = threadIdx.x, lane = tid & 31, wid = tid >> 5;
    int cbase = b*CC + g*32;

    #pragma unroll
    for (int p = 0; p < 4; ++p) {
        int idx = p*256 + tid;
        Ws[idx & 31][idx >> 5] = __float2bfloat16(w[g*1024 + idx]);
    }
    if (tid < 32) {
        bss[tid] = bias[g*32 + tid];
        if (srcb) {
            float s = sin_s[cbase+tid], q = sin_q[cbase+tid];
            float m = s*(1.f/NNT);
            sm[tid] = m;
            sr[tid] = rsqrtf(q*(1.f/NNT) - m*m + 1e-5f);
        }
    }
    __syncthreads();

    if (srcf) {
        #pragma unroll
        for (int p = 0; p < 16; ++p) {
            int idx = p*256 + tid;
            int row = idx >> 7, cq = idx & 127;
            float4 v = *(const float4*)(srcf + (size_t)(cbase+row)*NNT + n0 + cq*4);
            *(__nv_bfloat162*)&Bs[row][cq*4]   = __floats2bfloat162_rn(v.x, v.y);
            *(__nv_bfloat162*)&Bs[row][cq*4+2] = __floats2bfloat162_rn(v.z, v.w);
        }
    } else {
        #pragma unroll
        for (int p = 0; p < 8; ++p) {
            int idx = p*256 + tid;
            int row = idx >> 6, sg = idx & 63;
            uint4 v = *(const uint4*)(srcb + (size_t)(cbase+row)*NNT + n0 + sg*8);
            const __nv_bfloat162* hh = (const __nv_bfloat162*)&v;
            float m = sm[row], r = sr[row];
            __nv_bfloat16 o[8];
            #pragma unroll
            for (int j = 0; j < 4; ++j) {
                float2 f = __bfloat1622float2(hh[j]);
                float fx = (f.x - m)*r; fx = fx >= 0.f ? fx : 0.01f*fx;
                float fy = (f.y - m)*r; fy = fy >= 0.f ? fy : 0.01f*fy;
                *(__nv_bfloat162*)&o[j*2] = __floats2bfloat162_rn(fx, fy);
            }
            *(uint4*)&Bs[row][sg*8] = *(uint4*)o;
        }
    }
    __syncthreads();

    float acc[2][8][4] = {};
    #pragma unroll
    for (int kk = 0; kk < 2; ++kk) {
        unsigned int af[2][4];
        #pragma unroll
        for (int mt = 0; mt < 2; ++mt)
            ldm_x4(af[mt], &Ws[mt*16 + (lane & 15)][kk*16 + (lane >> 4)*8]);
        unsigned int bfr[4][4];
        #pragma unroll
        for (int ng = 0; ng < 4; ++ng)
            ldm_x4_t(bfr[ng], &Bs[kk*16 + (lane & 15)][wid*64 + ng*16 + (lane >> 4)*8]);
        #pragma unroll
        for (int mt = 0; mt < 2; ++mt)
            #pragma unroll
            for (int nt = 0; nt < 8; ++nt)
                mma16816(acc[mt][nt], af[mt],
                         bfr[nt>>1][(nt&1)*2], bfr[nt>>1][(nt&1)*2+1]);
    }

    float ssum[2][2] = {}, ssq[2][2] = {};
    #pragma unroll
    for (int mt = 0; mt < 2; ++mt) {
        #pragma unroll
        for (int h = 0; h < 2; ++h) {
            int oc = mt*16 + (lane >> 2) + h*8;
            float bv = bss[oc];
            __nv_bfloat16* drow = dst + (size_t)(cbase+oc)*NNT + n0 + wid*64;
            #pragma unroll
            for (int nt = 0; nt < 8; ++nt) {
                float v0 = acc[mt][nt][h*2+0] + bv;
                float v1 = acc[mt][nt][h*2+1] + bv;
                *(__nv_bfloat162*)&drow[nt*8 + (lane & 3)*2] =
                    __floats2bfloat162_rn(v0, v1);
                ssum[mt][h] += v0 + v1;
                ssq [mt][h] += v0*v0 + v1*v1;
            }
        }
    }
    #pragma unroll
    for (int mt = 0; mt < 2; ++mt)
        #pragma unroll
        for (int h = 0; h < 2; ++h) {
            float s = ssum[mt][h], q = ssq[mt][h];
            s += __shfl_xor_sync(0xffffffffu, s, 1);
            q += __shfl_xor_sync(0xffffffffu, q, 1);
            s += __shfl_xor_sync(0xffffffffu, s, 2);
            q += __shfl_xor_sync(0xffffffffu, q, 2);
            if ((lane & 3) == 0) {
                int oc = mt*16 + (lane >> 2) + h*8;
                sst[wid][oc][0] = s;
                sst[wid][oc][1] = q;
            }
        }
    __syncthreads();
    if (tid < 64) {
        int oc = tid & 31, which = tid >> 5;
        float s = 0.f;
        #pragma unroll
        for (int ww = 0; ww < 8; ++ww) s += sst[ww][oc][which];
        atomicAdd(&(which ? sout_q : sout_s)[cbase+oc], s);
    }
}

// mega-fused LN kernel; (mean,rstd) and (lg,lb) packed as float2 pairs.
__global__ __launch_bounds__(256) void k_megaln(
    const float* __restrict__ x, const float* __restrict__ pos,
    const float* __restrict__ lg, const float* __restrict__ lb,
    const float* __restrict__ wp, float* __restrict__ dout)
{
    extern __shared__ float dsm[];
    float*  xs  = dsm;                              // 8448 f32
    float2* st2 = (float2*)(dsm + 8448);            // 256 pairs (mean, rstd)
    float2* lgb = (float2*)(dsm + 8960);            // 256 pairs (lg, lb)
    __nv_bfloat16* cs = (__nv_bfloat16*)(dsm + 9472);
    int tid = threadIdx.x, tx = tid & 31, ty = tid >> 5;
    int lane = tid & 31, w = tid >> 5;
    int n0 = blockIdx.x*32, b = blockIdx.y;
    {
        float s = g_zero[ZOFF_CS2S + b*256 + tid];
        float q = g_zero[ZOFF_CS2Q + b*256 + tid];
        float m = s*(1.f/NNT);
        st2[tid] = make_float2(m, rsqrtf(q*(1.f/NNT) - m*m + 1e-5f));
        lgb[tid] = make_float2(lg[tid], lb[tid]);
    }
    __syncthreads();
    for (int cc = ty; cc < 256; cc += 8) {
        size_t s = (size_t)(b*CC + cc)*NNT + n0 + tx;
        float xv = x[s];
        float2 st = st2[cc];
        float hv = (__bfloat162float(g_c2b[s]) - st.x)*st.y + xv;
        xs[cc*33 + tx] = xv;
        cs[cc*34 + tx] = __float2bfloat16(hv >= 0.f ? hv : 0.01f*hv);
    }
    __syncthreads();
    float pacc[8];
    #pragma unroll
    for (int j = 0; j < 8; ++j) pacc[j] = 0.f;
    for (int t8 = 0; t8 < 4; ++t8) {
        int tok = w + t8*8;
        const float* prow = pos + (size_t)(n0 + tok)*CC;
        float v1[8], v2[8];
        float s1 = 0.f, q1 = 0.f, s2 = 0.f, q2 = 0.f;
        #pragma unroll
        for (int q = 0; q < 4; ++q) {
            int c0 = lane*2 + q*64;
            float2 p2 = *(const float2*)(prow + c0);
            float ax = xs[c0*33 + tok] + p2.x;
            float ay = xs[(c0+1)*33 + tok] + p2.y;
            float dx = __bfloat162float(cs[c0*34 + tok]) + p2.x;
            float dy = __bfloat162float(cs[(c0+1)*34 + tok]) + p2.y;
            v1[q*2] = ax; v1[q*2+1] = ay;
            v2[q*2] = dx; v2[q*2+1] = dy;
            s1 += ax + ay; q1 += ax*ax + ay*ay;
            s2 += dx + dy; q2 += dx*dx + dy*dy;
        }
        #pragma unroll
        for (int o = 16; o; o >>= 1) {
            s1 += __shfl_xor_sync(0xffffffffu, s1, o);
            q1 += __shfl_xor_sync(0xffffffffu, q1, o);
            s2 += __shfl_xor_sync(0xffffffffu, s2, o);
            q2 += __shfl_xor_sync(0xffffffffu, q2, o);
        }
        float m1 = s1*(1.f/CC), r1 = rsqrtf(q1*(1.f/CC) - m1*m1 + 1e-5f);
        float m2 = s2*(1.f/CC), r2 = rsqrtf(q2*(1.f/CC) - m2*m2 + 1e-5f);
        float wpt = wp[n0 + tok];
        size_t gbase = ((size_t)b*NNT + n0 + tok)*CC;
        #pragma unroll
        for (int q = 0; q < 4; ++q) {
            int c0 = lane*2 + q*64;
            float4 gb = *(const float4*)(lgb + c0);   // lg0,lb0,lg1,lb1
            float o1x = (v1[q*2]   - m1)*r1*gb.x + gb.y;
            float o1y = (v1[q*2+1] - m1)*r1*gb.z + gb.w;
            float o2x = (v2[q*2]   - m2)*r2*gb.x + gb.y;
            float o2y = (v2[q*2+1] - m2)*r2*gb.z + gb.w;
            *(__nv_bfloat162*)&g_xt_bf [gbase + c0] = __floats2bfloat162_rn(o1x, o1y);
            *(__nv_bfloat162*)&g_xct_bf[gbase + c0] = __floats2bfloat162_rn(o2x, o2y);
            xs[c0*33 + tok]     = o1x;
            xs[(c0+1)*33 + tok] = o1y;
            pacc[q*2]   += o2x*wpt;
            pacc[q*2+1] += o2y*wpt;
        }
    }
    __syncthreads();
    float* pws = (float*)cs;
    #pragma unroll
    for (int q = 0; q < 4; ++q) {
        int c0 = lane*2 + q*64;
        *(float2*)&pws[w*256 + c0] = make_float2(pacc[q*2], pacc[q*2+1]);
    }
    __syncthreads();
    {
        float s = 0.f;
        #pragma unroll
        for (int ww = 0; ww < 8; ++ww) s += pws[ww*256 + tid];
        atomicAdd(&g_zero[ZOFF_POOL + b*256 + tid], s);
    }
    for (int cc = ty; cc < 256; cc += 8)
        dout[(size_t)(b*CC + cc)*NNT + n0 + tx] = xs[cc*33 + tx];
}

// bf16 HMMA GEMM, K=64 chunks, cp.async double buffering, dynamic smem.
#define AS_(st,r,c) smem_mma[(size_t)(st)*9216 + (r)*72 + (c)]
#define BS_(st,r,c) smem_mma[18432 + (size_t)(st)*8704 + (r)*136 + (c)]
__global__ __launch_bounds__(256) void k_mma(
    const __nv_bfloat16* __restrict__ A, const __nv_bfloat16* __restrict__ A2,
    const __nv_bfloat16* __restrict__ Bw, const __nv_bfloat16* __restrict__ Bw2,
    const float* __restrict__ bias, const float* __restrict__ bias2,
    const float* __restrict__ gate,
    __nv_bfloat16* __restrict__ Cb, int Nld, int ldc, int doqss,
    float* __restrict__ dout, const float* __restrict__ gfin)
{
    extern __shared__ __nv_bfloat16 smem_mma[];
    int tid = threadIdx.x;
    int wid = tid >> 5, lane = tid & 31;
    int wm = wid >> 2;
    int wn = wid & 3;
    int m0 = blockIdx.y * 128;
    int n0 = blockIdx.x * 128;
    int coff = 0;
    const float* grow = nullptr;
    if (blockIdx.z == 1) {
        A = A2; Bw = Bw2; bias = bias2; coff = 128;
        grow = gate + (m0 / NNT)*CC;
    }

    float acc[4][4][4] = {};

    #pragma unroll
    for (int p = 0; p < 4; ++p) {
        int idx = p*256 + tid; int r = idx >> 3, sg = idx & 7;
        cpa16(&AS_(0, r, sg*8), A + (size_t)(m0 + r)*256 + sg*8);
    }
    #pragma unroll
    for (int p = 0; p < 4; ++p) {
        int idx = p*256 + tid; int r = idx >> 4, sg = idx & 15;
        cpa16(&BS_(0, r, sg*8), Bw + (size_t)r*Nld + n0 + sg*8);
    }
    cp_commit();

    for (int it = 0; it < 4; ++it) {
        int k0 = it*64, st = it & 1;
        if (it < 3) {
            int kn = k0 + 64, sn = st ^ 1;
            #pragma unroll
            for (int p = 0; p < 4; ++p) {
                int idx = p*256 + tid; int r = idx >> 3, sg = idx & 7;
                cpa16(&AS_(sn, r, sg*8), A + (size_t)(m0 + r)*256 + kn + sg*8);
            }
            #pragma unroll
            for (int p = 0; p < 4; ++p) {
                int idx = p*256 + tid; int r = idx >> 4, sg = idx & 15;
                cpa16(&BS_(sn, r, sg*8), Bw + (size_t)(kn + r)*Nld + n0 + sg*8);
            }
            cp_commit();
            cp_wait<1>();
        } else {
            cp_wait<0>();
        }
        __syncthreads();
        if (grow) {
            #pragma unroll
            for (int p = 0; p < 4; ++p) {
                int idx = p*256 + tid; int r = idx >> 3, sg = idx & 7;
                __nv_bfloat16* qp = &AS_(st, r, sg*8);
                #pragma unroll
                for (int j = 0; j < 8; ++j)
                    qp[j] = __float2bfloat16(__bfloat162float(qp[j])*grow[k0+sg*8+j]);
            }
            __syncthreads();
        }
        #pragma unroll
        for (int kk = 0; kk < 4; ++kk) {
            unsigned int af[4][4];
            #pragma unroll
            for (int mt = 0; mt < 4; ++mt)
                ldm_x4(af[mt], &AS_(st, wm*64 + mt*16 + (lane & 15), kk*16 + (lane >> 4)*8));
            unsigned int bfr[2][4];
            #pragma unroll
            for (int g2 = 0; g2 < 2; ++g2)
                ldm_x4_t(bfr[g2], &BS_(st, kk*16 + (lane & 15), wn*32 + g2*16 + (lane >> 4)*8));
            #pragma unroll
            for (int mt = 0; mt < 4; ++mt)
                #pragma unroll
                for (int nt = 0; nt < 4; ++nt)
                    mma16816(acc[mt][nt], af[mt],
                             bfr[nt>>1][(nt&1)*2], bfr[nt>>1][(nt&1)*2+1]);
        }
        __syncthreads();
    }
    if (doqss && n0 < 256) {
        int b = m0 / NNT;
        #pragma unroll
        for (int nt = 0; nt < 4; ++nt) {
            float s0 = 0.f, s1 = 0.f;
            #pragma unroll
            for (int mt = 0; mt < 4; ++mt) {
                #pragma unroll
                for (int h = 0; h < 2; ++h) {
                    float a0 = acc[mt][nt][h*2+0], a1 = acc[mt][nt][h*2+1];
                    s0 += a0*a0; s1 += a1*a1;
                }
            }
            #pragma unroll
            for (int o = 4; o <= 16; o <<= 1) {
                s0 += __shfl_xor_sync(0xffffffffu, s0, o);
                s1 += __shfl_xor_sync(0xffffffffu, s1, o);
            }
            if ((lane >> 2) == 0) {
                int col = n0 + wn*32 + nt*8 + (lane & 3)*2;
                atomicAdd(&g_zero[ZOFF_QSS + b*256 + col],   s0);
                atomicAdd(&g_zero[ZOFF_QSS + b*256 + col+1], s1);
            }
        }
    }
    if (doqss && n0 >= 256) {
        __nv_bfloat16* Cs = smem_mma;
        __nv_bfloat16* Es = smem_mma + 17408;
        int b = m0 / NNT;
        int n0t = m0 % NNT;
        int which = (n0 >= 512) ? 1 : 0;
        int dbase = n0 - 256 - which*256;
        #pragma unroll
        for (int mt = 0; mt < 4; ++mt) {
            int row0 = wm*64 + mt*16 + (lane >> 2);
            #pragma unroll
            for (int nt = 0; nt < 4; ++nt) {
                int col = wn*32 + nt*8 + (lane & 3)*2;
                #pragma unroll
                for (int h = 0; h < 2; ++h)
                    *(__nv_bfloat162*)&Cs[(row0 + h*8)*136 + col] =
                        __floats2bfloat162_rn(acc[mt][nt][h*2+0], acc[mt][nt][h*2+1]);
            }
        }
        #pragma unroll
        for (int p = 0; p < 4; ++p) {
            int idx = p*256 + tid; int r = idx >> 3, sg = idx & 7;
            *(uint4*)&Es[r*72 + sg*8] =
                *(const uint4*)(g_we_bf + (size_t)(n0t + r)*64 + sg*8);
        }
        __syncthreads();
        float a2[8][4] = {};
        #pragma unroll
        for (int kk = 0; kk < 128; kk += 16) {
            unsigned int af[4];
            ldm_x4_t(af, &Cs[(kk + (lane & 7) + ((lane >> 4) << 3))*136
                             + wid*16 + ((lane >> 3) & 1)*8]);
            unsigned int bfr[4][4];
            #pragma unroll
            for (int ng = 0; ng < 4; ++ng)
                ldm_x4_t(bfr[ng], &Es[(kk + (lane & 15))*72 + ng*16 + (lane >> 4)*8]);
            #pragma unroll
            for (int nt = 0; nt < 8; ++nt)
                mma16816(a2[nt], af, bfr[nt>>1][(nt&1)*2], bfr[nt>>1][(nt&1)*2+1]);
        }
        float* out = &g_zero[ZOFF_KP + which*32768 + b*16384];
        int m = dbase + wid*16 + (lane >> 2);
        #pragma unroll
        for (int nt = 0; nt < 8; ++nt) {
            int p = nt*8 + (lane & 3)*2;
            atomicAdd(&out[m*64 + p],       a2[nt][0]);
            atomicAdd(&out[m*64 + p + 1],   a2[nt][1]);
            atomicAdd(&out[(m+8)*64 + p],   a2[nt][2]);
            atomicAdd(&out[(m+8)*64 + p+1], a2[nt][3]);
        }
        return;
    }
    if (gfin) {
        // single-pass transpose epilogue: all warps, one barrier
        float* ts = (float*)smem_mma;          // 128 x 132 f32 = 67584 B
        const int TS = 132;
        int b = m0 / NNT;
        int n0t = m0 % NNT;
        #pragma unroll
        for (int nt = 0; nt < 4; ++nt) {
            int ll = wn*32 + nt*8 + (lane & 3)*2;
            float gm0 = gfin[coff + ll], gm1 = gfin[coff + ll + 1];
            float b0 = bias[ll], b1 = bias[ll + 1];
            #pragma unroll
            for (int mt = 0; mt < 4; ++mt) {
                #pragma unroll
                for (int h = 0; h < 2; ++h) {
                    int rr = wm*64 + mt*16 + (lane >> 2) + h*8;
                    ts[ll*TS + rr]     = (acc[mt][nt][h*2+0] + b0)*gm0;
                    ts[(ll+1)*TS + rr] = (acc[mt][nt][h*2+1] + b1)*gm1;
                }
            }
        }
        __syncthreads();
        #pragma unroll
        for (int r = 0; r < 16; ++r) {
            int c = wid*16 + r;
            float* dp = dout + (size_t)(b*CC + coff + c)*NNT + n0t;
            float4 dv = *(float4*)(dp + lane*4);
            dv.x += ts[c*TS + lane*4 + 0];
            dv.y += ts[c*TS + lane*4 + 1];
            dv.z += ts[c*TS + lane*4 + 2];
            dv.w += ts[c*TS + lane*4 + 3];
            *(float4*)(dp + lane*4) = dv;
        }
        return;
    }
    #pragma unroll
    for (int mt = 0; mt < 4; ++mt) {
        int row0 = m0 + wm*64 + mt*16 + (lane >> 2);
        #pragma unroll
        for (int nt = 0; nt < 4; ++nt) {
            int col = wn*32 + nt*8 + (lane & 3)*2;
            #pragma unroll
            for (int h = 0; h < 2; ++h) {
                int r = row0 + h*8;
                float v0 = acc[mt][nt][h*2+0];
                float v1 = acc[mt][nt][h*2+1];
                if (bias) { v0 += bias[n0+col]; v1 += bias[n0+col+1]; }
                __nv_bfloat16* p = Cb + (size_t)r*ldc + coff + n0 + col;
                p[0] = __float2bfloat16(v0); p[1] = __float2bfloat16(v1);
            }
        }
    }
}

// fused attention tile; block (0,0) additionally computes the CA gate.
__global__ __launch_bounds__(256) void k_attn(
    const float* __restrict__ be, const float* __restrict__ temp,
    const float* __restrict__ bp, const float* __restrict__ w1,
    const float* __restrict__ w2)
{
    int bh = blockIdx.y; int b = bh >> 2, h = bh & 3;
    int n0 = blockIdx.x*64;
    __shared__ __align__(16) __nv_bfloat16 sA[64][72];
    __shared__ __align__(16) __nv_bfloat16 sB[64][72];
    __shared__ float ss[64][68];
    __shared__ float qr[64];
    int tid = threadIdx.x;
    int wid = tid >> 5, lane = tid & 31;
    int wm = wid & 1, wn = wid >> 1;
    const float* kbase = &g_zero[ZOFF_KP + bh*4096];
    const float* vbase = &g_zero[ZOFF_VP + bh*4096];

    // fused CA gate (one block; block-uniform branch)
    if (blockIdx.x == 0 && blockIdx.y == 0) {
        float* ps = &ss[0][0];
        float* hs = ps + 256;
        for (int b2 = 0; b2 < BB; ++b2) {
            ps[tid] = g_zero[ZOFF_POOL + b2*CC + tid] + bp[0];
            __syncthreads();
            if (tid < 64) {
                float a = 0.f;
                for (int c = 0; c < 256; ++c) a += ps[c]*w1[c*64 + tid];
                hs[tid] = fmaxf(a, 0.f);
            }
            __syncthreads();
            float a = 0.f;
            for (int j = 0; j < 64; ++j) a += hs[j]*w2[j*256 + tid];
            g_gate[b2*CC + tid] = 1.f/(1.f + expf(-a));
            __syncthreads();
        }
    }

    if (tid < 64)
        qr[tid] = 1.f / fmaxf(sqrtf(g_zero[ZOFF_QSS + b*256 + h*64 + tid]), 1e-12f);
    #pragma unroll
    for (int v = 0; v < 4; ++v) {
        int i4 = v*256 + tid; int d = i4 >> 4, pp = (i4 & 15)*4;
        float4 kv = *(const float4*)(kbase + d*64 + pp);
        sB[d][pp]   = __float2bfloat16(kv.x + be[pp]);
        sB[d][pp+1] = __float2bfloat16(kv.y + be[pp+1]);
        sB[d][pp+2] = __float2bfloat16(kv.z + be[pp+2]);
        sB[d][pp+3] = __float2bfloat16(kv.w + be[pp+3]);
    }
    __syncthreads();
    #pragma unroll
    for (int l = 0; l < 2; ++l) {
        int i8 = l*256 + tid; int r = i8 >> 3, sg = (i8 & 7)*8;
        uint4 v = *(const uint4*)(g_qkv_bf + ((size_t)(b*NNT + n0 + r))*768 + h*64 + sg);
        const __nv_bfloat162* hh = (const __nv_bfloat162*)&v;
        __nv_bfloat16 outv[8];
        #pragma unroll
        for (int j = 0; j < 4; ++j) {
            float2 f = __bfloat1622float2(hh[j]);
            outv[j*2]   = __float2bfloat16(f.x * qr[sg + j*2]);
            outv[j*2+1] = __float2bfloat16(f.y * qr[sg + j*2+1]);
        }
        *(uint4*)&sA[r][sg] = *(uint4*)outv;
    }
    __syncthreads();
    float acc1[2][2][4] = {};
    #pragma unroll
    for (int kk = 0; kk < 64; kk += 16) {
        unsigned int af[2][4];
        #pragma unroll
        for (int mt = 0; mt < 2; ++mt)
            ldm_x4(af[mt], &sA[wm*32 + mt*16 + (lane & 15)][kk + (lane >> 4)*8]);
        unsigned int bfr[4];
        ldm_x4_t(bfr, &sB[kk + (lane & 15)][wn*16 + (lane >> 4)*8]);
        #pragma unroll
        for (int mt = 0; mt < 2; ++mt)
            #pragma unroll
            for (int nt = 0; nt < 2; ++nt)
                mma16816(acc1[mt][nt], af[mt], bfr[nt*2], bfr[nt*2+1]);
    }
    float ts = temp[h];
    #pragma unroll
    for (int mt = 0; mt < 2; ++mt) {
        int r = wm*32 + mt*16 + (lane >> 2);
        #pragma unroll
        for (int nt = 0; nt < 2; ++nt) {
            int c = wn*16 + nt*8 + (lane & 3)*2;
            ss[r][c]     = acc1[mt][nt][0]*ts;
            ss[r][c+1]   = acc1[mt][nt][1]*ts;
            ss[r+8][c]   = acc1[mt][nt][2]*ts;
            ss[r+8][c+1] = acc1[mt][nt][3]*ts;
        }
    }
    __syncthreads();
    #pragma unroll
    for (int v = 0; v < 4; ++v) {
        int i4 = v*256 + tid; int d = i4 >> 4, pp = (i4 & 15)*4;
        float4 vv = *(const float4*)(vbase + d*64 + pp);
        sA[d][pp]   = __float2bfloat16(vv.x + be[pp]);
        sA[d][pp+1] = __float2bfloat16(vv.y + be[pp+1]);
        sA[d][pp+2] = __float2bfloat16(vv.z + be[pp+2]);
        sA[d][pp+3] = __float2bfloat16(vv.w + be[pp+3]);
    }
    {
        int row = tid >> 2, g4 = (tid & 3)*16;
        float e[16];
        float mx = -1e30f;
        #pragma unroll
        for (int p = 0; p < 16; ++p) { e[p] = ss[row][g4+p]; mx = fmaxf(mx, e[p]); }
        mx = fmaxf(mx, __shfl_xor_sync(0xffffffffu, mx, 1));
        mx = fmaxf(mx, __shfl_xor_sync(0xffffffffu, mx, 2));
        float sum = 0.f;
        #pragma unroll
        for (int p = 0; p < 16; ++p) { e[p] = __expf(e[p] - mx); sum += e[p]; }
        sum += __shfl_xor_sync(0xffffffffu, sum, 1);
        sum += __shfl_xor_sync(0xffffffffu, sum, 2);
        float inv = 1.f/sum;
        #pragma unroll
        for (int p = 0; p < 16; ++p)
            sB[g4+p][row] = __float2bfloat16(e[p]*inv);
    }
    __syncthreads();
    float acc2[2][2][4] = {};
    #pragma unroll
    for (int kk = 0; kk < 64; kk += 16) {
        unsigned int af[2][4];
        #pragma unroll
        for (int mt = 0; mt < 2; ++mt)
            ldm_x4(af[mt], &sA[wm*32 + mt*16 + (lane & 15)][kk + (lane >> 4)*8]);
        unsigned int bfr[4];
        ldm_x4_t(bfr, &sB[kk + (lane & 15)][wn*16 + (lane >> 4)*8]);
        #pragma unroll
        for (int mt = 0; mt < 2; ++mt)
            #pragma unroll
            for (int nt = 0; nt < 2; ++nt)
                mma16816(acc2[mt][nt], af[mt], bfr[nt*2], bfr[nt*2+1]);
    }
    __nv_bfloat16* sabase = g_sa_bf + (size_t)b*NNT*CC;
    #pragma unroll
    for (int mt = 0; mt < 2; ++mt) {
        int d0 = wm*32 + mt*16 + (lane >> 2);
        #pragma unroll
        for (int nt = 0; nt < 2; ++nt) {
            int nc = n0 + wn*16 + nt*8 + (lane & 3)*2;
            *(__nv_bfloat162*)&sabase[(size_t)(d0*4 + h)*NNT + nc] =
                __floats2bfloat162_rn(acc2[mt][nt][0], acc2[mt][nt][1]);
            *(__nv_bfloat162*)&sabase[(size_t)((d0+8)*4 + h)*NNT + nc] =
                __floats2bfloat162_rn(acc2[mt][nt][2], acc2[mt][nt][3]);
        }
    }
}

// ---------------- launch ----------------
extern "C" void kernel_launch(void* const* d_in, const int* in_sizes, int n_in,
                              void* d_out, int out_size)
{
    const float* x      = (const float*)d_in[0];
    const float* pos    = (const float*)d_in[1];
    const float* ln_g   = (const float*)d_in[2];
    const float* ln_b   = (const float*)d_in[3];
    const float* gamma  = (const float*)d_in[4];
    const float* temp2  = (const float*)d_in[5];
    const float* w_qkv  = (const float*)d_in[6];
    const float* w_e    = (const float*)d_in[7];
    const float* b_e    = (const float*)d_in[8];
    const float* w_pool = (const float*)d_in[9];
    const float* b_pool = (const float*)d_in[10];
    const float* w_fc1  = (const float*)d_in[11];
    const float* w_fc2  = (const float*)d_in[12];
    const float* b_out1 = (const float*)d_in[14];
    const float* b_out2 = (const float*)d_in[16];
    const float* w_c1   = (const float*)d_in[17];
    const float* b_c1   = (const float*)d_in[18];
    const float* w_c2   = (const float*)d_in[19];
    const float* b_c2   = (const float*)d_in[20];

    __nv_bfloat16 *p_h1b, *p_c2b, *p_xtbf, *p_xctbf, *p_sabf;
    __nv_bfloat16 *p_wq, *p_w1, *p_w2, *p_qkvbf;
    float *p_gate, *p_zero;
    cudaGetSymbolAddress((void**)&p_h1b,   g_h1b);
    cudaGetSymbolAddress((void**)&p_c2b,   g_c2b);
    cudaGetSymbolAddress((void**)&p_xtbf,  g_xt_bf);
    cudaGetSymbolAddress((void**)&p_xctbf, g_xct_bf);
    cudaGetSymbolAddress((void**)&p_qkvbf, g_qkv_bf);
    cudaGetSymbolAddress((void**)&p_sabf,  g_sa_bf);
    cudaGetSymbolAddress((void**)&p_wq,    g_wqkv_bf);
    cudaGetSymbolAddress((void**)&p_w1,    g_wo1_bf);
    cudaGetSymbolAddress((void**)&p_w2,    g_wo2_bf);
    cudaGetSymbolAddress((void**)&p_gate,  g_gate);
    cudaGetSymbolAddress((void**)&p_zero,  g_zero);

    static int s_attr_done = 0;
    if (!s_attr_done) {
        cudaFuncSetAttribute(k_megaln,
            cudaFuncAttributeMaxDynamicSharedMemorySize, 55296);
        cudaFuncSetAttribute(k_mma,
            cudaFuncAttributeMaxDynamicSharedMemorySize, 71680);
        s_attr_done = 1;
    }

    k_init <<<3456, 256>>>(w_qkv, (const float*)d_in[13],
                           (const float*)d_in[15], w_e);
    // MHCResBlock: grouped convs via HMMA with fused stats
    k_convmma<<<dim3(27,16), 256>>>(x, (const __nv_bfloat16*)0, w_c1, b_c1, p_h1b,
                                    (const float*)0, (const float*)0,
                                    p_zero + ZOFF_CS1S, p_zero + ZOFF_CS1Q);
    k_convmma<<<dim3(27,16), 256>>>((const float*)0, p_h1b, w_c2, b_c2, p_c2b,
                                    p_zero + ZOFF_CS1S, p_zero + ZOFF_CS1Q,
                                    p_zero + ZOFF_CS2S, p_zero + ZOFF_CS2Q);
    // mega-fused transpose + xc + double-LN + pool + d_out(x_n)
    k_megaln<<<dim3(432, BB), 256, 55296>>>(x, pos, ln_g, ln_b, w_pool,
                                            (float*)d_out);
    // qkv (pipelined bf16 HMMA, fused q sum-squares + fused K/V low-rank proj)
    k_mma  <<<dim3(6,216,1), 256, 71680>>>(p_xtbf, (const __nv_bfloat16*)0, p_wq,
                                    (const __nv_bfloat16*)0, (const float*)0,
                                    (const float*)0, (const float*)0,
                                    p_qkvbf, 768, 768, 1,
                                    (float*)0, (const float*)0);
    // spatial attention (+ fused CA gate in block 0)
    k_attn <<<dim3(216, BB*NHH), 256>>>(b_e, temp2, b_pool, w_fc1, w_fc2);
    // both output projections with fused gamma-residual into d_out
    k_mma  <<<dim3(1,216,2), 256, 71680>>>(p_sabf, p_xctbf, p_w1, p_w2,
                                    b_out1, b_out2, p_gate,
                                    (__nv_bfloat16*)0, 128, 256, 0,
                                    (float*)d_out, gamma);
}